// round 1
// baseline (speedup 1.0000x reference)
#include <cuda_runtime.h>

#define N1 8192
#define N2 8192
#define D1 256
#define D2 128

// Scratch (allocation-free rule: __device__ globals)
__device__ float g_q[N1 * D2];                 // 4 MB
__device__ float g_Wt[D1 * D2];                // W1 transposed [256][128]
__device__ float g_S[(size_t)N1 * N2];         // 256 MB score/attn matrix

// ---------------------------------------------------------------------------
// Kernel 0: transpose W1 [128,256] -> Wt [256,128]
// ---------------------------------------------------------------------------
__global__ void transpose_w_kernel(const float* __restrict__ W1,
                                   float* __restrict__ Wt) {
    int idx = blockIdx.x * blockDim.x + threadIdx.x;   // 32768 elems
    if (idx < D1 * D2) {
        int n = idx / D1;       // 0..127 (row of W1)
        int k = idx % D1;       // 0..255
        Wt[k * D2 + n] = W1[idx];
    }
}

// ---------------------------------------------------------------------------
// NN GEMM, N fixed at 128 (full width): C[m][n] = sum_k A[m*lda+k] * B[k*128+n]
// BM=32, BN=128, BK=16, 256 threads, 2x8 micro-tile per thread.
// Used for: q = x1 @ Wt (+bias), f1 = attn @ x2.
// ---------------------------------------------------------------------------
__global__ void gemm_nn_128_kernel(const float* __restrict__ A, int lda,
                                   const float* __restrict__ B,
                                   float* __restrict__ C,
                                   int K, const float* __restrict__ bias) {
    __shared__ float As[32][16];
    __shared__ float Bs[16][128];

    const int m0  = blockIdx.x * 32;
    const int tid = threadIdx.x;
    const int ty  = tid >> 4;    // 0..15 -> rows ty*2, ty*2+1
    const int tx  = tid & 15;    // 0..15 -> cols tx*8 .. tx*8+7

    float acc0[8] = {}, acc1[8] = {};

    for (int k0 = 0; k0 < K; k0 += 16) {
        // As: 32x16 = 512 floats, 2 per thread
        {
            int m  = tid >> 3;          // 0..31
            int k2 = (tid & 7) * 2;     // 0,2,..,14
            const float* p = A + (size_t)(m0 + m) * lda + k0 + k2;
            As[m][k2]     = p[0];
            As[m][k2 + 1] = p[1];
        }
        // Bs: 16x128 = 2048 floats, 8 per thread (2x float4), coalesced
        #pragma unroll
        for (int c = 0; c < 2; c++) {
            int idx = c * 1024 + tid * 4;
            int k   = idx >> 7;
            int n   = idx & 127;
            float4 v = *(const float4*)(B + (size_t)(k0 + k) * 128 + n);
            *(float4*)&Bs[k][n] = v;
        }
        __syncthreads();

        #pragma unroll
        for (int k = 0; k < 16; k++) {
            float a0 = As[ty * 2][k];
            float a1 = As[ty * 2 + 1][k];
            float4 b0 = *(const float4*)&Bs[k][tx * 8];
            float4 b1 = *(const float4*)&Bs[k][tx * 8 + 4];
            acc0[0] += a0 * b0.x; acc0[1] += a0 * b0.y;
            acc0[2] += a0 * b0.z; acc0[3] += a0 * b0.w;
            acc0[4] += a0 * b1.x; acc0[5] += a0 * b1.y;
            acc0[6] += a0 * b1.z; acc0[7] += a0 * b1.w;
            acc1[0] += a1 * b0.x; acc1[1] += a1 * b0.y;
            acc1[2] += a1 * b0.z; acc1[3] += a1 * b0.w;
            acc1[4] += a1 * b1.x; acc1[5] += a1 * b1.y;
            acc1[6] += a1 * b1.z; acc1[7] += a1 * b1.w;
        }
        __syncthreads();
    }

    // epilogue
    float bv[8];
    #pragma unroll
    for (int j = 0; j < 8; j++) bv[j] = bias ? bias[tx * 8 + j] : 0.0f;

    {
        int m = m0 + ty * 2;
        float* p0 = C + (size_t)m * 128 + tx * 8;
        float* p1 = C + (size_t)(m + 1) * 128 + tx * 8;
        #pragma unroll
        for (int j = 0; j < 8; j++) p0[j] = acc0[j] + bv[j];
        #pragma unroll
        for (int j = 0; j < 8; j++) p1[j] = acc1[j] + bv[j];
    }
}

// ---------------------------------------------------------------------------
// NT GEMM: S[m][n] = sum_k q[m*128+k] * x2[n*128+k]
// BM=BN=128, BK=8, 256 threads, 8x8 micro-tile.
// ---------------------------------------------------------------------------
__global__ void gemm_nt_s_kernel(const float* __restrict__ Q,
                                 const float* __restrict__ X2,
                                 float* __restrict__ S) {
    __shared__ float As[8][128];
    __shared__ float Bs[8][128];

    const int m0  = blockIdx.y * 128;
    const int n0  = blockIdx.x * 128;
    const int tid = threadIdx.x;
    const int tr  = tid >> 4;    // 0..15 -> rows tr*8..tr*8+7
    const int tc  = tid & 15;    // 0..15 -> cols tc*8..tc*8+7

    float acc[8][8] = {};

    for (int k0 = 0; k0 < 128; k0 += 8) {
        {
            int r  = tid >> 1;          // 0..127
            int k4 = (tid & 1) * 4;     // 0 or 4
            float4 va = *(const float4*)(Q  + (size_t)(m0 + r) * 128 + k0 + k4);
            As[k4 + 0][r] = va.x; As[k4 + 1][r] = va.y;
            As[k4 + 2][r] = va.z; As[k4 + 3][r] = va.w;
            float4 vb = *(const float4*)(X2 + (size_t)(n0 + r) * 128 + k0 + k4);
            Bs[k4 + 0][r] = vb.x; Bs[k4 + 1][r] = vb.y;
            Bs[k4 + 2][r] = vb.z; Bs[k4 + 3][r] = vb.w;
        }
        __syncthreads();

        #pragma unroll
        for (int k = 0; k < 8; k++) {
            float ra[8], rb[8];
            *(float4*)&ra[0] = *(const float4*)&As[k][tr * 8];
            *(float4*)&ra[4] = *(const float4*)&As[k][tr * 8 + 4];
            *(float4*)&rb[0] = *(const float4*)&Bs[k][tc * 8];
            *(float4*)&rb[4] = *(const float4*)&Bs[k][tc * 8 + 4];
            #pragma unroll
            for (int i = 0; i < 8; i++)
                #pragma unroll
                for (int j = 0; j < 8; j++)
                    acc[i][j] += ra[i] * rb[j];
        }
        __syncthreads();
    }

    #pragma unroll
    for (int i = 0; i < 8; i++) {
        int row = m0 + tr * 8 + i;
        float* p = S + (size_t)row * N2 + n0 + tc * 8;
        *(float4*)&p[0] = make_float4(acc[i][0], acc[i][1], acc[i][2], acc[i][3]);
        *(float4*)&p[4] = make_float4(acc[i][4], acc[i][5], acc[i][6], acc[i][7]);
    }
}

// ---------------------------------------------------------------------------
// Row softmax in place. One block per row; row staged in 32 KB smem.
// ---------------------------------------------------------------------------
__global__ void softmax_rows_kernel(float* __restrict__ S) {
    __shared__ float buf[N2];          // 32 KB
    __shared__ float red[40];

    const int row = blockIdx.x;
    const int tid = threadIdx.x;       // 256
    float4* S4 = (float4*)(S + (size_t)row * N2);
    float4* b4 = (float4*)buf;

    float lmax = -1e30f;
    #pragma unroll
    for (int j = 0; j < 8; j++) {
        float4 v = S4[tid + j * 256];
        b4[tid + j * 256] = v;
        lmax = fmaxf(lmax, fmaxf(fmaxf(v.x, v.y), fmaxf(v.z, v.w)));
    }
    #pragma unroll
    for (int o = 16; o; o >>= 1) lmax = fmaxf(lmax, __shfl_xor_sync(~0u, lmax, o));
    if ((tid & 31) == 0) red[tid >> 5] = lmax;
    __syncthreads();
    if (tid == 0) {
        float m = red[0];
        for (int i = 1; i < 8; i++) m = fmaxf(m, red[i]);
        red[32] = m;
    }
    __syncthreads();
    const float rmax = red[32];

    float lsum = 0.0f;
    #pragma unroll
    for (int j = 0; j < 8; j++) {
        float4 v = b4[tid + j * 256];
        v.x = __expf(v.x - rmax);
        v.y = __expf(v.y - rmax);
        v.z = __expf(v.z - rmax);
        v.w = __expf(v.w - rmax);
        b4[tid + j * 256] = v;
        lsum += (v.x + v.y) + (v.z + v.w);
    }
    #pragma unroll
    for (int o = 16; o; o >>= 1) lsum += __shfl_xor_sync(~0u, lsum, o);
    if ((tid & 31) == 0) red[tid >> 5] = lsum;
    __syncthreads();
    if (tid == 0) {
        float s = 0.0f;
        for (int i = 0; i < 8; i++) s += red[i];
        red[33] = s;
    }
    __syncthreads();
    const float inv = 1.0f / red[33];

    #pragma unroll
    for (int j = 0; j < 8; j++) {
        float4 v = b4[tid + j * 256];
        v.x *= inv; v.y *= inv; v.z *= inv; v.w *= inv;
        S4[tid + j * 256] = v;
    }
}

// ---------------------------------------------------------------------------
// TN GEMM: f2[m][n] = sum_k S[k*8192 + m] * x1[k*256 + n]   (m = n2, n = d1)
// BM=64, BN=64, BK=16, 256 threads, 4x4 micro-tile.
// grid.x = n-tiles (4) so blocks sharing an S column-block are adjacent.
// ---------------------------------------------------------------------------
__global__ void gemm_tn_f2_kernel(const float* __restrict__ Sm,
                                  const float* __restrict__ X1,
                                  float* __restrict__ C) {
    __shared__ float As[16][64];
    __shared__ float Bs[16][64];

    const int n0  = blockIdx.x * 64;
    const int m0  = blockIdx.y * 64;
    const int tid = threadIdx.x;
    const int ty  = tid >> 4;    // 0..15 -> rows ty*4..+3
    const int tx  = tid & 15;    // 0..15 -> cols tx*4..+3

    float acc[4][4] = {};

    for (int k0 = 0; k0 < N1; k0 += 16) {
        {
            int k  = tid >> 4;          // 0..15
            int c4 = (tid & 15) * 4;    // 0..60
            *(float4*)&As[k][c4] = *(const float4*)(Sm + (size_t)(k0 + k) * N2 + m0 + c4);
            *(float4*)&Bs[k][c4] = *(const float4*)(X1 + (size_t)(k0 + k) * D1 + n0 + c4);
        }
        __syncthreads();

        #pragma unroll
        for (int k = 0; k < 16; k++) {
            float4 a = *(const float4*)&As[k][ty * 4];
            float4 b = *(const float4*)&Bs[k][tx * 4];
            acc[0][0] += a.x * b.x; acc[0][1] += a.x * b.y;
            acc[0][2] += a.x * b.z; acc[0][3] += a.x * b.w;
            acc[1][0] += a.y * b.x; acc[1][1] += a.y * b.y;
            acc[1][2] += a.y * b.z; acc[1][3] += a.y * b.w;
            acc[2][0] += a.z * b.x; acc[2][1] += a.z * b.y;
            acc[2][2] += a.z * b.z; acc[2][3] += a.z * b.w;
            acc[3][0] += a.w * b.x; acc[3][1] += a.w * b.y;
            acc[3][2] += a.w * b.z; acc[3][3] += a.w * b.w;
        }
        __syncthreads();
    }

    #pragma unroll
    for (int i = 0; i < 4; i++) {
        int row = m0 + ty * 4 + i;
        float* p = C + (size_t)row * D1 + n0 + tx * 4;
        *(float4*)p = make_float4(acc[i][0], acc[i][1], acc[i][2], acc[i][3]);
    }
}

// ---------------------------------------------------------------------------
// Launch
// ---------------------------------------------------------------------------
extern "C" void kernel_launch(void* const* d_in, const int* in_sizes, int n_in,
                              void* d_out, int out_size) {
    const float* x1 = (const float*)d_in[0];   // [8192, 256]
    const float* x2 = (const float*)d_in[1];   // [8192, 128]
    const float* W1 = (const float*)d_in[2];   // [128, 256]
    const float* b1 = (const float*)d_in[3];   // [128]

    float* out = (float*)d_out;
    float* f1  = out;                              // fused_x1 [8192, 128]
    float* f2  = out + (size_t)N1 * D2;            // fused_x2 [8192, 256]

    float *qp, *wtp, *sp;
    cudaGetSymbolAddress((void**)&qp,  g_q);
    cudaGetSymbolAddress((void**)&wtp, g_Wt);
    cudaGetSymbolAddress((void**)&sp,  g_S);

    // 1) Wt = W1^T
    transpose_w_kernel<<<(D1 * D2 + 255) / 256, 256>>>(W1, wtp);
    // 2) q = x1 @ Wt + b1            [8192, 128]
    gemm_nn_128_kernel<<<N1 / 32, 256>>>(x1, D1, wtp, qp, D1, b1);
    // 3) S = q @ x2^T                [8192, 8192]
    gemm_nt_s_kernel<<<dim3(N2 / 128, N1 / 128), 256>>>(qp, x2, sp);
    // 4) softmax rows of S (in place)
    softmax_rows_kernel<<<N1, 256>>>(sp);
    // 5) f1 = attn @ x2              [8192, 128]
    gemm_nn_128_kernel<<<N1 / 32, 256>>>(sp, N2, x2, f1, N2, nullptr);
    // 6) f2 = attn^T @ x1            [8192, 256]
    gemm_tn_f2_kernel<<<dim3(D1 / 64, N2 / 64), 256>>>(sp, x1, f2);
}

// round 3
// speedup vs baseline: 3.1676x; 3.1676x over previous
#include <cuda_runtime.h>
#include <cuda_bf16.h>
#include <cstdint>

#define N1 8192
#define N2 8192
#define D1 256
#define D2 128

// ---------------------------------------------------------------------------
// Scratch (__device__ globals; allocation-free rule)
// ---------------------------------------------------------------------------
__device__ float g_S[(size_t)N1 * N2];                       // 256 MB scores
__device__ __nv_bfloat16 g_attn_h[(size_t)N1 * N2];          // 128 MB
__device__ __nv_bfloat16 g_attn_l[(size_t)N1 * N2];          // 128 MB
__device__ __nv_bfloat16 g_attnT_h[(size_t)N1 * N2];         // 128 MB
__device__ __nv_bfloat16 g_attnT_l[(size_t)N1 * N2];         // 128 MB
__device__ __nv_bfloat16 g_qh[N1 * D2], g_ql[N1 * D2];
__device__ __nv_bfloat16 g_x2h[N2 * D2], g_x2l[N2 * D2];
__device__ __nv_bfloat16 g_x2th[D2 * N2], g_x2tl[D2 * N2];
__device__ __nv_bfloat16 g_x1th[(size_t)D1 * N1], g_x1tl[(size_t)D1 * N1];
__device__ float g_Wt[D1 * D2];

// ---------------------------------------------------------------------------
// Helpers
// ---------------------------------------------------------------------------
__device__ __forceinline__ uint32_t smem_u32(const void* p) {
    uint32_t a;
    asm("{ .reg .u64 t; cvta.to.shared.u64 t, %1; cvt.u32.u64 %0, t; }" : "=r"(a) : "l"(p));
    return a;
}

__device__ __forceinline__ void ldsm4(uint32_t r[4], uint32_t addr) {
    asm volatile("ldmatrix.sync.aligned.m8n8.x4.shared.b16 {%0,%1,%2,%3}, [%4];"
                 : "=r"(r[0]), "=r"(r[1]), "=r"(r[2]), "=r"(r[3]) : "r"(addr));
}

__device__ __forceinline__ void mma16816(float c[4], const uint32_t a[4], const uint32_t b[2]) {
    asm volatile("mma.sync.aligned.m16n8k16.row.col.f32.bf16.bf16.f32 "
                 "{%0,%1,%2,%3}, {%4,%5,%6,%7}, {%8,%9}, {%0,%1,%2,%3};"
                 : "+f"(c[0]), "+f"(c[1]), "+f"(c[2]), "+f"(c[3])
                 : "r"(a[0]), "r"(a[1]), "r"(a[2]), "r"(a[3]), "r"(b[0]), "r"(b[1]));
}

__device__ __forceinline__ void split_bf16(float v, __nv_bfloat16& h, __nv_bfloat16& l) {
    h = __float2bfloat16(v);
    l = __float2bfloat16(v - __bfloat162float(h));
}

// ---------------------------------------------------------------------------
// Prep kernels
// ---------------------------------------------------------------------------
__global__ void transpose_w_kernel(const float* __restrict__ W1, float* __restrict__ Wt) {
    int idx = blockIdx.x * blockDim.x + threadIdx.x;
    if (idx < D1 * D2) {
        int n = idx / D1, k = idx % D1;
        Wt[k * D2 + n] = W1[idx];
    }
}

// q = x1 @ Wt + b1, output split bf16 hi/lo
__global__ void q_gemm_kernel(const float* __restrict__ A, const float* __restrict__ B,
                              __nv_bfloat16* __restrict__ Ch, __nv_bfloat16* __restrict__ Cl,
                              const float* __restrict__ bias) {
    __shared__ float As[32][16];
    __shared__ float Bs[16][128];
    const int m0 = blockIdx.x * 32;
    const int tid = threadIdx.x;
    const int ty = tid >> 4, tx = tid & 15;
    float acc0[8] = {}, acc1[8] = {};

    for (int k0 = 0; k0 < D1; k0 += 16) {
        {
            int m = tid >> 3, k2 = (tid & 7) * 2;
            const float* p = A + (size_t)(m0 + m) * D1 + k0 + k2;
            As[m][k2] = p[0]; As[m][k2 + 1] = p[1];
        }
        #pragma unroll
        for (int c = 0; c < 2; c++) {
            int idx = c * 1024 + tid * 4;
            int k = idx >> 7, n = idx & 127;
            *(float4*)&Bs[k][n] = *(const float4*)(B + (size_t)(k0 + k) * 128 + n);
        }
        __syncthreads();
        #pragma unroll
        for (int k = 0; k < 16; k++) {
            float a0 = As[ty * 2][k], a1 = As[ty * 2 + 1][k];
            float4 b0 = *(const float4*)&Bs[k][tx * 8];
            float4 b1 = *(const float4*)&Bs[k][tx * 8 + 4];
            acc0[0] += a0 * b0.x; acc0[1] += a0 * b0.y; acc0[2] += a0 * b0.z; acc0[3] += a0 * b0.w;
            acc0[4] += a0 * b1.x; acc0[5] += a0 * b1.y; acc0[6] += a0 * b1.z; acc0[7] += a0 * b1.w;
            acc1[0] += a1 * b0.x; acc1[1] += a1 * b0.y; acc1[2] += a1 * b0.z; acc1[3] += a1 * b0.w;
            acc1[4] += a1 * b1.x; acc1[5] += a1 * b1.y; acc1[6] += a1 * b1.z; acc1[7] += a1 * b1.w;
        }
        __syncthreads();
    }
    int m = m0 + ty * 2;
    #pragma unroll
    for (int j = 0; j < 8; j++) {
        float bv = bias[tx * 8 + j];
        __nv_bfloat16 h, l;
        split_bf16(acc0[j] + bv, h, l);
        Ch[(size_t)m * 128 + tx * 8 + j] = h; Cl[(size_t)m * 128 + tx * 8 + j] = l;
        split_bf16(acc1[j] + bv, h, l);
        Ch[(size_t)(m + 1) * 128 + tx * 8 + j] = h; Cl[(size_t)(m + 1) * 128 + tx * 8 + j] = l;
    }
}

// elementwise split fp32 -> bf16 hi/lo
__global__ void split_kernel(const float* __restrict__ in, int n,
                             __nv_bfloat16* __restrict__ oh, __nv_bfloat16* __restrict__ ol) {
    int i = blockIdx.x * blockDim.x + threadIdx.x;
    if (i * 4 < n) {
        float4 v = *(const float4*)(in + (size_t)i * 4);
        __nv_bfloat16 h, l;
        size_t o = (size_t)i * 4;
        split_bf16(v.x, h, l); oh[o] = h;     ol[o] = l;
        split_bf16(v.y, h, l); oh[o + 1] = h; ol[o + 1] = l;
        split_bf16(v.z, h, l); oh[o + 2] = h; ol[o + 2] = l;
        split_bf16(v.w, h, l); oh[o + 3] = h; ol[o + 3] = l;
    }
}

// transpose+split: in [R][C] fp32 -> out [C][R] bf16 hi/lo
__global__ void transpose_split_kernel(const float* __restrict__ in, int R, int C,
                                       __nv_bfloat16* __restrict__ oh,
                                       __nv_bfloat16* __restrict__ ol) {
    __shared__ float t[32][33];
    int c0 = blockIdx.x * 32, r0 = blockIdx.y * 32;
    for (int i = threadIdx.y; i < 32; i += 8)
        t[i][threadIdx.x] = in[(size_t)(r0 + i) * C + c0 + threadIdx.x];
    __syncthreads();
    for (int i = threadIdx.y; i < 32; i += 8) {
        float v = t[threadIdx.x][i];
        __nv_bfloat16 h, l;
        split_bf16(v, h, l);
        size_t o = (size_t)(c0 + i) * R + r0 + threadIdx.x;
        oh[o] = h; ol[o] = l;
    }
}

// bf16 8192x8192 transpose (64x64 tiles)
__global__ void transpose_bf16_kernel(const __nv_bfloat16* __restrict__ src,
                                      __nv_bfloat16* __restrict__ dst) {
    __shared__ __nv_bfloat16 t[64][65];
    int x0 = blockIdx.x * 64, y0 = blockIdx.y * 64;
    int tid = threadIdx.x;
    int c = (tid & 31) * 2;
    for (int rr = tid >> 5; rr < 64; rr += 8) {
        __nv_bfloat162 v = *(const __nv_bfloat162*)(src + (size_t)(y0 + rr) * N2 + x0 + c);
        t[rr][c] = v.x; t[rr][c + 1] = v.y;
    }
    __syncthreads();
    for (int rr = tid >> 5; rr < 64; rr += 8) {
        __nv_bfloat162 v;
        v.x = t[c][rr]; v.y = t[c + 1][rr];
        *(__nv_bfloat162*)(dst + (size_t)(x0 + rr) * N1 + y0 + c) = v;
    }
}

// ---------------------------------------------------------------------------
// Row softmax: read fp32 S, write bf16 hi/lo attn
// ---------------------------------------------------------------------------
__global__ void softmax_rows_kernel(const float* __restrict__ S,
                                    __nv_bfloat16* __restrict__ Ah,
                                    __nv_bfloat16* __restrict__ Al) {
    __shared__ float buf[N2];
    __shared__ float red[40];
    const int row = blockIdx.x;
    const int tid = threadIdx.x;
    const float4* S4 = (const float4*)(S + (size_t)row * N2);
    float4* b4 = (float4*)buf;

    float lmax = -1e30f;
    #pragma unroll
    for (int j = 0; j < 8; j++) {
        float4 v = S4[tid + j * 256];
        b4[tid + j * 256] = v;
        lmax = fmaxf(lmax, fmaxf(fmaxf(v.x, v.y), fmaxf(v.z, v.w)));
    }
    #pragma unroll
    for (int o = 16; o; o >>= 1) lmax = fmaxf(lmax, __shfl_xor_sync(~0u, lmax, o));
    if ((tid & 31) == 0) red[tid >> 5] = lmax;
    __syncthreads();
    if (tid == 0) {
        float m = red[0];
        for (int i = 1; i < 8; i++) m = fmaxf(m, red[i]);
        red[32] = m;
    }
    __syncthreads();
    const float rmax = red[32];

    float lsum = 0.0f;
    #pragma unroll
    for (int j = 0; j < 8; j++) {
        float4 v = b4[tid + j * 256];
        v.x = __expf(v.x - rmax); v.y = __expf(v.y - rmax);
        v.z = __expf(v.z - rmax); v.w = __expf(v.w - rmax);
        b4[tid + j * 256] = v;
        lsum += (v.x + v.y) + (v.z + v.w);
    }
    #pragma unroll
    for (int o = 16; o; o >>= 1) lsum += __shfl_xor_sync(~0u, lsum, o);
    if ((tid & 31) == 0) red[tid >> 5] = lsum;
    __syncthreads();
    if (tid == 0) {
        float s = 0.0f;
        for (int i = 0; i < 8; i++) s += red[i];
        red[33] = s;
    }
    __syncthreads();
    const float inv = 1.0f / red[33];

    #pragma unroll
    for (int j = 0; j < 8; j++) {
        float4 v = b4[tid + j * 256];
        v.x *= inv; v.y *= inv; v.z *= inv; v.w *= inv;
        __nv_bfloat16 h0, l0, h1, l1, h2, l2, h3, l3;
        split_bf16(v.x, h0, l0); split_bf16(v.y, h1, l1);
        split_bf16(v.z, h2, l2); split_bf16(v.w, h3, l3);
        size_t o = (size_t)row * N2 + (size_t)(tid + j * 256) * 4;
        *(__nv_bfloat162*)(Ah + o)     = __nv_bfloat162(h0, h1);
        *(__nv_bfloat162*)(Ah + o + 2) = __nv_bfloat162(h2, h3);
        *(__nv_bfloat162*)(Al + o)     = __nv_bfloat162(l0, l1);
        *(__nv_bfloat162*)(Al + o + 2) = __nv_bfloat162(l2, l3);
    }
}

// ---------------------------------------------------------------------------
// mma.sync NT GEMM, split-bf16 3-MMA: C = Ah*Bh^T + Ah*Bl^T + Al*Bh^T
// A (hi/lo): [M][K] K-major bf16; B (hi/lo): [Ntot][K] K-major bf16.
// BK = 64, 3-stage cp.async pipeline, XOR-swizzled 128B smem rows.
// ---------------------------------------------------------------------------
template <int BM, int BN>
__device__ __forceinline__ void load_stage(
    uint32_t base, int tid, int m0, int n0, int k0, int K,
    const __nv_bfloat16* Ah, const __nv_bfloat16* Al,
    const __nv_bfloat16* Bh, const __nv_bfloat16* Bl) {
    constexpr int CH = 2 * (BM + BN) * 8;   // 16B chunks per stage
    #pragma unroll
    for (int it = 0; it < CH / 256; it++) {
        int i = tid + it * 256;
        int c = i & 7, row = i >> 3;
        const __nv_bfloat16* src;
        if (row < BM)               src = Ah + (size_t)(m0 + row) * K + k0 + c * 8;
        else if (row < 2 * BM)      src = Al + (size_t)(m0 + row - BM) * K + k0 + c * 8;
        else if (row < 2 * BM + BN) src = Bh + (size_t)(n0 + row - 2 * BM) * K + k0 + c * 8;
        else                        src = Bl + (size_t)(n0 + row - 2 * BM - BN) * K + k0 + c * 8;
        uint32_t dst = base + row * 128 + ((c ^ (row & 7)) << 4);
        asm volatile("cp.async.cg.shared.global [%0], [%1], 16;" :: "r"(dst), "l"(src) : "memory");
    }
    asm volatile("cp.async.commit_group;" ::: "memory");
}

template <int BM, int BN, int WR, int WC>
__global__ __launch_bounds__(256, 1) void gemm_mma_kernel(
    const __nv_bfloat16* __restrict__ Ah, const __nv_bfloat16* __restrict__ Al,
    const __nv_bfloat16* __restrict__ Bh, const __nv_bfloat16* __restrict__ Bl,
    float* __restrict__ C, int K, int ldc) {
    extern __shared__ char smem[];
    constexpr int WTM = BM / WR, WTN = BN / WC;
    constexpr int MT = WTM / 16, NT = WTN / 8;
    constexpr int STAGE = 2 * (BM + BN) * 128;   // bytes

    const int tid = threadIdx.x, wid = tid >> 5, lane = tid & 31;
    const int m0 = blockIdx.y * BM, n0 = blockIdx.x * BN;
    const int wm0 = (wid % WR) * WTM, wn0 = (wid / WR) * WTN;
    uint32_t sb = smem_u32(smem);

    // ldmatrix lane addressing
    const int a_r = lane & 15, a_k = lane >> 4;
    const int b_r = (lane & 7) + ((lane >> 4) << 3), b_k = (lane >> 3) & 1;

    float acc[MT][NT][4] = {};

    const int nCh = K >> 6;
    #pragma unroll
    for (int s = 0; s < 2; s++) {
        if (s < nCh) load_stage<BM, BN>(sb + s * STAGE, tid, m0, n0, s * 64, K, Ah, Al, Bh, Bl);
        else asm volatile("cp.async.commit_group;" ::: "memory");
    }

    for (int c = 0; c < nCh; c++) {
        if (c + 2 < nCh)
            load_stage<BM, BN>(sb + ((c + 2) % 3) * STAGE, tid, m0, n0, (c + 2) * 64, K,
                               Ah, Al, Bh, Bl);
        else
            asm volatile("cp.async.commit_group;" ::: "memory");
        asm volatile("cp.async.wait_group 2;" ::: "memory");
        __syncthreads();

        const uint32_t st = sb + (c % 3) * STAGE;
        #pragma unroll
        for (int ks = 0; ks < 4; ks++) {
            uint32_t afh[MT][4], afl[MT][4];
            #pragma unroll
            for (int mt = 0; mt < MT; mt++) {
                int r = wm0 + mt * 16 + a_r;
                int kc = ks * 2 + a_k;
                uint32_t col = (uint32_t)((kc ^ (r & 7)) << 4);
                ldsm4(afh[mt], st + r * 128 + col);
                ldsm4(afl[mt], st + (BM + r) * 128 + col);
            }
            uint32_t bfh[NT][2], bfl[NT][2];
            #pragma unroll
            for (int nt = 0; nt < NT; nt += 2) {
                int r = wn0 + nt * 8 + b_r;
                int kc = ks * 2 + b_k;
                uint32_t col = (uint32_t)((kc ^ (r & 7)) << 4);
                uint32_t t[4];
                ldsm4(t, st + (2 * BM + r) * 128 + col);
                bfh[nt][0] = t[0]; bfh[nt][1] = t[1];
                bfh[nt + 1][0] = t[2]; bfh[nt + 1][1] = t[3];
                ldsm4(t, st + (2 * BM + BN + r) * 128 + col);
                bfl[nt][0] = t[0]; bfl[nt][1] = t[1];
                bfl[nt + 1][0] = t[2]; bfl[nt + 1][1] = t[3];
            }
            #pragma unroll
            for (int mt = 0; mt < MT; mt++)
                #pragma unroll
                for (int nt = 0; nt < NT; nt++) {
                    mma16816(acc[mt][nt], afh[mt], bfh[nt]);
                    mma16816(acc[mt][nt], afh[mt], bfl[nt]);
                    mma16816(acc[mt][nt], afl[mt], bfh[nt]);
                }
        }
        __syncthreads();
    }

    // epilogue
    #pragma unroll
    for (int mt = 0; mt < MT; mt++) {
        int row = m0 + wm0 + mt * 16 + (lane >> 2);
        #pragma unroll
        for (int nt = 0; nt < NT; nt++) {
            int col = n0 + wn0 + nt * 8 + (lane & 3) * 2;
            *(float2*)&C[(size_t)row * ldc + col]       = make_float2(acc[mt][nt][0], acc[mt][nt][1]);
            *(float2*)&C[(size_t)(row + 8) * ldc + col] = make_float2(acc[mt][nt][2], acc[mt][nt][3]);
        }
    }
}

// ---------------------------------------------------------------------------
// Launch
// ---------------------------------------------------------------------------
extern "C" void kernel_launch(void* const* d_in, const int* in_sizes, int n_in,
                              void* d_out, int out_size) {
    const float* x1 = (const float*)d_in[0];   // [8192, 256]
    const float* x2 = (const float*)d_in[1];   // [8192, 128]
    const float* W1 = (const float*)d_in[2];   // [128, 256]
    const float* b1 = (const float*)d_in[3];   // [128]

    float* out = (float*)d_out;
    float* f1 = out;                          // [8192, 128]
    float* f2 = out + (size_t)N1 * D2;        // [8192, 256]

    float *sp, *wtp;
    __nv_bfloat16 *qh, *ql, *x2h, *x2l, *x2th, *x2tl, *x1th, *x1tl;
    __nv_bfloat16 *ath, *atl, *atth, *attl;
    cudaGetSymbolAddress((void**)&sp, g_S);
    cudaGetSymbolAddress((void**)&wtp, g_Wt);
    cudaGetSymbolAddress((void**)&qh, g_qh);
    cudaGetSymbolAddress((void**)&ql, g_ql);
    cudaGetSymbolAddress((void**)&x2h, g_x2h);
    cudaGetSymbolAddress((void**)&x2l, g_x2l);
    cudaGetSymbolAddress((void**)&x2th, g_x2th);
    cudaGetSymbolAddress((void**)&x2tl, g_x2tl);
    cudaGetSymbolAddress((void**)&x1th, g_x1th);
    cudaGetSymbolAddress((void**)&x1tl, g_x1tl);
    cudaGetSymbolAddress((void**)&ath, g_attn_h);
    cudaGetSymbolAddress((void**)&atl, g_attn_l);
    cudaGetSymbolAddress((void**)&atth, g_attnT_h);
    cudaGetSymbolAddress((void**)&attl, g_attnT_l);

    constexpr int SMEM_BIG   = 3 * 2 * (128 + 128) * 128;   // 196608
    constexpr int SMEM_SMALL = 3 * 2 * (64 + 128) * 128;    // 147456
    cudaFuncSetAttribute((const void*)gemm_mma_kernel<128, 128, 4, 2>,
                         cudaFuncAttributeMaxDynamicSharedMemorySize, SMEM_BIG);
    cudaFuncSetAttribute((const void*)gemm_mma_kernel<64, 128, 2, 4>,
                         cudaFuncAttributeMaxDynamicSharedMemorySize, SMEM_SMALL);

    // 1) Wt = W1^T
    transpose_w_kernel<<<(D1 * D2 + 255) / 256, 256>>>(W1, wtp);
    // 2) q = x1 @ Wt + b1 -> qh/ql bf16  [8192,128]
    q_gemm_kernel<<<N1 / 32, 256>>>(x1, wtp, qh, ql, b1);
    // 3) split x2 -> x2h/x2l  (B for S gemm; already K-major [N2][128])
    split_kernel<<<(N2 * D2 / 4 + 255) / 256, 256>>>(x2, N2 * D2, x2h, x2l);
    // 4) x2^T split -> x2th/x2tl [128][8192]  (B for f1)
    transpose_split_kernel<<<dim3(D2 / 32, N2 / 32), dim3(32, 8)>>>(x2, N2, D2, x2th, x2tl);
    // 5) x1^T split -> x1th/x1tl [256][8192]  (B for f2)
    transpose_split_kernel<<<dim3(D1 / 32, N1 / 32), dim3(32, 8)>>>(x1, N1, D1, x1th, x1tl);
    // 6) S = q @ x2^T  [8192,8192] fp32
    gemm_mma_kernel<128, 128, 4, 2><<<dim3(N2 / 128, N1 / 128), 256, SMEM_BIG>>>(
        qh, ql, x2h, x2l, sp, D2, N2);
    // 7) softmax rows -> attn hi/lo bf16
    softmax_rows_kernel<<<N1, 256>>>(sp, ath, atl);
    // 8) transpose attn -> attnT (hi, lo)
    transpose_bf16_kernel<<<dim3(N2 / 64, N1 / 64), 256>>>(ath, atth);
    transpose_bf16_kernel<<<dim3(N2 / 64, N1 / 64), 256>>>(atl, attl);
    // 9) f1 = attn @ x2  [8192,128]   (A=attn K-major, B=x2^T [128][8192])
    gemm_mma_kernel<64, 128, 2, 4><<<dim3(1, N1 / 64), 256, SMEM_SMALL>>>(
        ath, atl, x2th, x2tl, f1, N2, D2);
    // 10) f2 = attn^T @ x1  [8192,256]  (A=attnT K-major, B=x1^T [256][8192])
    gemm_mma_kernel<128, 128, 4, 2><<<dim3(D1 / 128, N2 / 128), 256, SMEM_BIG>>>(
        atth, attl, x1th, x1tl, f2, N1, D1);
}

// round 5
// speedup vs baseline: 3.6287x; 1.1456x over previous
#include <cuda_runtime.h>
#include <cuda_bf16.h>
#include <cstdint>

#define N1 8192
#define N2 8192
#define D1 256
#define D2 128

// ---------------------------------------------------------------------------
// Scratch (__device__ globals; allocation-free rule)
// ---------------------------------------------------------------------------
__device__ float g_S[(size_t)N1 * N2];                 // 256 MB scores
__device__ float g_lse[N1];                            // row max + log(sum)
__device__ __nv_bfloat16 g_qh[N1 * D2], g_ql[N1 * D2];
__device__ __nv_bfloat16 g_x2h[N2 * D2], g_x2l[N2 * D2];       // [n2][d2] K-major for S
__device__ __nv_bfloat16 g_x2th[D2 * N2], g_x2tl[D2 * N2];     // [d2][n2] for f1 B
__device__ __nv_bfloat16 g_x1h[(size_t)N1 * D1], g_x1l[(size_t)N1 * D1]; // [n1][d1] for f2 B
__device__ float g_Wt[D1 * D2];

// ---------------------------------------------------------------------------
// Helpers
// ---------------------------------------------------------------------------
__device__ __forceinline__ uint32_t smem_u32(const void* p) {
    uint32_t a;
    asm("{ .reg .u64 t; cvta.to.shared.u64 t, %1; cvt.u32.u64 %0, t; }" : "=r"(a) : "l"(p));
    return a;
}
__device__ __forceinline__ void ldsm4(uint32_t r[4], uint32_t addr) {
    asm volatile("ldmatrix.sync.aligned.m8n8.x4.shared.b16 {%0,%1,%2,%3}, [%4];"
                 : "=r"(r[0]), "=r"(r[1]), "=r"(r[2]), "=r"(r[3]) : "r"(addr));
}
__device__ __forceinline__ void ldsm4t(uint32_t r[4], uint32_t addr) {
    asm volatile("ldmatrix.sync.aligned.m8n8.x4.trans.shared.b16 {%0,%1,%2,%3}, [%4];"
                 : "=r"(r[0]), "=r"(r[1]), "=r"(r[2]), "=r"(r[3]) : "r"(addr));
}
__device__ __forceinline__ void mma16816(float c[4], const uint32_t a[4], const uint32_t b[2]) {
    asm volatile("mma.sync.aligned.m16n8k16.row.col.f32.bf16.bf16.f32 "
                 "{%0,%1,%2,%3}, {%4,%5,%6,%7}, {%8,%9}, {%0,%1,%2,%3};"
                 : "+f"(c[0]), "+f"(c[1]), "+f"(c[2]), "+f"(c[3])
                 : "r"(a[0]), "r"(a[1]), "r"(a[2]), "r"(a[3]), "r"(b[0]), "r"(b[1]));
}
__device__ __forceinline__ void split_bf16(float v, __nv_bfloat16& h, __nv_bfloat16& l) {
    h = __float2bfloat16(v);
    l = __float2bfloat16(v - __bfloat162float(h));
}
__device__ __forceinline__ uint32_t pack2(__nv_bfloat16 a, __nv_bfloat16 b) {
    __nv_bfloat162 t(a, b);
    return *reinterpret_cast<uint32_t*>(&t);
}
__device__ __forceinline__ void sts8(uint32_t addr, uint32_t a, uint32_t b) {
    asm volatile("st.shared.v2.b32 [%0], {%1, %2};" :: "r"(addr), "r"(a), "r"(b) : "memory");
}
// exp 4 floats -> bf16 hi (2 words) + lo (2 words)
__device__ __forceinline__ void exp_split4(float4 v, float lse,
                                           uint32_t& h0, uint32_t& h1,
                                           uint32_t& l0, uint32_t& l1) {
    float e0 = __expf(v.x - lse), e1 = __expf(v.y - lse);
    float e2 = __expf(v.z - lse), e3 = __expf(v.w - lse);
    __nv_bfloat16 a, b, c, d, al, bl, cl, dl;
    split_bf16(e0, a, al); split_bf16(e1, b, bl);
    split_bf16(e2, c, cl); split_bf16(e3, d, dl);
    h0 = pack2(a, b); h1 = pack2(c, d);
    l0 = pack2(al, bl); l1 = pack2(cl, dl);
}

// ---------------------------------------------------------------------------
// Prep kernels
// ---------------------------------------------------------------------------
__global__ void transpose_w_kernel(const float* __restrict__ W1, float* __restrict__ Wt) {
    int idx = blockIdx.x * blockDim.x + threadIdx.x;
    if (idx < D1 * D2) {
        int n = idx / D1, k = idx % D1;
        Wt[k * D2 + n] = W1[idx];
    }
}

__global__ void q_gemm_kernel(const float* __restrict__ A, const float* __restrict__ B,
                              __nv_bfloat16* __restrict__ Ch, __nv_bfloat16* __restrict__ Cl,
                              const float* __restrict__ bias) {
    __shared__ float As[32][16];
    __shared__ float Bs[16][128];
    const int m0 = blockIdx.x * 32;
    const int tid = threadIdx.x;
    const int ty = tid >> 4, tx = tid & 15;
    float acc0[8] = {}, acc1[8] = {};

    for (int k0 = 0; k0 < D1; k0 += 16) {
        {
            int m = tid >> 3, k2 = (tid & 7) * 2;
            const float* p = A + (size_t)(m0 + m) * D1 + k0 + k2;
            As[m][k2] = p[0]; As[m][k2 + 1] = p[1];
        }
        #pragma unroll
        for (int c = 0; c < 2; c++) {
            int idx = c * 1024 + tid * 4;
            int k = idx >> 7, n = idx & 127;
            *(float4*)&Bs[k][n] = *(const float4*)(B + (size_t)(k0 + k) * 128 + n);
        }
        __syncthreads();
        #pragma unroll
        for (int k = 0; k < 16; k++) {
            float a0 = As[ty * 2][k], a1 = As[ty * 2 + 1][k];
            float4 b0 = *(const float4*)&Bs[k][tx * 8];
            float4 b1 = *(const float4*)&Bs[k][tx * 8 + 4];
            acc0[0] += a0 * b0.x; acc0[1] += a0 * b0.y; acc0[2] += a0 * b0.z; acc0[3] += a0 * b0.w;
            acc0[4] += a0 * b1.x; acc0[5] += a0 * b1.y; acc0[6] += a0 * b1.z; acc0[7] += a0 * b1.w;
            acc1[0] += a1 * b0.x; acc1[1] += a1 * b0.y; acc1[2] += a1 * b0.z; acc1[3] += a1 * b0.w;
            acc1[4] += a1 * b1.x; acc1[5] += a1 * b1.y; acc1[6] += a1 * b1.z; acc1[7] += a1 * b1.w;
        }
        __syncthreads();
    }
    int m = m0 + ty * 2;
    #pragma unroll
    for (int j = 0; j < 8; j++) {
        float bv = bias[tx * 8 + j];
        __nv_bfloat16 h, l;
        split_bf16(acc0[j] + bv, h, l);
        Ch[(size_t)m * 128 + tx * 8 + j] = h; Cl[(size_t)m * 128 + tx * 8 + j] = l;
        split_bf16(acc1[j] + bv, h, l);
        Ch[(size_t)(m + 1) * 128 + tx * 8 + j] = h; Cl[(size_t)(m + 1) * 128 + tx * 8 + j] = l;
    }
}

__global__ void split_kernel(const float* __restrict__ in, int n,
                             __nv_bfloat16* __restrict__ oh, __nv_bfloat16* __restrict__ ol) {
    int i = blockIdx.x * blockDim.x + threadIdx.x;
    if (i * 4 < n) {
        float4 v = *(const float4*)(in + (size_t)i * 4);
        __nv_bfloat16 h, l;
        size_t o = (size_t)i * 4;
        split_bf16(v.x, h, l); oh[o] = h;     ol[o] = l;
        split_bf16(v.y, h, l); oh[o + 1] = h; ol[o + 1] = l;
        split_bf16(v.z, h, l); oh[o + 2] = h; ol[o + 2] = l;
        split_bf16(v.w, h, l); oh[o + 3] = h; ol[o + 3] = l;
    }
}

__global__ void transpose_split_kernel(const float* __restrict__ in, int R, int C,
                                       __nv_bfloat16* __restrict__ oh,
                                       __nv_bfloat16* __restrict__ ol) {
    __shared__ float t[32][33];
    int c0 = blockIdx.x * 32, r0 = blockIdx.y * 32;
    for (int i = threadIdx.y; i < 32; i += 8)
        t[i][threadIdx.x] = in[(size_t)(r0 + i) * C + c0 + threadIdx.x];
    __syncthreads();
    for (int i = threadIdx.y; i < 32; i += 8) {
        float v = t[threadIdx.x][i];
        __nv_bfloat16 h, l;
        split_bf16(v, h, l);
        size_t o = (size_t)(c0 + i) * R + r0 + threadIdx.x;
        oh[o] = h; ol[o] = l;
    }
}

// ---------------------------------------------------------------------------
// Row stats: lse[row] = max + log(sum exp(x-max))
// ---------------------------------------------------------------------------
__global__ void row_lse_kernel(const float* __restrict__ S, float* __restrict__ lse) {
    __shared__ float buf[N2];
    __shared__ float red[40];
    const int row = blockIdx.x;
    const int tid = threadIdx.x;
    const float4* S4 = (const float4*)(S + (size_t)row * N2);
    float4* b4 = (float4*)buf;

    float lmax = -1e30f;
    #pragma unroll
    for (int j = 0; j < 8; j++) {
        float4 v = S4[tid + j * 256];
        b4[tid + j * 256] = v;
        lmax = fmaxf(lmax, fmaxf(fmaxf(v.x, v.y), fmaxf(v.z, v.w)));
    }
    #pragma unroll
    for (int o = 16; o; o >>= 1) lmax = fmaxf(lmax, __shfl_xor_sync(~0u, lmax, o));
    if ((tid & 31) == 0) red[tid >> 5] = lmax;
    __syncthreads();
    if (tid == 0) {
        float m = red[0];
        for (int i = 1; i < 8; i++) m = fmaxf(m, red[i]);
        red[32] = m;
    }
    __syncthreads();
    const float rmax = red[32];

    float lsum = 0.0f;
    #pragma unroll
    for (int j = 0; j < 8; j++) {
        float4 v = b4[tid + j * 256];
        lsum += __expf(v.x - rmax) + __expf(v.y - rmax)
              + __expf(v.z - rmax) + __expf(v.w - rmax);
    }
    #pragma unroll
    for (int o = 16; o; o >>= 1) lsum += __shfl_xor_sync(~0u, lsum, o);
    if ((tid & 31) == 0) red[tid >> 5] = lsum;
    __syncthreads();
    if (tid == 0) {
        float s = 0.0f;
        for (int i = 0; i < 8; i++) s += red[i];
        lse[row] = rmax + __logf(s);
    }
}

// ---------------------------------------------------------------------------
// S GEMM: NT mma.sync split-bf16 3-MMA
// ---------------------------------------------------------------------------
template <int BM, int BN>
__device__ __forceinline__ void load_stage(
    uint32_t base, int tid, int m0, int n0, int k0, int K,
    const __nv_bfloat16* Ah, const __nv_bfloat16* Al,
    const __nv_bfloat16* Bh, const __nv_bfloat16* Bl) {
    constexpr int CH = 2 * (BM + BN) * 8;
    #pragma unroll
    for (int it = 0; it < CH / 256; it++) {
        int i = tid + it * 256;
        int c = i & 7, row = i >> 3;
        const __nv_bfloat16* src;
        if (row < BM)               src = Ah + (size_t)(m0 + row) * K + k0 + c * 8;
        else if (row < 2 * BM)      src = Al + (size_t)(m0 + row - BM) * K + k0 + c * 8;
        else if (row < 2 * BM + BN) src = Bh + (size_t)(n0 + row - 2 * BM) * K + k0 + c * 8;
        else                        src = Bl + (size_t)(n0 + row - 2 * BM - BN) * K + k0 + c * 8;
        uint32_t dst = base + row * 128 + ((c ^ (row & 7)) << 4);
        asm volatile("cp.async.cg.shared.global [%0], [%1], 16;" :: "r"(dst), "l"(src) : "memory");
    }
    asm volatile("cp.async.commit_group;" ::: "memory");
}

template <int BM, int BN, int WR, int WC>
__global__ __launch_bounds__(256, 1) void gemm_mma_kernel(
    const __nv_bfloat16* __restrict__ Ah, const __nv_bfloat16* __restrict__ Al,
    const __nv_bfloat16* __restrict__ Bh, const __nv_bfloat16* __restrict__ Bl,
    float* __restrict__ C, int K, int ldc) {
    extern __shared__ char smem[];
    constexpr int WTM = BM / WR, WTN = BN / WC;
    constexpr int MT = WTM / 16, NT = WTN / 8;
    constexpr int STAGE = 2 * (BM + BN) * 128;

    const int tid = threadIdx.x, wid = tid >> 5, lane = tid & 31;
    const int m0 = blockIdx.y * BM, n0 = blockIdx.x * BN;
    const int wm0 = (wid % WR) * WTM, wn0 = (wid / WR) * WTN;
    uint32_t sb = smem_u32(smem);

    const int a_r = lane & 15, a_k = lane >> 4;
    const int b_r = (lane & 7) + ((lane >> 4) << 3), b_k = (lane >> 3) & 1;

    float acc[MT][NT][4] = {};
    const int nCh = K >> 6;
    #pragma unroll
    for (int s = 0; s < 2; s++) {
        if (s < nCh) load_stage<BM, BN>(sb + s * STAGE, tid, m0, n0, s * 64, K, Ah, Al, Bh, Bl);
        else asm volatile("cp.async.commit_group;" ::: "memory");
    }

    for (int c = 0; c < nCh; c++) {
        if (c + 2 < nCh)
            load_stage<BM, BN>(sb + ((c + 2) % 3) * STAGE, tid, m0, n0, (c + 2) * 64, K,
                               Ah, Al, Bh, Bl);
        else
            asm volatile("cp.async.commit_group;" ::: "memory");
        asm volatile("cp.async.wait_group 2;" ::: "memory");
        __syncthreads();

        const uint32_t st = sb + (c % 3) * STAGE;
        #pragma unroll
        for (int ks = 0; ks < 4; ks++) {
            uint32_t afh[MT][4], afl[MT][4];
            #pragma unroll
            for (int mt = 0; mt < MT; mt++) {
                int r = wm0 + mt * 16 + a_r;
                int kc = ks * 2 + a_k;
                uint32_t col = (uint32_t)((kc ^ (r & 7)) << 4);
                ldsm4(afh[mt], st + r * 128 + col);
                ldsm4(afl[mt], st + (BM + r) * 128 + col);
            }
            uint32_t bfh[NT][2], bfl[NT][2];
            #pragma unroll
            for (int nt = 0; nt < NT; nt += 2) {
                int r = wn0 + nt * 8 + b_r;
                int kc = ks * 2 + b_k;
                uint32_t col = (uint32_t)((kc ^ (r & 7)) << 4);
                uint32_t t[4];
                ldsm4(t, st + (2 * BM + r) * 128 + col);
                bfh[nt][0] = t[0]; bfh[nt][1] = t[1];
                bfh[nt + 1][0] = t[2]; bfh[nt + 1][1] = t[3];
                ldsm4(t, st + (2 * BM + BN + r) * 128 + col);
                bfl[nt][0] = t[0]; bfl[nt][1] = t[1];
                bfl[nt + 1][0] = t[2]; bfl[nt + 1][1] = t[3];
            }
            #pragma unroll
            for (int mt = 0; mt < MT; mt++)
                #pragma unroll
                for (int nt = 0; nt < NT; nt++) {
                    mma16816(acc[mt][nt], afh[mt], bfh[nt]);
                    mma16816(acc[mt][nt], afh[mt], bfl[nt]);
                    mma16816(acc[mt][nt], afl[mt], bfh[nt]);
                }
        }
        __syncthreads();
    }

    #pragma unroll
    for (int mt = 0; mt < MT; mt++) {
        int row = m0 + wm0 + mt * 16 + (lane >> 2);
        #pragma unroll
        for (int nt = 0; nt < NT; nt++) {
            int col = n0 + wn0 + nt * 8 + (lane & 3) * 2;
            *(float2*)&C[(size_t)row * ldc + col]       = make_float2(acc[mt][nt][0], acc[mt][nt][1]);
            *(float2*)&C[(size_t)(row + 8) * ldc + col] = make_float2(acc[mt][nt][2], acc[mt][nt][3]);
        }
    }
}

// ---------------------------------------------------------------------------
// f1 = attn @ x2 : NT GEMM with fused softmax-A.
// ---------------------------------------------------------------------------
static constexpr int F1_A_STAGE = 64 * 128 * 2;     // 16 KB (hi+lo)
static constexpr int F1_B_OFF   = 2 * F1_A_STAGE;   // 32 KB
static constexpr int F1_B_STAGE = 128 * 128 * 2;    // 32 KB
static constexpr int F1_SMEM    = F1_B_OFF + 2 * F1_B_STAGE;  // 96 KB

__global__ __launch_bounds__(256, 1) void gemm_f1_kernel(
    const float* __restrict__ S, const float* __restrict__ lse,
    const __nv_bfloat16* __restrict__ Bh, const __nv_bfloat16* __restrict__ Bl,
    float* __restrict__ C) {
    extern __shared__ char smem[];
    uint32_t sb = smem_u32(smem);
    const int tid = threadIdx.x, wid = tid >> 5, lane = tid & 31;
    const int m0 = blockIdx.y * 64;
    const int wm0 = (wid & 1) * 32, wn0 = (wid >> 1) * 32;
    const int a_r = lane & 15, a_k = lane >> 4;
    const int b_r = (lane & 7) + ((lane >> 4) << 3), b_k = (lane >> 3) & 1;

    float acc[2][4][4] = {};
    float4 areg[4];
    const int nCh = N2 >> 6;   // 128

    float tl[4];
    #pragma unroll
    for (int it = 0; it < 4; it++) tl[it] = lse[m0 + ((tid + it * 256) >> 4)];

    auto ldgA = [&](int c) {
        #pragma unroll
        for (int it = 0; it < 4; it++) {
            int idx = tid + it * 256;
            int m = idx >> 4, kq = idx & 15;
            areg[it] = *(const float4*)(S + (size_t)(m0 + m) * N2 + c * 64 + kq * 4);
        }
    };
    auto stsA = [&](int buf) {
        uint32_t ab = sb + buf * F1_A_STAGE;
        #pragma unroll
        for (int it = 0; it < 4; it++) {
            int idx = tid + it * 256;
            int m = idx >> 4, kq = idx & 15;
            uint32_t h0, h1, l0, l1;
            exp_split4(areg[it], tl[it], h0, h1, l0, l1);
            uint32_t off = m * 128 + (((kq >> 1) ^ (m & 7)) << 4) + (kq & 1) * 8;
            sts8(ab + off, h0, h1);
            sts8(ab + 64 * 128 + off, l0, l1);
        }
    };
    auto ldB = [&](int c, int buf) {
        uint32_t bb = sb + F1_B_OFF + buf * F1_B_STAGE;
        #pragma unroll
        for (int it = 0; it < 8; it++) {
            int i = tid + it * 256;
            int hl = i >> 10, j = i & 1023, n = j >> 3, cc = j & 7;
            const __nv_bfloat16* src = (hl ? Bl : Bh) + (size_t)n * N2 + c * 64 + cc * 8;
            uint32_t dst = bb + hl * 128 * 128 + n * 128 + ((cc ^ (n & 7)) << 4);
            asm volatile("cp.async.cg.shared.global [%0], [%1], 16;" :: "r"(dst), "l"(src) : "memory");
        }
        asm volatile("cp.async.commit_group;" ::: "memory");
    };

    ldgA(0); stsA(0); ldB(0, 0);

    for (int c = 0; c < nCh; c++) {
        const bool more = (c + 1 < nCh);
        if (more) ldgA(c + 1);
        asm volatile("cp.async.wait_group 0;" ::: "memory");
        __syncthreads();
        if (more) ldB(c + 1, (c + 1) & 1);

        const uint32_t ast = sb + (c & 1) * F1_A_STAGE;
        const uint32_t bst = sb + F1_B_OFF + (c & 1) * F1_B_STAGE;
        #pragma unroll
        for (int ks = 0; ks < 4; ks++) {
            uint32_t afh[2][4], afl[2][4];
            #pragma unroll
            for (int mt = 0; mt < 2; mt++) {
                int r = wm0 + mt * 16 + a_r;
                int kc = ks * 2 + a_k;
                uint32_t col = (uint32_t)((kc ^ (r & 7)) << 4);
                ldsm4(afh[mt], ast + r * 128 + col);
                ldsm4(afl[mt], ast + 64 * 128 + r * 128 + col);
            }
            uint32_t bfh[4][2], bfl[4][2];
            #pragma unroll
            for (int nt = 0; nt < 4; nt += 2) {
                int r = wn0 + nt * 8 + b_r;
                int kc = ks * 2 + b_k;
                uint32_t col = (uint32_t)((kc ^ (r & 7)) << 4);
                uint32_t t[4];
                ldsm4(t, bst + r * 128 + col);
                bfh[nt][0] = t[0]; bfh[nt][1] = t[1];
                bfh[nt + 1][0] = t[2]; bfh[nt + 1][1] = t[3];
                ldsm4(t, bst + 128 * 128 + r * 128 + col);
                bfl[nt][0] = t[0]; bfl[nt][1] = t[1];
                bfl[nt + 1][0] = t[2]; bfl[nt + 1][1] = t[3];
            }
            #pragma unroll
            for (int mt = 0; mt < 2; mt++)
                #pragma unroll
                for (int nt = 0; nt < 4; nt++) {
                    mma16816(acc[mt][nt], afh[mt], bfh[nt]);
                    mma16816(acc[mt][nt], afh[mt], bfl[nt]);
                    mma16816(acc[mt][nt], afl[mt], bfh[nt]);
                }
        }
        if (more) stsA((c + 1) & 1);
    }

    #pragma unroll
    for (int mt = 0; mt < 2; mt++) {
        int row = m0 + wm0 + mt * 16 + (lane >> 2);
        #pragma unroll
        for (int nt = 0; nt < 4; nt++) {
            int col = wn0 + nt * 8 + (lane & 3) * 2;
            *(float2*)&C[(size_t)row * D2 + col]       = make_float2(acc[mt][nt][0], acc[mt][nt][1]);
            *(float2*)&C[(size_t)(row + 8) * D2 + col] = make_float2(acc[mt][nt][2], acc[mt][nt][3]);
        }
    }
}

// ---------------------------------------------------------------------------
// f2 = attn^T @ x1 : TN GEMM with fused softmax-A, trans-ldmatrix fragments.
// ---------------------------------------------------------------------------
static constexpr int F2_A_STAGE = 64 * 256 * 2;     // 32 KB (hi 16 + lo 16)
static constexpr int F2_B_OFF   = 2 * F2_A_STAGE;   // 64 KB
static constexpr int F2_B_STAGE = 64 * 256 * 2;     // 32 KB
static constexpr int F2_SMEM    = F2_B_OFF + 2 * F2_B_STAGE;  // 128 KB

__global__ __launch_bounds__(256, 1) void gemm_f2_kernel(
    const float* __restrict__ S, const float* __restrict__ lse,
    const __nv_bfloat16* __restrict__ Bh, const __nv_bfloat16* __restrict__ Bl,
    float* __restrict__ C) {
    extern __shared__ char smem[];
    uint32_t sb = smem_u32(smem);
    const int tid = threadIdx.x, wid = tid >> 5, lane = tid & 31;
    const int m0 = blockIdx.y * 128, n0 = blockIdx.x * 128;
    const int wm0 = (wid & 3) * 32, wn0 = (wid >> 2) * 64;
    const int lt = lane >> 3, li = lane & 7;

    float acc[2][8][4] = {};
    float4 areg[8];
    float lreg[8];
    const int nCh = N1 >> 6;   // 128

    auto ldgA = [&](int c) {
        #pragma unroll
        for (int it = 0; it < 8; it++) {
            int idx = tid + it * 256;
            int k = idx >> 5, mq = idx & 31;
            areg[it] = *(const float4*)(S + (size_t)(c * 64 + k) * N2 + m0 + mq * 4);
            lreg[it] = __ldg(lse + c * 64 + k);
        }
    };
    auto stsA = [&](int buf) {
        uint32_t ab = sb + buf * F2_A_STAGE;
        #pragma unroll
        for (int it = 0; it < 8; it++) {
            int idx = tid + it * 256;
            int k = idx >> 5, mq = idx & 31;
            uint32_t h0, h1, l0, l1;
            exp_split4(areg[it], lreg[it], h0, h1, l0, l1);
            uint32_t off = k * 256 + (((mq >> 1) ^ (k & 7)) << 4) + (mq & 1) * 8;
            sts8(ab + off, h0, h1);
            sts8(ab + 64 * 256 + off, l0, l1);
        }
    };
    auto ldB = [&](int c, int buf) {
        uint32_t bb = sb + F2_B_OFF + buf * F2_B_STAGE;
        #pragma unroll
        for (int it = 0; it < 8; it++) {
            int i = tid + it * 256;
            int hl = i >> 10, j = i & 1023, k = j >> 4, cc = j & 15;
            const __nv_bfloat16* src = (hl ? Bl : Bh) + (size_t)(c * 64 + k) * D1 + n0 + cc * 8;
            uint32_t dst = bb + hl * 64 * 256 + k * 256 + ((cc ^ (k & 7)) << 4);
            asm volatile("cp.async.cg.shared.global [%0], [%1], 16;" :: "r"(dst), "l"(src) : "memory");
        }
        asm volatile("cp.async.commit_group;" ::: "memory");
    };

    ldgA(0); stsA(0); ldB(0, 0);

    for (int c = 0; c < nCh; c++) {
        const bool more = (c + 1 < nCh);
        if (more) ldgA(c + 1);
        asm volatile("cp.async.wait_group 0;" ::: "memory");
        __syncthreads();
        if (more) ldB(c + 1, (c + 1) & 1);

        const uint32_t ast = sb + (c & 1) * F2_A_STAGE;
        const uint32_t bst = sb + F2_B_OFF + (c & 1) * F2_B_STAGE;
        #pragma unroll
        for (int ks = 0; ks < 4; ks++) {
            uint32_t afh[2][4], afl[2][4];
            #pragma unroll
            for (int mt = 0; mt < 2; mt++) {
                int mb = wm0 + mt * 16 + (lt & 1) * 8;
                int k = ks * 16 + (lt >> 1) * 8 + li;
                uint32_t addr = k * 256 + (((mb >> 3) ^ (k & 7)) << 4);
                ldsm4t(afh[mt], ast + addr);
                ldsm4t(afl[mt], ast + 64 * 256 + addr);
            }
            uint32_t bfh[8][2], bfl[8][2];
            #pragma unroll
            for (int nt = 0; nt < 8; nt += 2) {
                int nb = wn0 + nt * 8 + (lt >> 1) * 8;
                int k = ks * 16 + (lt & 1) * 8 + li;
                uint32_t addr = k * 256 + (((nb >> 3) ^ (k & 7)) << 4);
                uint32_t t[4];
                ldsm4t(t, bst + addr);
                bfh[nt][0] = t[0]; bfh[nt][1] = t[1];
                bfh[nt + 1][0] = t[2]; bfh[nt + 1][1] = t[3];
                ldsm4t(t, bst + 64 * 256 + addr);
                bfl[nt][0] = t[0]; bfl[nt][1] = t[1];
                bfl[nt + 1][0] = t[2]; bfl[nt + 1][1] = t[3];
            }
            #pragma unroll
            for (int mt = 0; mt < 2; mt++)
                #pragma unroll
                for (int nt = 0; nt < 8; nt++) {
                    mma16816(acc[mt][nt], afh[mt], bfh[nt]);
                    mma16816(acc[mt][nt], afh[mt], bfl[nt]);
                    mma16816(acc[mt][nt], afl[mt], bfh[nt]);
                }
        }
        if (more) stsA((c + 1) & 1);
    }

    #pragma unroll
    for (int mt = 0; mt < 2; mt++) {
        int row = m0 + wm0 + mt * 16 + (lane >> 2);
        #pragma unroll
        for (int nt = 0; nt < 8; nt++) {
            int col = n0 + wn0 + nt * 8 + (lane & 3) * 2;
            *(float2*)&C[(size_t)row * D1 + col]       = make_float2(acc[mt][nt][0], acc[mt][nt][1]);
            *(float2*)&C[(size_t)(row + 8) * D1 + col] = make_float2(acc[mt][nt][2], acc[mt][nt][3]);
        }
    }
}

// ---------------------------------------------------------------------------
// Launch
// ---------------------------------------------------------------------------
extern "C" void kernel_launch(void* const* d_in, const int* in_sizes, int n_in,
                              void* d_out, int out_size) {
    const float* x1 = (const float*)d_in[0];   // [8192, 256]
    const float* x2 = (const float*)d_in[1];   // [8192, 128]
    const float* W1 = (const float*)d_in[2];   // [128, 256]
    const float* b1 = (const float*)d_in[3];   // [128]

    float* out = (float*)d_out;
    float* f1 = out;                          // [8192, 128]
    float* f2 = out + (size_t)N1 * D2;        // [8192, 256]

    float *sp, *wtp, *lsep;
    __nv_bfloat16 *qh, *ql, *x2h, *x2l, *x2th, *x2tl, *x1h, *x1l;
    cudaGetSymbolAddress((void**)&sp, g_S);
    cudaGetSymbolAddress((void**)&wtp, g_Wt);
    cudaGetSymbolAddress((void**)&lsep, g_lse);
    cudaGetSymbolAddress((void**)&qh, g_qh);
    cudaGetSymbolAddress((void**)&ql, g_ql);
    cudaGetSymbolAddress((void**)&x2h, g_x2h);
    cudaGetSymbolAddress((void**)&x2l, g_x2l);
    cudaGetSymbolAddress((void**)&x2th, g_x2th);
    cudaGetSymbolAddress((void**)&x2tl, g_x2tl);
    cudaGetSymbolAddress((void**)&x1h, g_x1h);
    cudaGetSymbolAddress((void**)&x1l, g_x1l);

    constexpr int SMEM_BIG = 3 * 2 * (128 + 128) * 128;   // 196608
    cudaFuncSetAttribute((const void*)gemm_mma_kernel<128, 128, 4, 2>,
                         cudaFuncAttributeMaxDynamicSharedMemorySize, SMEM_BIG);
    cudaFuncSetAttribute((const void*)gemm_f1_kernel,
                         cudaFuncAttributeMaxDynamicSharedMemorySize, F1_SMEM);
    cudaFuncSetAttribute((const void*)gemm_f2_kernel,
                         cudaFuncAttributeMaxDynamicSharedMemorySize, F2_SMEM);

    // 1) prep
    transpose_w_kernel<<<(D1 * D2 + 255) / 256, 256>>>(W1, wtp);
    q_gemm_kernel<<<N1 / 32, 256>>>(x1, wtp, qh, ql, b1);
    split_kernel<<<(N2 * D2 / 4 + 255) / 256, 256>>>(x2, N2 * D2, x2h, x2l);
    transpose_split_kernel<<<dim3(D2 / 32, N2 / 32), dim3(32, 8)>>>(x2, N2, D2, x2th, x2tl);
    split_kernel<<<(N1 * D1 / 4 + 255) / 256, 256>>>(x1, N1 * D1, x1h, x1l);
    // 2) S = q @ x2^T  [8192,8192] fp32
    gemm_mma_kernel<128, 128, 4, 2><<<dim3(N2 / 128, N1 / 128), 256, SMEM_BIG>>>(
        qh, ql, x2h, x2l, sp, D2, N2);
    // 3) row stats
    row_lse_kernel<<<N1, 256>>>(sp, lsep);
    // 4) f1 = softmax(S) @ x2   (fused exp in A path)
    gemm_f1_kernel<<<dim3(1, N1 / 64), 256, F1_SMEM>>>(sp, lsep, x2th, x2tl, f1);
    // 5) f2 = softmax(S)^T @ x1 (fused exp, TN, L2-paired grid)
    gemm_f2_kernel<<<dim3(D1 / 128, N2 / 128), 256, F2_SMEM>>>(sp, lsep, x1h, x1l, f2);
}

// round 6
// speedup vs baseline: 4.6071x; 1.2696x over previous
#include <cuda_runtime.h>
#include <cuda_fp16.h>
#include <cstdint>

#define N1 8192
#define N2 8192
#define D1 256
#define D2 128
#define NBLK (N2 / 128)   // 64 n-blocks in S gemm

// ---------------------------------------------------------------------------
// Scratch (__device__ globals; allocation-free rule)
// ---------------------------------------------------------------------------
__device__ float g_S[(size_t)N1 * N2];                 // 256 MB scores
__device__ float g_lse[N1];
__device__ float g_pmax[(size_t)NBLK * N1];            // per-block row max
__device__ float g_psum[(size_t)NBLK * N1];            // per-block row sumexp
__device__ __half g_qh[N1 * D2], g_ql[N1 * D2];
__device__ __half g_x2h[N2 * D2], g_x2l[N2 * D2];      // [n2][d2] K-major for S
__device__ __half g_x2th[D2 * N2], g_x2tl[D2 * N2];    // [d2][n2] for f1 B
__device__ __half g_x1h[(size_t)N1 * D1], g_x1l[(size_t)N1 * D1]; // [n1][d1] for f2 B
__device__ float g_Wt[D1 * D2];

// ---------------------------------------------------------------------------
// Helpers
// ---------------------------------------------------------------------------
__device__ __forceinline__ uint32_t smem_u32(const void* p) {
    uint32_t a;
    asm("{ .reg .u64 t; cvta.to.shared.u64 t, %1; cvt.u32.u64 %0, t; }" : "=r"(a) : "l"(p));
    return a;
}
__device__ __forceinline__ void ldsm4(uint32_t r[4], uint32_t addr) {
    asm volatile("ldmatrix.sync.aligned.m8n8.x4.shared.b16 {%0,%1,%2,%3}, [%4];"
                 : "=r"(r[0]), "=r"(r[1]), "=r"(r[2]), "=r"(r[3]) : "r"(addr));
}
__device__ __forceinline__ void ldsm4t(uint32_t r[4], uint32_t addr) {
    asm volatile("ldmatrix.sync.aligned.m8n8.x4.trans.shared.b16 {%0,%1,%2,%3}, [%4];"
                 : "=r"(r[0]), "=r"(r[1]), "=r"(r[2]), "=r"(r[3]) : "r"(addr));
}
__device__ __forceinline__ void mma16816(float c[4], const uint32_t a[4], const uint32_t b[2]) {
    asm volatile("mma.sync.aligned.m16n8k16.row.col.f32.f16.f16.f32 "
                 "{%0,%1,%2,%3}, {%4,%5,%6,%7}, {%8,%9}, {%0,%1,%2,%3};"
                 : "+f"(c[0]), "+f"(c[1]), "+f"(c[2]), "+f"(c[3])
                 : "r"(a[0]), "r"(a[1]), "r"(a[2]), "r"(a[3]), "r"(b[0]), "r"(b[1]));
}
__device__ __forceinline__ void split_h(float v, __half& h, __half& l) {
    h = __float2half(v);
    l = __float2half(v - __half2float(h));
}
__device__ __forceinline__ uint32_t pack2h(__half a, __half b) {
    __half2 t(a, b);
    return *reinterpret_cast<uint32_t*>(&t);
}
__device__ __forceinline__ void sts8(uint32_t addr, uint32_t a, uint32_t b) {
    asm volatile("st.shared.v2.b32 [%0], {%1, %2};" :: "r"(addr), "r"(a), "r"(b) : "memory");
}
// exp 4 floats -> single fp16 (2 words)
__device__ __forceinline__ void exp_h4(float4 v, float lse, uint32_t& h0, uint32_t& h1) {
    __half2 a = __floats2half2_rn(__expf(v.x - lse), __expf(v.y - lse));
    __half2 b = __floats2half2_rn(__expf(v.z - lse), __expf(v.w - lse));
    h0 = *reinterpret_cast<uint32_t*>(&a);
    h1 = *reinterpret_cast<uint32_t*>(&b);
}

// ---------------------------------------------------------------------------
// Prep kernels
// ---------------------------------------------------------------------------
__global__ void transpose_w_kernel(const float* __restrict__ W1, float* __restrict__ Wt) {
    int idx = blockIdx.x * blockDim.x + threadIdx.x;
    if (idx < D1 * D2) {
        int n = idx / D1, k = idx % D1;
        Wt[k * D2 + n] = W1[idx];
    }
}

__global__ void q_gemm_kernel(const float* __restrict__ A, const float* __restrict__ B,
                              __half* __restrict__ Ch, __half* __restrict__ Cl,
                              const float* __restrict__ bias) {
    __shared__ float As[32][16];
    __shared__ float Bs[16][128];
    const int m0 = blockIdx.x * 32;
    const int tid = threadIdx.x;
    const int ty = tid >> 4, tx = tid & 15;
    float acc0[8] = {}, acc1[8] = {};

    for (int k0 = 0; k0 < D1; k0 += 16) {
        {
            int m = tid >> 3, k2 = (tid & 7) * 2;
            const float* p = A + (size_t)(m0 + m) * D1 + k0 + k2;
            As[m][k2] = p[0]; As[m][k2 + 1] = p[1];
        }
        #pragma unroll
        for (int c = 0; c < 2; c++) {
            int idx = c * 1024 + tid * 4;
            int k = idx >> 7, n = idx & 127;
            *(float4*)&Bs[k][n] = *(const float4*)(B + (size_t)(k0 + k) * 128 + n);
        }
        __syncthreads();
        #pragma unroll
        for (int k = 0; k < 16; k++) {
            float a0 = As[ty * 2][k], a1 = As[ty * 2 + 1][k];
            float4 b0 = *(const float4*)&Bs[k][tx * 8];
            float4 b1 = *(const float4*)&Bs[k][tx * 8 + 4];
            acc0[0] += a0 * b0.x; acc0[1] += a0 * b0.y; acc0[2] += a0 * b0.z; acc0[3] += a0 * b0.w;
            acc0[4] += a0 * b1.x; acc0[5] += a0 * b1.y; acc0[6] += a0 * b1.z; acc0[7] += a0 * b1.w;
            acc1[0] += a1 * b0.x; acc1[1] += a1 * b0.y; acc1[2] += a1 * b0.z; acc1[3] += a1 * b0.w;
            acc1[4] += a1 * b1.x; acc1[5] += a1 * b1.y; acc1[6] += a1 * b1.z; acc1[7] += a1 * b1.w;
        }
        __syncthreads();
    }
    int m = m0 + ty * 2;
    #pragma unroll
    for (int j = 0; j < 8; j++) {
        float bv = bias[tx * 8 + j];
        __half h, l;
        split_h(acc0[j] + bv, h, l);
        Ch[(size_t)m * 128 + tx * 8 + j] = h; Cl[(size_t)m * 128 + tx * 8 + j] = l;
        split_h(acc1[j] + bv, h, l);
        Ch[(size_t)(m + 1) * 128 + tx * 8 + j] = h; Cl[(size_t)(m + 1) * 128 + tx * 8 + j] = l;
    }
}

__global__ void split_kernel(const float* __restrict__ in, int n,
                             __half* __restrict__ oh, __half* __restrict__ ol) {
    int i = blockIdx.x * blockDim.x + threadIdx.x;
    if (i * 4 < n) {
        float4 v = *(const float4*)(in + (size_t)i * 4);
        __half h, l;
        size_t o = (size_t)i * 4;
        split_h(v.x, h, l); oh[o] = h;     ol[o] = l;
        split_h(v.y, h, l); oh[o + 1] = h; ol[o + 1] = l;
        split_h(v.z, h, l); oh[o + 2] = h; ol[o + 2] = l;
        split_h(v.w, h, l); oh[o + 3] = h; ol[o + 3] = l;
    }
}

__global__ void transpose_split_kernel(const float* __restrict__ in, int R, int C,
                                       __half* __restrict__ oh, __half* __restrict__ ol) {
    __shared__ float t[32][33];
    int c0 = blockIdx.x * 32, r0 = blockIdx.y * 32;
    for (int i = threadIdx.y; i < 32; i += 8)
        t[i][threadIdx.x] = in[(size_t)(r0 + i) * C + c0 + threadIdx.x];
    __syncthreads();
    for (int i = threadIdx.y; i < 32; i += 8) {
        float v = t[threadIdx.x][i];
        __half h, l;
        split_h(v, h, l);
        size_t o = (size_t)(c0 + i) * R + r0 + threadIdx.x;
        oh[o] = h; ol[o] = l;
    }
}

// ---------------------------------------------------------------------------
// lse combine: lse[row] = M + log( sum_nb psum[nb]*exp(pmax[nb]-M) )
// ---------------------------------------------------------------------------
__global__ void lse_combine_kernel(const float* __restrict__ pmax,
                                   const float* __restrict__ psum,
                                   float* __restrict__ lse) {
    int row = blockIdx.x * 256 + threadIdx.x;
    float M = -1e30f;
    #pragma unroll 8
    for (int nb = 0; nb < NBLK; nb++)
        M = fmaxf(M, pmax[(size_t)nb * N1 + row]);
    float s = 0.0f;
    #pragma unroll 8
    for (int nb = 0; nb < NBLK; nb++)
        s += psum[(size_t)nb * N1 + row] * __expf(pmax[(size_t)nb * N1 + row] - M);
    lse[row] = M + __logf(s);
}

// ---------------------------------------------------------------------------
// S GEMM: NT mma.sync split-fp16 3-MMA + per-block row (max,sumexp) partials.
// BM=BN=128, WR=4, WC=2. BK=64, 3-stage cp.async.
// ---------------------------------------------------------------------------
static constexpr int S_STAGE = 2 * (128 + 128) * 128;     // 64 KB
static constexpr int SMEM_S  = 3 * S_STAGE;               // 192 KB

__device__ __forceinline__ void s_load_stage(
    uint32_t base, int tid, int m0, int n0, int k0,
    const __half* Ah, const __half* Al, const __half* Bh, const __half* Bl) {
    #pragma unroll
    for (int it = 0; it < 16; it++) {
        int i = tid + it * 256;
        int c = i & 7, row = i >> 3;
        const __half* src;
        if (row < 128)       src = Ah + (size_t)(m0 + row) * D2 + k0 + c * 8;
        else if (row < 256)  src = Al + (size_t)(m0 + row - 128) * D2 + k0 + c * 8;
        else if (row < 384)  src = Bh + (size_t)(n0 + row - 256) * D2 + k0 + c * 8;
        else                 src = Bl + (size_t)(n0 + row - 384) * D2 + k0 + c * 8;
        uint32_t dst = base + row * 128 + ((c ^ (row & 7)) << 4);
        asm volatile("cp.async.cg.shared.global [%0], [%1], 16;" :: "r"(dst), "l"(src) : "memory");
    }
    asm volatile("cp.async.commit_group;" ::: "memory");
}

__global__ __launch_bounds__(256, 1) void gemm_s_kernel(
    const __half* __restrict__ Ah, const __half* __restrict__ Al,
    const __half* __restrict__ Bh, const __half* __restrict__ Bl,
    float* __restrict__ C, float* __restrict__ pmax, float* __restrict__ psum) {
    extern __shared__ char smem[];
    const int tid = threadIdx.x, wid = tid >> 5, lane = tid & 31;
    const int m0 = blockIdx.y * 128, n0 = blockIdx.x * 128;
    const int wm0 = (wid & 3) * 32, wn0 = (wid >> 2) * 64;
    uint32_t sb = smem_u32(smem);

    const int a_r = lane & 15, a_k = lane >> 4;
    const int b_r = (lane & 7) + ((lane >> 4) << 3), b_k = (lane >> 3) & 1;

    float acc[2][8][4] = {};
    const int nCh = D2 >> 6;   // 2
    s_load_stage(sb, tid, m0, n0, 0, Ah, Al, Bh, Bl);
    s_load_stage(sb + S_STAGE, tid, m0, n0, 64, Ah, Al, Bh, Bl);

    for (int c = 0; c < nCh; c++) {
        asm volatile("cp.async.wait_group %0;" :: "n"(0) : "memory");
        __syncthreads();
        const uint32_t st = sb + c * S_STAGE;
        #pragma unroll
        for (int ks = 0; ks < 4; ks++) {
            uint32_t afh[2][4], afl[2][4];
            #pragma unroll
            for (int mt = 0; mt < 2; mt++) {
                int r = wm0 + mt * 16 + a_r;
                int kc = ks * 2 + a_k;
                uint32_t col = (uint32_t)((kc ^ (r & 7)) << 4);
                ldsm4(afh[mt], st + r * 128 + col);
                ldsm4(afl[mt], st + (128 + r) * 128 + col);
            }
            uint32_t bfh[8][2], bfl[8][2];
            #pragma unroll
            for (int nt = 0; nt < 8; nt += 2) {
                int r = wn0 + nt * 8 + b_r;
                int kc = ks * 2 + b_k;
                uint32_t col = (uint32_t)((kc ^ (r & 7)) << 4);
                uint32_t t[4];
                ldsm4(t, st + (256 + r) * 128 + col);
                bfh[nt][0] = t[0]; bfh[nt][1] = t[1];
                bfh[nt + 1][0] = t[2]; bfh[nt + 1][1] = t[3];
                ldsm4(t, st + (384 + r) * 128 + col);
                bfl[nt][0] = t[0]; bfl[nt][1] = t[1];
                bfl[nt + 1][0] = t[2]; bfl[nt + 1][1] = t[3];
            }
            #pragma unroll
            for (int mt = 0; mt < 2; mt++)
                #pragma unroll
                for (int nt = 0; nt < 8; nt++) {
                    mma16816(acc[mt][nt], afh[mt], bfh[nt]);
                    mma16816(acc[mt][nt], afh[mt], bfl[nt]);
                    mma16816(acc[mt][nt], afl[mt], bfh[nt]);
                }
        }
        __syncthreads();
    }

    // write S
    #pragma unroll
    for (int mt = 0; mt < 2; mt++) {
        int row = m0 + wm0 + mt * 16 + (lane >> 2);
        #pragma unroll
        for (int nt = 0; nt < 8; nt++) {
            int col = n0 + wn0 + nt * 8 + (lane & 3) * 2;
            *(float2*)&C[(size_t)row * N2 + col]       = make_float2(acc[mt][nt][0], acc[mt][nt][1]);
            *(float2*)&C[(size_t)(row + 8) * N2 + col] = make_float2(acc[mt][nt][2], acc[mt][nt][3]);
        }
    }

    // per-block row (max, sumexp) partials over this 128-col slab
    float* pm = (float*)smem;          // [8][32]
    float* ps = pm + 256;              // [8][32]
    #pragma unroll
    for (int mt = 0; mt < 2; mt++) {
        #pragma unroll
        for (int half = 0; half < 2; half++) {
            float mx = -1e30f;
            #pragma unroll
            for (int nt = 0; nt < 8; nt++)
                mx = fmaxf(mx, fmaxf(acc[mt][nt][2 * half], acc[mt][nt][2 * half + 1]));
            mx = fmaxf(mx, __shfl_xor_sync(~0u, mx, 1));
            mx = fmaxf(mx, __shfl_xor_sync(~0u, mx, 2));
            float sm = 0.0f;
            #pragma unroll
            for (int nt = 0; nt < 8; nt++)
                sm += __expf(acc[mt][nt][2 * half] - mx) + __expf(acc[mt][nt][2 * half + 1] - mx);
            sm += __shfl_xor_sync(~0u, sm, 1);
            sm += __shfl_xor_sync(~0u, sm, 2);
            if ((lane & 3) == 0) {
                int rlw = mt * 16 + half * 8 + (lane >> 2);
                pm[wid * 32 + rlw] = mx;
                ps[wid * 32 + rlw] = sm;
            }
        }
    }
    __syncthreads();
    if (tid < 128) {
        int g = tid >> 5, rlw = tid & 31;
        float m1 = pm[g * 32 + rlw], m2 = pm[(g + 4) * 32 + rlw];
        float M = fmaxf(m1, m2);
        float s = ps[g * 32 + rlw] * __expf(m1 - M) + ps[(g + 4) * 32 + rlw] * __expf(m2 - M);
        pmax[(size_t)blockIdx.x * N1 + m0 + tid] = M;
        psum[(size_t)blockIdx.x * N1 + m0 + tid] = s;
    }
}

// ---------------------------------------------------------------------------
// f1 = attn @ x2 : NT GEMM, A = exp(S-lse) single fp16 (fused), B = x2t split.
// BM=64, BN=128. 2 MMAs per tile. smem: A 2x8KB + B 2x32KB = 80KB
// ---------------------------------------------------------------------------
static constexpr int F1_A_STAGE = 64 * 128;          // 8 KB
static constexpr int F1_B_OFF   = 2 * F1_A_STAGE;    // 16 KB
static constexpr int F1_B_STAGE = 128 * 128 * 2;     // 32 KB
static constexpr int F1_SMEM    = F1_B_OFF + 2 * F1_B_STAGE;  // 80 KB

__global__ __launch_bounds__(256, 1) void gemm_f1_kernel(
    const float* __restrict__ S, const float* __restrict__ lse,
    const __half* __restrict__ Bh, const __half* __restrict__ Bl,
    float* __restrict__ C) {
    extern __shared__ char smem[];
    uint32_t sb = smem_u32(smem);
    const int tid = threadIdx.x, wid = tid >> 5, lane = tid & 31;
    const int m0 = blockIdx.y * 64;
    const int wm0 = (wid & 1) * 32, wn0 = (wid >> 1) * 32;
    const int a_r = lane & 15, a_k = lane >> 4;
    const int b_r = (lane & 7) + ((lane >> 4) << 3), b_k = (lane >> 3) & 1;

    float acc[2][4][4] = {};
    float4 areg[4];
    const int nCh = N2 >> 6;   // 128

    float tl[4];
    #pragma unroll
    for (int it = 0; it < 4; it++) tl[it] = lse[m0 + ((tid + it * 256) >> 4)];

    auto ldgA = [&](int c) {
        #pragma unroll
        for (int it = 0; it < 4; it++) {
            int idx = tid + it * 256;
            int m = idx >> 4, kq = idx & 15;
            areg[it] = *(const float4*)(S + (size_t)(m0 + m) * N2 + c * 64 + kq * 4);
        }
    };
    auto stsA = [&](int buf) {
        uint32_t ab = sb + buf * F1_A_STAGE;
        #pragma unroll
        for (int it = 0; it < 4; it++) {
            int idx = tid + it * 256;
            int m = idx >> 4, kq = idx & 15;
            uint32_t h0, h1;
            exp_h4(areg[it], tl[it], h0, h1);
            // A row = 64 k-values fp16 = 128B; 16 threads per row, 8B each
            uint32_t off = m * 128 + (((kq >> 1) ^ (m & 7)) << 4) + (kq & 1) * 8;
            sts8(ab + off, h0, h1);
        }
    };
    auto ldB = [&](int c, int buf) {
        uint32_t bb = sb + F1_B_OFF + buf * F1_B_STAGE;
        #pragma unroll
        for (int it = 0; it < 8; it++) {
            int i = tid + it * 256;
            int hl = i >> 10, j = i & 1023, n = j >> 3, cc = j & 7;
            const __half* src = (hl ? Bl : Bh) + (size_t)n * N2 + c * 64 + cc * 8;
            uint32_t dst = bb + hl * 128 * 128 + n * 128 + ((cc ^ (n & 7)) << 4);
            asm volatile("cp.async.cg.shared.global [%0], [%1], 16;" :: "r"(dst), "l"(src) : "memory");
        }
        asm volatile("cp.async.commit_group;" ::: "memory");
    };

    ldgA(0); stsA(0); ldB(0, 0);

    for (int c = 0; c < nCh; c++) {
        const bool more = (c + 1 < nCh);
        if (more) ldgA(c + 1);
        asm volatile("cp.async.wait_group 0;" ::: "memory");
        __syncthreads();
        if (more) ldB(c + 1, (c + 1) & 1);

        const uint32_t ast = sb + (c & 1) * F1_A_STAGE;
        const uint32_t bst = sb + F1_B_OFF + (c & 1) * F1_B_STAGE;
        #pragma unroll
        for (int ks = 0; ks < 4; ks++) {
            uint32_t afh[2][4];
            #pragma unroll
            for (int mt = 0; mt < 2; mt++) {
                int r = wm0 + mt * 16 + a_r;
                int kc = ks * 2 + a_k;
                uint32_t col = (uint32_t)((kc ^ (r & 7)) << 4);
                ldsm4(afh[mt], ast + r * 128 + col);
            }
            uint32_t bfh[4][2], bfl[4][2];
            #pragma unroll
            for (int nt = 0; nt < 4; nt += 2) {
                int r = wn0 + nt * 8 + b_r;
                int kc = ks * 2 + b_k;
                uint32_t col = (uint32_t)((kc ^ (r & 7)) << 4);
                uint32_t t[4];
                ldsm4(t, bst + r * 128 + col);
                bfh[nt][0] = t[0]; bfh[nt][1] = t[1];
                bfh[nt + 1][0] = t[2]; bfh[nt + 1][1] = t[3];
                ldsm4(t, bst + 128 * 128 + r * 128 + col);
                bfl[nt][0] = t[0]; bfl[nt][1] = t[1];
                bfl[nt + 1][0] = t[2]; bfl[nt + 1][1] = t[3];
            }
            #pragma unroll
            for (int mt = 0; mt < 2; mt++)
                #pragma unroll
                for (int nt = 0; nt < 4; nt++) {
                    mma16816(acc[mt][nt], afh[mt], bfh[nt]);
                    mma16816(acc[mt][nt], afh[mt], bfl[nt]);
                }
        }
        if (more) stsA((c + 1) & 1);
    }

    #pragma unroll
    for (int mt = 0; mt < 2; mt++) {
        int row = m0 + wm0 + mt * 16 + (lane >> 2);
        #pragma unroll
        for (int nt = 0; nt < 4; nt++) {
            int col = wn0 + nt * 8 + (lane & 3) * 2;
            *(float2*)&C[(size_t)row * D2 + col]       = make_float2(acc[mt][nt][0], acc[mt][nt][1]);
            *(float2*)&C[(size_t)(row + 8) * D2 + col] = make_float2(acc[mt][nt][2], acc[mt][nt][3]);
        }
    }
}

// ---------------------------------------------------------------------------
// f2 = attn^T @ x1 : TN GEMM, A = exp(S-lse) single fp16, trans-ldmatrix.
// BM=128, BN=128. 2 MMAs per tile. smem: A 2x16KB + B 2x32KB = 96KB
// ---------------------------------------------------------------------------
static constexpr int F2_A_STAGE = 64 * 256;          // 16 KB
static constexpr int F2_B_OFF   = 2 * F2_A_STAGE;    // 32 KB
static constexpr int F2_B_STAGE = 64 * 256 * 2;      // 32 KB
static constexpr int F2_SMEM    = F2_B_OFF + 2 * F2_B_STAGE;  // 96 KB

__global__ __launch_bounds__(256, 1) void gemm_f2_kernel(
    const float* __restrict__ S, const float* __restrict__ lse,
    const __half* __restrict__ Bh, const __half* __restrict__ Bl,
    float* __restrict__ C) {
    extern __shared__ char smem[];
    uint32_t sb = smem_u32(smem);
    const int tid = threadIdx.x, wid = tid >> 5, lane = tid & 31;
    const int m0 = blockIdx.y * 128, n0 = blockIdx.x * 128;
    const int wm0 = (wid & 3) * 32, wn0 = (wid >> 2) * 64;
    const int lt = lane >> 3, li = lane & 7;

    float acc[2][8][4] = {};
    float4 areg[8];
    float lreg[8];
    const int nCh = N1 >> 6;   // 128

    auto ldgA = [&](int c) {
        #pragma unroll
        for (int it = 0; it < 8; it++) {
            int idx = tid + it * 256;
            int k = idx >> 5, mq = idx & 31;
            areg[it] = *(const float4*)(S + (size_t)(c * 64 + k) * N2 + m0 + mq * 4);
            lreg[it] = __ldg(lse + c * 64 + k);
        }
    };
    auto stsA = [&](int buf) {
        uint32_t ab = sb + buf * F2_A_STAGE;
        #pragma unroll
        for (int it = 0; it < 8; it++) {
            int idx = tid + it * 256;
            int k = idx >> 5, mq = idx & 31;
            uint32_t h0, h1;
            exp_h4(areg[it], lreg[it], h0, h1);
            // A row = 128 m-values fp16 = 256B; 32 threads per row, 8B each
            uint32_t off = k * 256 + (((mq >> 1) ^ (k & 7)) << 4) + (mq & 1) * 8;
            sts8(ab + off, h0, h1);
        }
    };
    auto ldB = [&](int c, int buf) {
        uint32_t bb = sb + F2_B_OFF + buf * F2_B_STAGE;
        #pragma unroll
        for (int it = 0; it < 8; it++) {
            int i = tid + it * 256;
            int hl = i >> 10, j = i & 1023, k = j >> 4, cc = j & 15;
            const __half* src = (hl ? Bl : Bh) + (size_t)(c * 64 + k) * D1 + n0 + cc * 8;
            uint32_t dst = bb + hl * 64 * 256 + k * 256 + ((cc ^ (k & 7)) << 4);
            asm volatile("cp.async.cg.shared.global [%0], [%1], 16;" :: "r"(dst), "l"(src) : "memory");
        }
        asm volatile("cp.async.commit_group;" ::: "memory");
    };

    ldgA(0); stsA(0); ldB(0, 0);

    for (int c = 0; c < nCh; c++) {
        const bool more = (c + 1 < nCh);
        if (more) ldgA(c + 1);
        asm volatile("cp.async.wait_group 0;" ::: "memory");
        __syncthreads();
        if (more) ldB(c + 1, (c + 1) & 1);

        const uint32_t ast = sb + (c & 1) * F2_A_STAGE;
        const uint32_t bst = sb + F2_B_OFF + (c & 1) * F2_B_STAGE;
        #pragma unroll
        for (int ks = 0; ks < 4; ks++) {
            uint32_t afh[2][4];
            #pragma unroll
            for (int mt = 0; mt < 2; mt++) {
                int mb = wm0 + mt * 16 + (lt & 1) * 8;
                int k = ks * 16 + (lt >> 1) * 8 + li;
                uint32_t addr = k * 256 + (((mb >> 3) ^ (k & 7)) << 4);
                ldsm4t(afh[mt], ast + addr);
            }
            uint32_t bfh[8][2], bfl[8][2];
            #pragma unroll
            for (int nt = 0; nt < 8; nt += 2) {
                int nb = wn0 + nt * 8 + (lt >> 1) * 8;
                int k = ks * 16 + (lt & 1) * 8 + li;
                uint32_t addr = k * 256 + (((nb >> 3) ^ (k & 7)) << 4);
                uint32_t t[4];
                ldsm4t(t, bst + addr);
                bfh[nt][0] = t[0]; bfh[nt][1] = t[1];
                bfh[nt + 1][0] = t[2]; bfh[nt + 1][1] = t[3];
                ldsm4t(t, bst + 64 * 256 + addr);
                bfl[nt][0] = t[0]; bfl[nt][1] = t[1];
                bfl[nt + 1][0] = t[2]; bfl[nt + 1][1] = t[3];
            }
            #pragma unroll
            for (int mt = 0; mt < 2; mt++)
                #pragma unroll
                for (int nt = 0; nt < 8; nt++) {
                    mma16816(acc[mt][nt], afh[mt], bfh[nt]);
                    mma16816(acc[mt][nt], afh[mt], bfl[nt]);
                }
        }
        if (more) stsA((c + 1) & 1);
    }

    #pragma unroll
    for (int mt = 0; mt < 2; mt++) {
        int row = m0 + wm0 + mt * 16 + (lane >> 2);
        #pragma unroll
        for (int nt = 0; nt < 8; nt++) {
            int col = n0 + wn0 + nt * 8 + (lane & 3) * 2;
            *(float2*)&C[(size_t)row * D1 + col]       = make_float2(acc[mt][nt][0], acc[mt][nt][1]);
            *(float2*)&C[(size_t)(row + 8) * D1 + col] = make_float2(acc[mt][nt][2], acc[mt][nt][3]);
        }
    }
}

// ---------------------------------------------------------------------------
// Launch
// ---------------------------------------------------------------------------
extern "C" void kernel_launch(void* const* d_in, const int* in_sizes, int n_in,
                              void* d_out, int out_size) {
    const float* x1 = (const float*)d_in[0];   // [8192, 256]
    const float* x2 = (const float*)d_in[1];   // [8192, 128]
    const float* W1 = (const float*)d_in[2];   // [128, 256]
    const float* b1 = (const float*)d_in[3];   // [128]

    float* out = (float*)d_out;
    float* f1 = out;                          // [8192, 128]
    float* f2 = out + (size_t)N1 * D2;        // [8192, 256]

    float *sp, *wtp, *lsep, *pmaxp, *psump;
    __half *qh, *ql, *x2h, *x2l, *x2th, *x2tl, *x1h, *x1l;
    cudaGetSymbolAddress((void**)&sp, g_S);
    cudaGetSymbolAddress((void**)&wtp, g_Wt);
    cudaGetSymbolAddress((void**)&lsep, g_lse);
    cudaGetSymbolAddress((void**)&pmaxp, g_pmax);
    cudaGetSymbolAddress((void**)&psump, g_psum);
    cudaGetSymbolAddress((void**)&qh, g_qh);
    cudaGetSymbolAddress((void**)&ql, g_ql);
    cudaGetSymbolAddress((void**)&x2h, g_x2h);
    cudaGetSymbolAddress((void**)&x2l, g_x2l);
    cudaGetSymbolAddress((void**)&x2th, g_x2th);
    cudaGetSymbolAddress((void**)&x2tl, g_x2tl);
    cudaGetSymbolAddress((void**)&x1h, g_x1h);
    cudaGetSymbolAddress((void**)&x1l, g_x1l);

    cudaFuncSetAttribute((const void*)gemm_s_kernel,
                         cudaFuncAttributeMaxDynamicSharedMemorySize, SMEM_S);
    cudaFuncSetAttribute((const void*)gemm_f1_kernel,
                         cudaFuncAttributeMaxDynamicSharedMemorySize, F1_SMEM);
    cudaFuncSetAttribute((const void*)gemm_f2_kernel,
                         cudaFuncAttributeMaxDynamicSharedMemorySize, F2_SMEM);

    // 1) prep
    transpose_w_kernel<<<(D1 * D2 + 255) / 256, 256>>>(W1, wtp);
    q_gemm_kernel<<<N1 / 32, 256>>>(x1, wtp, qh, ql, b1);
    split_kernel<<<(N2 * D2 / 4 + 255) / 256, 256>>>(x2, N2 * D2, x2h, x2l);
    transpose_split_kernel<<<dim3(D2 / 32, N2 / 32), dim3(32, 8)>>>(x2, N2, D2, x2th, x2tl);
    split_kernel<<<(N1 * D1 / 4 + 255) / 256, 256>>>(x1, N1 * D1, x1h, x1l);
    // 2) S = q @ x2^T + row partials
    gemm_s_kernel<<<dim3(NBLK, N1 / 128), 256, SMEM_S>>>(
        qh, ql, x2h, x2l, sp, pmaxp, psump);
    // 3) combine partials -> lse
    lse_combine_kernel<<<N1 / 256, 256>>>(pmaxp, psump, lsep);
    // 4) f1 = softmax(S) @ x2
    gemm_f1_kernel<<<dim3(1, N1 / 64), 256, F1_SMEM>>>(sp, lsep, x2th, x2tl, f1);
    // 5) f2 = softmax(S)^T @ x1
    gemm_f2_kernel<<<dim3(D1 / 128, N2 / 128), 256, F2_SMEM>>>(sp, lsep, x1h, x1l, f2);
}

// round 7
// speedup vs baseline: 5.3418x; 1.1595x over previous
#include <cuda_runtime.h>
#include <cuda_fp16.h>
#include <cstdint>

#define N1 8192
#define N2 8192
#define D1 256
#define D2 128
#define NBLK (N2 / 128)   // 64 n-blocks in S gemm

// ---------------------------------------------------------------------------
// Scratch (__device__ globals; allocation-free rule)
// ---------------------------------------------------------------------------
__device__ float g_S[(size_t)N1 * N2];                 // 256 MB scores
__device__ float g_lse[N1];
__device__ float g_pmax[(size_t)NBLK * N1];            // per-block row max
__device__ float g_psum[(size_t)NBLK * N1];            // per-block row sumexp
__device__ __half g_qh[N1 * D2], g_ql[N1 * D2];
__device__ __half g_x2h[N2 * D2], g_x2l[N2 * D2];      // [n2][d2] K-major for S
__device__ __half g_x2t[D2 * N2];                      // [d2][n2] fp16, f1 B
__device__ __half g_x1f[(size_t)N1 * D1];              // [n1][d1] fp16, f2 B
__device__ float g_Wt[D1 * D2];

// ---------------------------------------------------------------------------
// Helpers
// ---------------------------------------------------------------------------
__device__ __forceinline__ uint32_t smem_u32(const void* p) {
    uint32_t a;
    asm("{ .reg .u64 t; cvta.to.shared.u64 t, %1; cvt.u32.u64 %0, t; }" : "=r"(a) : "l"(p));
    return a;
}
__device__ __forceinline__ void ldsm4(uint32_t r[4], uint32_t addr) {
    asm volatile("ldmatrix.sync.aligned.m8n8.x4.shared.b16 {%0,%1,%2,%3}, [%4];"
                 : "=r"(r[0]), "=r"(r[1]), "=r"(r[2]), "=r"(r[3]) : "r"(addr));
}
__device__ __forceinline__ void ldsm4t(uint32_t r[4], uint32_t addr) {
    asm volatile("ldmatrix.sync.aligned.m8n8.x4.trans.shared.b16 {%0,%1,%2,%3}, [%4];"
                 : "=r"(r[0]), "=r"(r[1]), "=r"(r[2]), "=r"(r[3]) : "r"(addr));
}
__device__ __forceinline__ void mma16816(float c[4], const uint32_t a[4], const uint32_t b[2]) {
    asm volatile("mma.sync.aligned.m16n8k16.row.col.f32.f16.f16.f32 "
                 "{%0,%1,%2,%3}, {%4,%5,%6,%7}, {%8,%9}, {%0,%1,%2,%3};"
                 : "+f"(c[0]), "+f"(c[1]), "+f"(c[2]), "+f"(c[3])
                 : "r"(a[0]), "r"(a[1]), "r"(a[2]), "r"(a[3]), "r"(b[0]), "r"(b[1]));
}
__device__ __forceinline__ void split_h(float v, __half& h, __half& l) {
    h = __float2half(v);
    l = __float2half(v - __half2float(h));
}
__device__ __forceinline__ void sts8(uint32_t addr, uint32_t a, uint32_t b) {
    asm volatile("st.shared.v2.b32 [%0], {%1, %2};" :: "r"(addr), "r"(a), "r"(b) : "memory");
}
__device__ __forceinline__ void exp_h4(float4 v, float lse, uint32_t& h0, uint32_t& h1) {
    __half2 a = __floats2half2_rn(__expf(v.x - lse), __expf(v.y - lse));
    __half2 b = __floats2half2_rn(__expf(v.z - lse), __expf(v.w - lse));
    h0 = *reinterpret_cast<uint32_t*>(&a);
    h1 = *reinterpret_cast<uint32_t*>(&b);
}

// ---------------------------------------------------------------------------
// Prep kernels
// ---------------------------------------------------------------------------
__global__ void transpose_w_kernel(const float* __restrict__ W1, float* __restrict__ Wt) {
    int idx = blockIdx.x * blockDim.x + threadIdx.x;
    if (idx < D1 * D2) {
        int n = idx / D1, k = idx % D1;
        Wt[k * D2 + n] = W1[idx];
    }
}

__global__ void q_gemm_kernel(const float* __restrict__ A, const float* __restrict__ B,
                              __half* __restrict__ Ch, __half* __restrict__ Cl,
                              const float* __restrict__ bias) {
    __shared__ float As[32][16];
    __shared__ float Bs[16][128];
    const int m0 = blockIdx.x * 32;
    const int tid = threadIdx.x;
    const int ty = tid >> 4, tx = tid & 15;
    float acc0[8] = {}, acc1[8] = {};

    for (int k0 = 0; k0 < D1; k0 += 16) {
        {
            int m = tid >> 3, k2 = (tid & 7) * 2;
            const float* p = A + (size_t)(m0 + m) * D1 + k0 + k2;
            As[m][k2] = p[0]; As[m][k2 + 1] = p[1];
        }
        #pragma unroll
        for (int c = 0; c < 2; c++) {
            int idx = c * 1024 + tid * 4;
            int k = idx >> 7, n = idx & 127;
            *(float4*)&Bs[k][n] = *(const float4*)(B + (size_t)(k0 + k) * 128 + n);
        }
        __syncthreads();
        #pragma unroll
        for (int k = 0; k < 16; k++) {
            float a0 = As[ty * 2][k], a1 = As[ty * 2 + 1][k];
            float4 b0 = *(const float4*)&Bs[k][tx * 8];
            float4 b1 = *(const float4*)&Bs[k][tx * 8 + 4];
            acc0[0] += a0 * b0.x; acc0[1] += a0 * b0.y; acc0[2] += a0 * b0.z; acc0[3] += a0 * b0.w;
            acc0[4] += a0 * b1.x; acc0[5] += a0 * b1.y; acc0[6] += a0 * b1.z; acc0[7] += a0 * b1.w;
            acc1[0] += a1 * b0.x; acc1[1] += a1 * b0.y; acc1[2] += a1 * b0.z; acc1[3] += a1 * b0.w;
            acc1[4] += a1 * b1.x; acc1[5] += a1 * b1.y; acc1[6] += a1 * b1.z; acc1[7] += a1 * b1.w;
        }
        __syncthreads();
    }
    int m = m0 + ty * 2;
    #pragma unroll
    for (int j = 0; j < 8; j++) {
        float bv = bias[tx * 8 + j];
        __half h, l;
        split_h(acc0[j] + bv, h, l);
        Ch[(size_t)m * 128 + tx * 8 + j] = h; Cl[(size_t)m * 128 + tx * 8 + j] = l;
        split_h(acc1[j] + bv, h, l);
        Ch[(size_t)(m + 1) * 128 + tx * 8 + j] = h; Cl[(size_t)(m + 1) * 128 + tx * 8 + j] = l;
    }
}

__global__ void split_kernel(const float* __restrict__ in, int n,
                             __half* __restrict__ oh, __half* __restrict__ ol) {
    int i = blockIdx.x * blockDim.x + threadIdx.x;
    if (i * 4 < n) {
        float4 v = *(const float4*)(in + (size_t)i * 4);
        __half h, l;
        size_t o = (size_t)i * 4;
        split_h(v.x, h, l); oh[o] = h;     ol[o] = l;
        split_h(v.y, h, l); oh[o + 1] = h; ol[o + 1] = l;
        split_h(v.z, h, l); oh[o + 2] = h; ol[o + 2] = l;
        split_h(v.w, h, l); oh[o + 3] = h; ol[o + 3] = l;
    }
}

// plain fp32 -> fp16
__global__ void tofp16_kernel(const float* __restrict__ in, int n, __half* __restrict__ o) {
    int i = blockIdx.x * blockDim.x + threadIdx.x;
    if (i * 4 < n) {
        float4 v = *(const float4*)(in + (size_t)i * 4);
        __half2 a = __floats2half2_rn(v.x, v.y);
        __half2 b = __floats2half2_rn(v.z, v.w);
        *(__half2*)(o + (size_t)i * 4)     = a;
        *(__half2*)(o + (size_t)i * 4 + 2) = b;
    }
}

// transpose fp32 [R][C] -> fp16 [C][R]
__global__ void transpose_h_kernel(const float* __restrict__ in, int R, int C,
                                   __half* __restrict__ o) {
    __shared__ float t[32][33];
    int c0 = blockIdx.x * 32, r0 = blockIdx.y * 32;
    for (int i = threadIdx.y; i < 32; i += 8)
        t[i][threadIdx.x] = in[(size_t)(r0 + i) * C + c0 + threadIdx.x];
    __syncthreads();
    for (int i = threadIdx.y; i < 32; i += 8)
        o[(size_t)(c0 + i) * R + r0 + threadIdx.x] = __float2half(t[threadIdx.x][i]);
}

// ---------------------------------------------------------------------------
// lse combine
// ---------------------------------------------------------------------------
__global__ void lse_combine_kernel(const float* __restrict__ pmax,
                                   const float* __restrict__ psum,
                                   float* __restrict__ lse) {
    int row = blockIdx.x * 256 + threadIdx.x;
    float M = -1e30f;
    #pragma unroll 8
    for (int nb = 0; nb < NBLK; nb++)
        M = fmaxf(M, pmax[(size_t)nb * N1 + row]);
    float s = 0.0f;
    #pragma unroll 8
    for (int nb = 0; nb < NBLK; nb++)
        s += psum[(size_t)nb * N1 + row] * __expf(pmax[(size_t)nb * N1 + row] - M);
    lse[row] = M + __logf(s);
}

// ---------------------------------------------------------------------------
// S GEMM: NT mma.sync split-fp16 3-MMA + per-block row (max,sumexp) partials.
// ---------------------------------------------------------------------------
static constexpr int S_STAGE = 2 * (128 + 128) * 128;     // 64 KB
static constexpr int SMEM_S  = 3 * S_STAGE;               // 192 KB

__device__ __forceinline__ void s_load_stage(
    uint32_t base, int tid, int m0, int n0, int k0,
    const __half* Ah, const __half* Al, const __half* Bh, const __half* Bl) {
    #pragma unroll
    for (int it = 0; it < 16; it++) {
        int i = tid + it * 256;
        int c = i & 7, row = i >> 3;
        const __half* src;
        if (row < 128)       src = Ah + (size_t)(m0 + row) * D2 + k0 + c * 8;
        else if (row < 256)  src = Al + (size_t)(m0 + row - 128) * D2 + k0 + c * 8;
        else if (row < 384)  src = Bh + (size_t)(n0 + row - 256) * D2 + k0 + c * 8;
        else                 src = Bl + (size_t)(n0 + row - 384) * D2 + k0 + c * 8;
        uint32_t dst = base + row * 128 + ((c ^ (row & 7)) << 4);
        asm volatile("cp.async.cg.shared.global [%0], [%1], 16;" :: "r"(dst), "l"(src) : "memory");
    }
    asm volatile("cp.async.commit_group;" ::: "memory");
}

__global__ __launch_bounds__(256, 1) void gemm_s_kernel(
    const __half* __restrict__ Ah, const __half* __restrict__ Al,
    const __half* __restrict__ Bh, const __half* __restrict__ Bl,
    float* __restrict__ C, float* __restrict__ pmax, float* __restrict__ psum) {
    extern __shared__ char smem[];
    const int tid = threadIdx.x, wid = tid >> 5, lane = tid & 31;
    const int m0 = blockIdx.y * 128, n0 = blockIdx.x * 128;
    const int wm0 = (wid & 3) * 32, wn0 = (wid >> 2) * 64;
    uint32_t sb = smem_u32(smem);

    const int a_r = lane & 15, a_k = lane >> 4;
    const int b_r = (lane & 7) + ((lane >> 4) << 3), b_k = (lane >> 3) & 1;

    float acc[2][8][4] = {};
    const int nCh = D2 >> 6;   // 2
    s_load_stage(sb, tid, m0, n0, 0, Ah, Al, Bh, Bl);
    s_load_stage(sb + S_STAGE, tid, m0, n0, 64, Ah, Al, Bh, Bl);

    for (int c = 0; c < nCh; c++) {
        asm volatile("cp.async.wait_group %0;" :: "n"(0) : "memory");
        __syncthreads();
        const uint32_t st = sb + c * S_STAGE;
        #pragma unroll
        for (int ks = 0; ks < 4; ks++) {
            uint32_t afh[2][4], afl[2][4];
            #pragma unroll
            for (int mt = 0; mt < 2; mt++) {
                int r = wm0 + mt * 16 + a_r;
                int kc = ks * 2 + a_k;
                uint32_t col = (uint32_t)((kc ^ (r & 7)) << 4);
                ldsm4(afh[mt], st + r * 128 + col);
                ldsm4(afl[mt], st + (128 + r) * 128 + col);
            }
            uint32_t bfh[8][2], bfl[8][2];
            #pragma unroll
            for (int nt = 0; nt < 8; nt += 2) {
                int r = wn0 + nt * 8 + b_r;
                int kc = ks * 2 + b_k;
                uint32_t col = (uint32_t)((kc ^ (r & 7)) << 4);
                uint32_t t[4];
                ldsm4(t, st + (256 + r) * 128 + col);
                bfh[nt][0] = t[0]; bfh[nt][1] = t[1];
                bfh[nt + 1][0] = t[2]; bfh[nt + 1][1] = t[3];
                ldsm4(t, st + (384 + r) * 128 + col);
                bfl[nt][0] = t[0]; bfl[nt][1] = t[1];
                bfl[nt + 1][0] = t[2]; bfl[nt + 1][1] = t[3];
            }
            #pragma unroll
            for (int mt = 0; mt < 2; mt++)
                #pragma unroll
                for (int nt = 0; nt < 8; nt++) {
                    mma16816(acc[mt][nt], afh[mt], bfh[nt]);
                    mma16816(acc[mt][nt], afh[mt], bfl[nt]);
                    mma16816(acc[mt][nt], afl[mt], bfh[nt]);
                }
        }
        __syncthreads();
    }

    #pragma unroll
    for (int mt = 0; mt < 2; mt++) {
        int row = m0 + wm0 + mt * 16 + (lane >> 2);
        #pragma unroll
        for (int nt = 0; nt < 8; nt++) {
            int col = n0 + wn0 + nt * 8 + (lane & 3) * 2;
            *(float2*)&C[(size_t)row * N2 + col]       = make_float2(acc[mt][nt][0], acc[mt][nt][1]);
            *(float2*)&C[(size_t)(row + 8) * N2 + col] = make_float2(acc[mt][nt][2], acc[mt][nt][3]);
        }
    }

    // per-block row (max, sumexp) partials over this 128-col slab
    float* pm = (float*)smem;          // [8][32]
    float* ps = pm + 256;              // [8][32]
    #pragma unroll
    for (int mt = 0; mt < 2; mt++) {
        #pragma unroll
        for (int half = 0; half < 2; half++) {
            float mx = -1e30f;
            #pragma unroll
            for (int nt = 0; nt < 8; nt++)
                mx = fmaxf(mx, fmaxf(acc[mt][nt][2 * half], acc[mt][nt][2 * half + 1]));
            mx = fmaxf(mx, __shfl_xor_sync(~0u, mx, 1));
            mx = fmaxf(mx, __shfl_xor_sync(~0u, mx, 2));
            float sm = 0.0f;
            #pragma unroll
            for (int nt = 0; nt < 8; nt++)
                sm += __expf(acc[mt][nt][2 * half] - mx) + __expf(acc[mt][nt][2 * half + 1] - mx);
            sm += __shfl_xor_sync(~0u, sm, 1);
            sm += __shfl_xor_sync(~0u, sm, 2);
            if ((lane & 3) == 0) {
                int rlw = mt * 16 + half * 8 + (lane >> 2);
                pm[wid * 32 + rlw] = mx;
                ps[wid * 32 + rlw] = sm;
            }
        }
    }
    __syncthreads();
    if (tid < 128) {
        int g = tid >> 5, rlw = tid & 31;
        float m1 = pm[g * 32 + rlw], m2 = pm[(g + 4) * 32 + rlw];
        float M = fmaxf(m1, m2);
        float s = ps[g * 32 + rlw] * __expf(m1 - M) + ps[(g + 4) * 32 + rlw] * __expf(m2 - M);
        pmax[(size_t)blockIdx.x * N1 + m0 + tid] = M;
        psum[(size_t)blockIdx.x * N1 + m0 + tid] = s;
    }
}

// ---------------------------------------------------------------------------
// f1 = attn @ x2 : NT GEMM, A = exp(S-lse) fp16 fused, B = x2t fp16. 1 MMA.
// BM=64, BN=128. smem: A 2x8KB + B 2x16KB = 48KB
// ---------------------------------------------------------------------------
static constexpr int F1_A_STAGE = 64 * 128;          // 8 KB
static constexpr int F1_B_OFF   = 2 * F1_A_STAGE;    // 16 KB
static constexpr int F1_B_STAGE = 128 * 128;         // 16 KB
static constexpr int F1_SMEM    = F1_B_OFF + 2 * F1_B_STAGE;  // 48 KB

__global__ __launch_bounds__(256, 1) void gemm_f1_kernel(
    const float* __restrict__ S, const float* __restrict__ lse,
    const __half* __restrict__ Bh, float* __restrict__ C) {
    extern __shared__ char smem[];
    uint32_t sb = smem_u32(smem);
    const int tid = threadIdx.x, wid = tid >> 5, lane = tid & 31;
    const int m0 = blockIdx.y * 64;
    const int wm0 = (wid & 1) * 32, wn0 = (wid >> 1) * 32;
    const int a_r = lane & 15, a_k = lane >> 4;
    const int b_r = (lane & 7) + ((lane >> 4) << 3), b_k = (lane >> 3) & 1;

    float acc[2][4][4] = {};
    float4 areg[4];
    const int nCh = N2 >> 6;   // 128

    float tl[4];
    #pragma unroll
    for (int it = 0; it < 4; it++) tl[it] = lse[m0 + ((tid + it * 256) >> 4)];

    auto ldgA = [&](int c) {
        #pragma unroll
        for (int it = 0; it < 4; it++) {
            int idx = tid + it * 256;
            int m = idx >> 4, kq = idx & 15;
            areg[it] = *(const float4*)(S + (size_t)(m0 + m) * N2 + c * 64 + kq * 4);
        }
    };
    auto stsA = [&](int buf) {
        uint32_t ab = sb + buf * F1_A_STAGE;
        #pragma unroll
        for (int it = 0; it < 4; it++) {
            int idx = tid + it * 256;
            int m = idx >> 4, kq = idx & 15;
            uint32_t h0, h1;
            exp_h4(areg[it], tl[it], h0, h1);
            uint32_t off = m * 128 + (((kq >> 1) ^ (m & 7)) << 4) + (kq & 1) * 8;
            sts8(ab + off, h0, h1);
        }
    };
    auto ldB = [&](int c, int buf) {
        uint32_t bb = sb + F1_B_OFF + buf * F1_B_STAGE;
        #pragma unroll
        for (int it = 0; it < 4; it++) {
            int i = tid + it * 256;
            int n = i >> 3, cc = i & 7;
            const __half* src = Bh + (size_t)n * N2 + c * 64 + cc * 8;
            uint32_t dst = bb + n * 128 + ((cc ^ (n & 7)) << 4);
            asm volatile("cp.async.cg.shared.global [%0], [%1], 16;" :: "r"(dst), "l"(src) : "memory");
        }
        asm volatile("cp.async.commit_group;" ::: "memory");
    };

    ldgA(0); stsA(0); ldB(0, 0);

    for (int c = 0; c < nCh; c++) {
        const bool more = (c + 1 < nCh);
        if (more) ldgA(c + 1);
        asm volatile("cp.async.wait_group 0;" ::: "memory");
        __syncthreads();
        if (more) ldB(c + 1, (c + 1) & 1);

        const uint32_t ast = sb + (c & 1) * F1_A_STAGE;
        const uint32_t bst = sb + F1_B_OFF + (c & 1) * F1_B_STAGE;
        #pragma unroll
        for (int ks = 0; ks < 4; ks++) {
            uint32_t afh[2][4];
            #pragma unroll
            for (int mt = 0; mt < 2; mt++) {
                int r = wm0 + mt * 16 + a_r;
                int kc = ks * 2 + a_k;
                uint32_t col = (uint32_t)((kc ^ (r & 7)) << 4);
                ldsm4(afh[mt], ast + r * 128 + col);
            }
            uint32_t bfh[4][2];
            #pragma unroll
            for (int nt = 0; nt < 4; nt += 2) {
                int r = wn0 + nt * 8 + b_r;
                int kc = ks * 2 + b_k;
                uint32_t col = (uint32_t)((kc ^ (r & 7)) << 4);
                uint32_t t[4];
                ldsm4(t, bst + r * 128 + col);
                bfh[nt][0] = t[0]; bfh[nt][1] = t[1];
                bfh[nt + 1][0] = t[2]; bfh[nt + 1][1] = t[3];
            }
            #pragma unroll
            for (int mt = 0; mt < 2; mt++)
                #pragma unroll
                for (int nt = 0; nt < 4; nt++)
                    mma16816(acc[mt][nt], afh[mt], bfh[nt]);
        }
        if (more) stsA((c + 1) & 1);
    }

    #pragma unroll
    for (int mt = 0; mt < 2; mt++) {
        int row = m0 + wm0 + mt * 16 + (lane >> 2);
        #pragma unroll
        for (int nt = 0; nt < 4; nt++) {
            int col = wn0 + nt * 8 + (lane & 3) * 2;
            *(float2*)&C[(size_t)row * D2 + col]       = make_float2(acc[mt][nt][0], acc[mt][nt][1]);
            *(float2*)&C[(size_t)(row + 8) * D2 + col] = make_float2(acc[mt][nt][2], acc[mt][nt][3]);
        }
    }
}

// ---------------------------------------------------------------------------
// f2 = attn^T @ x1 : TN GEMM, A = exp(S-lse) fp16 fused, B = x1 fp16. 1 MMA.
// BM=128, BN=128. smem: A 2x16KB + B 2x16KB = 64KB
// ---------------------------------------------------------------------------
static constexpr int F2_A_STAGE = 64 * 256;          // 16 KB
static constexpr int F2_B_OFF   = 2 * F2_A_STAGE;    // 32 KB
static constexpr int F2_B_STAGE = 64 * 256;          // 16 KB
static constexpr int F2_SMEM    = F2_B_OFF + 2 * F2_B_STAGE;  // 64 KB

__global__ __launch_bounds__(256, 1) void gemm_f2_kernel(
    const float* __restrict__ S, const float* __restrict__ lse,
    const __half* __restrict__ Bh, float* __restrict__ C) {
    extern __shared__ char smem[];
    uint32_t sb = smem_u32(smem);
    const int tid = threadIdx.x, wid = tid >> 5, lane = tid & 31;
    const int m0 = blockIdx.y * 128, n0 = blockIdx.x * 128;
    const int wm0 = (wid & 3) * 32, wn0 = (wid >> 2) * 64;
    const int lt = lane >> 3, li = lane & 7;

    float acc[2][8][4] = {};
    float4 areg[8];
    float lreg[8];
    const int nCh = N1 >> 6;   // 128

    auto ldgA = [&](int c) {
        #pragma unroll
        for (int it = 0; it < 8; it++) {
            int idx = tid + it * 256;
            int k = idx >> 5, mq = idx & 31;
            areg[it] = *(const float4*)(S + (size_t)(c * 64 + k) * N2 + m0 + mq * 4);
            lreg[it] = __ldg(lse + c * 64 + k);
        }
    };
    auto stsA = [&](int buf) {
        uint32_t ab = sb + buf * F2_A_STAGE;
        #pragma unroll
        for (int it = 0; it < 8; it++) {
            int idx = tid + it * 256;
            int k = idx >> 5, mq = idx & 31;
            uint32_t h0, h1;
            exp_h4(areg[it], lreg[it], h0, h1);
            uint32_t off = k * 256 + (((mq >> 1) ^ (k & 7)) << 4) + (mq & 1) * 8;
            sts8(ab + off, h0, h1);
        }
    };
    auto ldB = [&](int c, int buf) {
        uint32_t bb = sb + F2_B_OFF + buf * F2_B_STAGE;
        #pragma unroll
        for (int it = 0; it < 4; it++) {
            int i = tid + it * 256;
            int k = i >> 4, cc = i & 15;
            const __half* src = Bh + (size_t)(c * 64 + k) * D1 + n0 + cc * 8;
            uint32_t dst = bb + k * 256 + ((cc ^ (k & 7)) << 4);
            asm volatile("cp.async.cg.shared.global [%0], [%1], 16;" :: "r"(dst), "l"(src) : "memory");
        }
        asm volatile("cp.async.commit_group;" ::: "memory");
    };

    ldgA(0); stsA(0); ldB(0, 0);

    for (int c = 0; c < nCh; c++) {
        const bool more = (c + 1 < nCh);
        if (more) ldgA(c + 1);
        asm volatile("cp.async.wait_group 0;" ::: "memory");
        __syncthreads();
        if (more) ldB(c + 1, (c + 1) & 1);

        const uint32_t ast = sb + (c & 1) * F2_A_STAGE;
        const uint32_t bst = sb + F2_B_OFF + (c & 1) * F2_B_STAGE;
        #pragma unroll
        for (int ks = 0; ks < 4; ks++) {
            uint32_t afh[2][4];
            #pragma unroll
            for (int mt = 0; mt < 2; mt++) {
                int mb = wm0 + mt * 16 + (lt & 1) * 8;
                int k = ks * 16 + (lt >> 1) * 8 + li;
                uint32_t addr = k * 256 + (((mb >> 3) ^ (k & 7)) << 4);
                ldsm4t(afh[mt], ast + addr);
            }
            uint32_t bfh[8][2];
            #pragma unroll
            for (int nt = 0; nt < 8; nt += 2) {
                int nb = wn0 + nt * 8 + (lt >> 1) * 8;
                int k = ks * 16 + (lt & 1) * 8 + li;
                uint32_t addr = k * 256 + (((nb >> 3) ^ (k & 7)) << 4);
                uint32_t t[4];
                ldsm4t(t, bst + addr);
                bfh[nt][0] = t[0]; bfh[nt][1] = t[1];
                bfh[nt + 1][0] = t[2]; bfh[nt + 1][1] = t[3];
            }
            #pragma unroll
            for (int mt = 0; mt < 2; mt++)
                #pragma unroll
                for (int nt = 0; nt < 8; nt++)
                    mma16816(acc[mt][nt], afh[mt], bfh[nt]);
        }
        if (more) stsA((c + 1) & 1);
    }

    #pragma unroll
    for (int mt = 0; mt < 2; mt++) {
        int row = m0 + wm0 + mt * 16 + (lane >> 2);
        #pragma unroll
        for (int nt = 0; nt < 8; nt++) {
            int col = n0 + wn0 + nt * 8 + (lane & 3) * 2;
            *(float2*)&C[(size_t)row * D1 + col]       = make_float2(acc[mt][nt][0], acc[mt][nt][1]);
            *(float2*)&C[(size_t)(row + 8) * D1 + col] = make_float2(acc[mt][nt][2], acc[mt][nt][3]);
        }
    }
}

// ---------------------------------------------------------------------------
// Launch
// ---------------------------------------------------------------------------
extern "C" void kernel_launch(void* const* d_in, const int* in_sizes, int n_in,
                              void* d_out, int out_size) {
    const float* x1 = (const float*)d_in[0];   // [8192, 256]
    const float* x2 = (const float*)d_in[1];   // [8192, 128]
    const float* W1 = (const float*)d_in[2];   // [128, 256]
    const float* b1 = (const float*)d_in[3];   // [128]

    float* out = (float*)d_out;
    float* f1 = out;                          // [8192, 128]
    float* f2 = out + (size_t)N1 * D2;        // [8192, 256]

    float *sp, *wtp, *lsep, *pmaxp, *psump;
    __half *qh, *ql, *x2h, *x2l, *x2t, *x1f;
    cudaGetSymbolAddress((void**)&sp, g_S);
    cudaGetSymbolAddress((void**)&wtp, g_Wt);
    cudaGetSymbolAddress((void**)&lsep, g_lse);
    cudaGetSymbolAddress((void**)&pmaxp, g_pmax);
    cudaGetSymbolAddress((void**)&psump, g_psum);
    cudaGetSymbolAddress((void**)&qh, g_qh);
    cudaGetSymbolAddress((void**)&ql, g_ql);
    cudaGetSymbolAddress((void**)&x2h, g_x2h);
    cudaGetSymbolAddress((void**)&x2l, g_x2l);
    cudaGetSymbolAddress((void**)&x2t, g_x2t);
    cudaGetSymbolAddress((void**)&x1f, g_x1f);

    cudaFuncSetAttribute((const void*)gemm_s_kernel,
                         cudaFuncAttributeMaxDynamicSharedMemorySize, SMEM_S);
    cudaFuncSetAttribute((const void*)gemm_f1_kernel,
                         cudaFuncAttributeMaxDynamicSharedMemorySize, F1_SMEM);
    cudaFuncSetAttribute((const void*)gemm_f2_kernel,
                         cudaFuncAttributeMaxDynamicSharedMemorySize, F2_SMEM);

    // 1) prep
    transpose_w_kernel<<<(D1 * D2 + 255) / 256, 256>>>(W1, wtp);
    q_gemm_kernel<<<N1 / 32, 256>>>(x1, wtp, qh, ql, b1);
    split_kernel<<<(N2 * D2 / 4 + 255) / 256, 256>>>(x2, N2 * D2, x2h, x2l);
    transpose_h_kernel<<<dim3(D2 / 32, N2 / 32), dim3(32, 8)>>>(x2, N2, D2, x2t);
    tofp16_kernel<<<(N1 * D1 / 4 + 255) / 256, 256>>>(x1, N1 * D1, x1f);
    // 2) S = q @ x2^T + row partials
    gemm_s_kernel<<<dim3(NBLK, N1 / 128), 256, SMEM_S>>>(
        qh, ql, x2h, x2l, sp, pmaxp, psump);
    // 3) combine partials -> lse
    lse_combine_kernel<<<N1 / 256, 256>>>(pmaxp, psump, lsep);
    // 4) f1 = softmax(S) @ x2
    gemm_f1_kernel<<<dim3(1, N1 / 64), 256, F1_SMEM>>>(sp, lsep, x2t, f1);
    // 5) f2 = softmax(S)^T @ x1
    gemm_f2_kernel<<<dim3(D1 / 128, N2 / 128), 256, F2_SMEM>>>(sp, lsep, x1f, f2);
}

// round 8
// speedup vs baseline: 5.4654x; 1.0231x over previous
#include <cuda_runtime.h>
#include <cuda_fp16.h>
#include <cstdint>

#define N1 8192
#define N2 8192
#define D1 256
#define D2 128
#define NBLK (N2 / 128)   // 64 column-slabs of S/E

// ---------------------------------------------------------------------------
// Scratch (__device__ globals; allocation-free rule)
// ---------------------------------------------------------------------------
__device__ __half g_E[(size_t)N1 * N2];                // 128 MB: exp(S - pmax_slab)
__device__ float g_lse[N1];
__device__ float g_pmax[(size_t)NBLK * N1];            // per-slab row max
__device__ float g_psum[(size_t)NBLK * N1];            // per-slab row sumexp
__device__ __half g_qh[N1 * D2], g_ql[N1 * D2];
__device__ __half g_x2h[N2 * D2], g_x2l[N2 * D2];      // [n2][d2] K-major for S
__device__ __half g_x2t[D2 * N2];                      // [d2][n2] fp16, f1 B
__device__ __half g_x1f[(size_t)N1 * D1];              // [n1][d1] fp16, f2 B
__device__ float g_Wt[D1 * D2];

// ---------------------------------------------------------------------------
// Helpers
// ---------------------------------------------------------------------------
__device__ __forceinline__ uint32_t smem_u32(const void* p) {
    uint32_t a;
    asm("{ .reg .u64 t; cvta.to.shared.u64 t, %1; cvt.u32.u64 %0, t; }" : "=r"(a) : "l"(p));
    return a;
}
__device__ __forceinline__ void ldsm4(uint32_t r[4], uint32_t addr) {
    asm volatile("ldmatrix.sync.aligned.m8n8.x4.shared.b16 {%0,%1,%2,%3}, [%4];"
                 : "=r"(r[0]), "=r"(r[1]), "=r"(r[2]), "=r"(r[3]) : "r"(addr));
}
__device__ __forceinline__ void ldsm4t(uint32_t r[4], uint32_t addr) {
    asm volatile("ldmatrix.sync.aligned.m8n8.x4.trans.shared.b16 {%0,%1,%2,%3}, [%4];"
                 : "=r"(r[0]), "=r"(r[1]), "=r"(r[2]), "=r"(r[3]) : "r"(addr));
}
__device__ __forceinline__ void mma16816(float c[4], const uint32_t a[4], const uint32_t b[2]) {
    asm volatile("mma.sync.aligned.m16n8k16.row.col.f32.f16.f16.f32 "
                 "{%0,%1,%2,%3}, {%4,%5,%6,%7}, {%8,%9}, {%0,%1,%2,%3};"
                 : "+f"(c[0]), "+f"(c[1]), "+f"(c[2]), "+f"(c[3])
                 : "r"(a[0]), "r"(a[1]), "r"(a[2]), "r"(a[3]), "r"(b[0]), "r"(b[1]));
}
__device__ __forceinline__ void split_h(float v, __half& h, __half& l) {
    h = __float2half(v);
    l = __float2half(v - __half2float(h));
}
__device__ __forceinline__ void sts16(uint32_t addr, uint32_t a, uint32_t b,
                                      uint32_t c, uint32_t d) {
    asm volatile("st.shared.v4.b32 [%0], {%1,%2,%3,%4};"
                 :: "r"(addr), "r"(a), "r"(b), "r"(c), "r"(d) : "memory");
}
__device__ __forceinline__ uint32_t mulh2(uint32_t e, uint32_t s) {
    __half2 r = __hmul2(*(__half2*)&e, *(__half2*)&s);
    return *(uint32_t*)&r;
}

// ---------------------------------------------------------------------------
// Prep kernels
// ---------------------------------------------------------------------------
__global__ void transpose_w_kernel(const float* __restrict__ W1, float* __restrict__ Wt) {
    int idx = blockIdx.x * blockDim.x + threadIdx.x;
    if (idx < D1 * D2) {
        int n = idx / D1, k = idx % D1;
        Wt[k * D2 + n] = W1[idx];
    }
}

__global__ void q_gemm_kernel(const float* __restrict__ A, const float* __restrict__ B,
                              __half* __restrict__ Ch, __half* __restrict__ Cl,
                              const float* __restrict__ bias) {
    __shared__ float As[32][16];
    __shared__ float Bs[16][128];
    const int m0 = blockIdx.x * 32;
    const int tid = threadIdx.x;
    const int ty = tid >> 4, tx = tid & 15;
    float acc0[8] = {}, acc1[8] = {};

    for (int k0 = 0; k0 < D1; k0 += 16) {
        {
            int m = tid >> 3, k2 = (tid & 7) * 2;
            const float* p = A + (size_t)(m0 + m) * D1 + k0 + k2;
            As[m][k2] = p[0]; As[m][k2 + 1] = p[1];
        }
        #pragma unroll
        for (int c = 0; c < 2; c++) {
            int idx = c * 1024 + tid * 4;
            int k = idx >> 7, n = idx & 127;
            *(float4*)&Bs[k][n] = *(const float4*)(B + (size_t)(k0 + k) * 128 + n);
        }
        __syncthreads();
        #pragma unroll
        for (int k = 0; k < 16; k++) {
            float a0 = As[ty * 2][k], a1 = As[ty * 2 + 1][k];
            float4 b0 = *(const float4*)&Bs[k][tx * 8];
            float4 b1 = *(const float4*)&Bs[k][tx * 8 + 4];
            acc0[0] += a0 * b0.x; acc0[1] += a0 * b0.y; acc0[2] += a0 * b0.z; acc0[3] += a0 * b0.w;
            acc0[4] += a0 * b1.x; acc0[5] += a0 * b1.y; acc0[6] += a0 * b1.z; acc0[7] += a0 * b1.w;
            acc1[0] += a1 * b0.x; acc1[1] += a1 * b0.y; acc1[2] += a1 * b0.z; acc1[3] += a1 * b0.w;
            acc1[4] += a1 * b1.x; acc1[5] += a1 * b1.y; acc1[6] += a1 * b1.z; acc1[7] += a1 * b1.w;
        }
        __syncthreads();
    }
    int m = m0 + ty * 2;
    #pragma unroll
    for (int j = 0; j < 8; j++) {
        float bv = bias[tx * 8 + j];
        __half h, l;
        split_h(acc0[j] + bv, h, l);
        Ch[(size_t)m * 128 + tx * 8 + j] = h; Cl[(size_t)m * 128 + tx * 8 + j] = l;
        split_h(acc1[j] + bv, h, l);
        Ch[(size_t)(m + 1) * 128 + tx * 8 + j] = h; Cl[(size_t)(m + 1) * 128 + tx * 8 + j] = l;
    }
}

__global__ void split_kernel(const float* __restrict__ in, int n,
                             __half* __restrict__ oh, __half* __restrict__ ol) {
    int i = blockIdx.x * blockDim.x + threadIdx.x;
    if (i * 4 < n) {
        float4 v = *(const float4*)(in + (size_t)i * 4);
        __half h, l;
        size_t o = (size_t)i * 4;
        split_h(v.x, h, l); oh[o] = h;     ol[o] = l;
        split_h(v.y, h, l); oh[o + 1] = h; ol[o + 1] = l;
        split_h(v.z, h, l); oh[o + 2] = h; ol[o + 2] = l;
        split_h(v.w, h, l); oh[o + 3] = h; ol[o + 3] = l;
    }
}

__global__ void tofp16_kernel(const float* __restrict__ in, int n, __half* __restrict__ o) {
    int i = blockIdx.x * blockDim.x + threadIdx.x;
    if (i * 4 < n) {
        float4 v = *(const float4*)(in + (size_t)i * 4);
        __half2 a = __floats2half2_rn(v.x, v.y);
        __half2 b = __floats2half2_rn(v.z, v.w);
        *(__half2*)(o + (size_t)i * 4)     = a;
        *(__half2*)(o + (size_t)i * 4 + 2) = b;
    }
}

__global__ void transpose_h_kernel(const float* __restrict__ in, int R, int C,
                                   __half* __restrict__ o) {
    __shared__ float t[32][33];
    int c0 = blockIdx.x * 32, r0 = blockIdx.y * 32;
    for (int i = threadIdx.y; i < 32; i += 8)
        t[i][threadIdx.x] = in[(size_t)(r0 + i) * C + c0 + threadIdx.x];
    __syncthreads();
    for (int i = threadIdx.y; i < 32; i += 8)
        o[(size_t)(c0 + i) * R + r0 + threadIdx.x] = __float2half(t[threadIdx.x][i]);
}

// ---------------------------------------------------------------------------
// lse combine
// ---------------------------------------------------------------------------
__global__ void lse_combine_kernel(const float* __restrict__ pmax,
                                   const float* __restrict__ psum,
                                   float* __restrict__ lse) {
    int row = blockIdx.x * 256 + threadIdx.x;
    float M = -1e30f;
    #pragma unroll 8
    for (int nb = 0; nb < NBLK; nb++)
        M = fmaxf(M, pmax[(size_t)nb * N1 + row]);
    float s = 0.0f;
    #pragma unroll 8
    for (int nb = 0; nb < NBLK; nb++)
        s += psum[(size_t)nb * N1 + row] * __expf(pmax[(size_t)nb * N1 + row] - M);
    lse[row] = M + __logf(s);
}

// ---------------------------------------------------------------------------
// S GEMM: split-fp16 3-MMA; epilogue writes E = exp(S - pmax_slab) fp16
// plus per-slab row (pmax, psum).
// ---------------------------------------------------------------------------
static constexpr int S_STAGE = 2 * (128 + 128) * 128;     // 64 KB
static constexpr int SMEM_S  = 3 * S_STAGE;               // 192 KB

__device__ __forceinline__ void s_load_stage(
    uint32_t base, int tid, int m0, int n0, int k0,
    const __half* Ah, const __half* Al, const __half* Bh, const __half* Bl) {
    #pragma unroll
    for (int it = 0; it < 16; it++) {
        int i = tid + it * 256;
        int c = i & 7, row = i >> 3;
        const __half* src;
        if (row < 128)       src = Ah + (size_t)(m0 + row) * D2 + k0 + c * 8;
        else if (row < 256)  src = Al + (size_t)(m0 + row - 128) * D2 + k0 + c * 8;
        else if (row < 384)  src = Bh + (size_t)(n0 + row - 256) * D2 + k0 + c * 8;
        else                 src = Bl + (size_t)(n0 + row - 384) * D2 + k0 + c * 8;
        uint32_t dst = base + row * 128 + ((c ^ (row & 7)) << 4);
        asm volatile("cp.async.cg.shared.global [%0], [%1], 16;" :: "r"(dst), "l"(src) : "memory");
    }
    asm volatile("cp.async.commit_group;" ::: "memory");
}

__global__ __launch_bounds__(256, 1) void gemm_s_kernel(
    const __half* __restrict__ Ah, const __half* __restrict__ Al,
    const __half* __restrict__ Bh, const __half* __restrict__ Bl,
    __half* __restrict__ E, float* __restrict__ pmax, float* __restrict__ psum) {
    extern __shared__ char smem[];
    const int tid = threadIdx.x, wid = tid >> 5, lane = tid & 31;
    const int m0 = blockIdx.y * 128, n0 = blockIdx.x * 128;
    const int wm0 = (wid & 3) * 32, wn0 = (wid >> 2) * 64;
    uint32_t sb = smem_u32(smem);

    const int a_r = lane & 15, a_k = lane >> 4;
    const int b_r = (lane & 7) + ((lane >> 4) << 3), b_k = (lane >> 3) & 1;

    float acc[2][8][4] = {};
    s_load_stage(sb, tid, m0, n0, 0, Ah, Al, Bh, Bl);
    s_load_stage(sb + S_STAGE, tid, m0, n0, 64, Ah, Al, Bh, Bl);

    for (int c = 0; c < 2; c++) {
        asm volatile("cp.async.wait_group %0;" :: "n"(0) : "memory");
        __syncthreads();
        const uint32_t st = sb + c * S_STAGE;
        #pragma unroll
        for (int ks = 0; ks < 4; ks++) {
            uint32_t afh[2][4], afl[2][4];
            #pragma unroll
            for (int mt = 0; mt < 2; mt++) {
                int r = wm0 + mt * 16 + a_r;
                int kc = ks * 2 + a_k;
                uint32_t col = (uint32_t)((kc ^ (r & 7)) << 4);
                ldsm4(afh[mt], st + r * 128 + col);
                ldsm4(afl[mt], st + (128 + r) * 128 + col);
            }
            uint32_t bfh[8][2], bfl[8][2];
            #pragma unroll
            for (int nt = 0; nt < 8; nt += 2) {
                int r = wn0 + nt * 8 + b_r;
                int kc = ks * 2 + b_k;
                uint32_t col = (uint32_t)((kc ^ (r & 7)) << 4);
                uint32_t t[4];
                ldsm4(t, st + (256 + r) * 128 + col);
                bfh[nt][0] = t[0]; bfh[nt][1] = t[1];
                bfh[nt + 1][0] = t[2]; bfh[nt + 1][1] = t[3];
                ldsm4(t, st + (384 + r) * 128 + col);
                bfl[nt][0] = t[0]; bfl[nt][1] = t[1];
                bfl[nt + 1][0] = t[2]; bfl[nt + 1][1] = t[3];
            }
            #pragma unroll
            for (int mt = 0; mt < 2; mt++)
                #pragma unroll
                for (int nt = 0; nt < 8; nt++) {
                    mma16816(acc[mt][nt], afh[mt], bfh[nt]);
                    mma16816(acc[mt][nt], afh[mt], bfl[nt]);
                    mma16816(acc[mt][nt], afl[mt], bfh[nt]);
                }
        }
        __syncthreads();
    }

    // ---- epilogue: slab row max -> E fp16 -> psum ----
    float* pm = (float*)smem;      // [8][32]
    float* Ms = pm + 256;          // [128]
    float* ps = Ms + 128;          // [8][32]

    #pragma unroll
    for (int mt = 0; mt < 2; mt++)
        #pragma unroll
        for (int half = 0; half < 2; half++) {
            float mx = -1e30f;
            #pragma unroll
            for (int nt = 0; nt < 8; nt++)
                mx = fmaxf(mx, fmaxf(acc[mt][nt][2 * half], acc[mt][nt][2 * half + 1]));
            mx = fmaxf(mx, __shfl_xor_sync(~0u, mx, 1));
            mx = fmaxf(mx, __shfl_xor_sync(~0u, mx, 2));
            if ((lane & 3) == 0)
                pm[wid * 32 + mt * 16 + half * 8 + (lane >> 2)] = mx;
        }
    __syncthreads();
    if (tid < 128) {
        int a = tid >> 5, rlw = tid & 31;
        Ms[tid] = fmaxf(pm[a * 32 + rlw], pm[(a + 4) * 32 + rlw]);
    }
    __syncthreads();

    #pragma unroll
    for (int mt = 0; mt < 2; mt++)
        #pragma unroll
        for (int half = 0; half < 2; half++) {
            int rl = wm0 + mt * 16 + half * 8 + (lane >> 2);
            float M = Ms[rl];
            float sm = 0.0f;
            #pragma unroll
            for (int nt = 0; nt < 8; nt++) {
                float e0 = __expf(acc[mt][nt][2 * half] - M);
                float e1 = __expf(acc[mt][nt][2 * half + 1] - M);
                sm += e0 + e1;
                __half2 h = __floats2half2_rn(e0, e1);
                *(__half2*)&E[(size_t)(m0 + rl) * N2 + n0 + wn0 + nt * 8 + (lane & 3) * 2] = h;
            }
            sm += __shfl_xor_sync(~0u, sm, 1);
            sm += __shfl_xor_sync(~0u, sm, 2);
            if ((lane & 3) == 0)
                ps[wid * 32 + mt * 16 + half * 8 + (lane >> 2)] = sm;
        }
    __syncthreads();
    if (tid < 128) {
        int a = tid >> 5, rlw = tid & 31;
        pmax[(size_t)blockIdx.x * N1 + m0 + tid] = Ms[tid];
        psum[(size_t)blockIdx.x * N1 + m0 + tid] = ps[a * 32 + rlw] + ps[(a + 4) * 32 + rlw];
    }
}

// ---------------------------------------------------------------------------
// f1 = attn @ x2 : NT GEMM. A = E fp16 * exp(pmax_slab - lse) (row scalar).
// BM=64, BN=128. smem: A 2x8KB + B 2x16KB = 48KB
// ---------------------------------------------------------------------------
static constexpr int F1_A_STAGE = 64 * 128;          // 8 KB
static constexpr int F1_B_OFF   = 2 * F1_A_STAGE;    // 16 KB
static constexpr int F1_B_STAGE = 128 * 128;         // 16 KB
static constexpr int F1_SMEM    = F1_B_OFF + 2 * F1_B_STAGE;  // 48 KB

__global__ __launch_bounds__(256, 1) void gemm_f1_kernel(
    const __half* __restrict__ E, const float* __restrict__ pmax,
    const float* __restrict__ lse,
    const __half* __restrict__ Bh, float* __restrict__ C) {
    extern __shared__ char smem[];
    uint32_t sb = smem_u32(smem);
    const int tid = threadIdx.x, wid = tid >> 5, lane = tid & 31;
    const int m0 = blockIdx.y * 64;
    const int wm0 = (wid & 1) * 32, wn0 = (wid >> 1) * 32;
    const int a_r = lane & 15, a_k = lane >> 4;
    const int b_r = (lane & 7) + ((lane >> 4) << 3), b_k = (lane >> 3) & 1;

    float acc[2][4][4] = {};
    uint4 ereg[2];
    float sreg[2];
    const int nCh = N2 >> 6;   // 128

    float tl2[2];
    #pragma unroll
    for (int it = 0; it < 2; it++) tl2[it] = lse[m0 + ((tid + it * 256) >> 3)];

    auto ldgA = [&](int c) {
        int blk = c >> 1;
        #pragma unroll
        for (int it = 0; it < 2; it++) {
            int idx = tid + it * 256;
            int m = idx >> 3, kq = idx & 7;
            ereg[it] = *(const uint4*)(E + (size_t)(m0 + m) * N2 + c * 64 + kq * 8);
            sreg[it] = __expf(pmax[(size_t)blk * N1 + m0 + m] - tl2[it]);
        }
    };
    auto stsA = [&](int buf) {
        uint32_t ab = sb + buf * F1_A_STAGE;
        #pragma unroll
        for (int it = 0; it < 2; it++) {
            int idx = tid + it * 256;
            int m = idx >> 3, kq = idx & 7;
            __half2 s2h = __float2half2_rn(sreg[it]);
            uint32_t s2 = *(uint32_t*)&s2h;
            uint32_t off = m * 128 + ((kq ^ (m & 7)) << 4);
            sts16(ab + off, mulh2(ereg[it].x, s2), mulh2(ereg[it].y, s2),
                  mulh2(ereg[it].z, s2), mulh2(ereg[it].w, s2));
        }
    };
    auto ldB = [&](int c, int buf) {
        uint32_t bb = sb + F1_B_OFF + buf * F1_B_STAGE;
        #pragma unroll
        for (int it = 0; it < 4; it++) {
            int i = tid + it * 256;
            int n = i >> 3, cc = i & 7;
            const __half* src = Bh + (size_t)n * N2 + c * 64 + cc * 8;
            uint32_t dst = bb + n * 128 + ((cc ^ (n & 7)) << 4);
            asm volatile("cp.async.cg.shared.global [%0], [%1], 16;" :: "r"(dst), "l"(src) : "memory");
        }
        asm volatile("cp.async.commit_group;" ::: "memory");
    };

    ldgA(0); stsA(0); ldB(0, 0);

    for (int c = 0; c < nCh; c++) {
        const bool more = (c + 1 < nCh);
        if (more) ldgA(c + 1);
        asm volatile("cp.async.wait_group 0;" ::: "memory");
        __syncthreads();
        if (more) ldB(c + 1, (c + 1) & 1);

        const uint32_t ast = sb + (c & 1) * F1_A_STAGE;
        const uint32_t bst = sb + F1_B_OFF + (c & 1) * F1_B_STAGE;
        #pragma unroll
        for (int ks = 0; ks < 4; ks++) {
            uint32_t afh[2][4];
            #pragma unroll
            for (int mt = 0; mt < 2; mt++) {
                int r = wm0 + mt * 16 + a_r;
                int kc = ks * 2 + a_k;
                uint32_t col = (uint32_t)((kc ^ (r & 7)) << 4);
                ldsm4(afh[mt], ast + r * 128 + col);
            }
            uint32_t bfh[4][2];
            #pragma unroll
            for (int nt = 0; nt < 4; nt += 2) {
                int r = wn0 + nt * 8 + b_r;
                int kc = ks * 2 + b_k;
                uint32_t col = (uint32_t)((kc ^ (r & 7)) << 4);
                uint32_t t[4];
                ldsm4(t, bst + r * 128 + col);
                bfh[nt][0] = t[0]; bfh[nt][1] = t[1];
                bfh[nt + 1][0] = t[2]; bfh[nt + 1][1] = t[3];
            }
            #pragma unroll
            for (int mt = 0; mt < 2; mt++)
                #pragma unroll
                for (int nt = 0; nt < 4; nt++)
                    mma16816(acc[mt][nt], afh[mt], bfh[nt]);
        }
        if (more) stsA((c + 1) & 1);
    }

    #pragma unroll
    for (int mt = 0; mt < 2; mt++) {
        int row = m0 + wm0 + mt * 16 + (lane >> 2);
        #pragma unroll
        for (int nt = 0; nt < 4; nt++) {
            int col = wn0 + nt * 8 + (lane & 3) * 2;
            *(float2*)&C[(size_t)row * D2 + col]       = make_float2(acc[mt][nt][0], acc[mt][nt][1]);
            *(float2*)&C[(size_t)(row + 8) * D2 + col] = make_float2(acc[mt][nt][2], acc[mt][nt][3]);
        }
    }
}

// ---------------------------------------------------------------------------
// f2 = attn^T @ x1 : TN GEMM. A = E fp16 * exp(pmax_slab - lse) (per-k scalar;
// slab fixed per CTA = blockIdx.y). BM=128, BN=128.
// smem: A 2x16KB + B 2x16KB = 64KB
// ---------------------------------------------------------------------------
static constexpr int F2_A_STAGE = 64 * 256;          // 16 KB
static constexpr int F2_B_OFF   = 2 * F2_A_STAGE;    // 32 KB
static constexpr int F2_B_STAGE = 64 * 256;          // 16 KB
static constexpr int F2_SMEM    = F2_B_OFF + 2 * F2_B_STAGE;  // 64 KB

__global__ __launch_bounds__(256, 1) void gemm_f2_kernel(
    const __half* __restrict__ E, const float* __restrict__ pmax,
    const float* __restrict__ lse,
    const __half* __restrict__ Bh, float* __restrict__ C) {
    extern __shared__ char smem[];
    uint32_t sb = smem_u32(smem);
    const int tid = threadIdx.x, wid = tid >> 5, lane = tid & 31;
    const int m0 = blockIdx.y * 128, n0 = blockIdx.x * 128;
    const int blk = blockIdx.y;          // E column slab
    const int wm0 = (wid & 3) * 32, wn0 = (wid >> 2) * 64;
    const int lt = lane >> 3, li = lane & 7;

    float acc[2][8][4] = {};
    uint4 ereg[4];
    float sreg[4];
    const int nCh = N1 >> 6;   // 128

    auto ldgA = [&](int c) {
        #pragma unroll
        for (int it = 0; it < 4; it++) {
            int idx = tid + it * 256;
            int k = idx >> 4, cc = idx & 15;
            ereg[it] = *(const uint4*)(E + (size_t)(c * 64 + k) * N2 + m0 + cc * 8);
            sreg[it] = __expf(pmax[(size_t)blk * N1 + c * 64 + k] - __ldg(lse + c * 64 + k));
        }
    };
    auto stsA = [&](int buf) {
        uint32_t ab = sb + buf * F2_A_STAGE;
        #pragma unroll
        for (int it = 0; it < 4; it++) {
            int idx = tid + it * 256;
            int k = idx >> 4, cc = idx & 15;
            __half2 s2h = __float2half2_rn(sreg[it]);
            uint32_t s2 = *(uint32_t*)&s2h;
            uint32_t off = k * 256 + ((cc ^ (k & 7)) << 4);
            sts16(ab + off, mulh2(ereg[it].x, s2), mulh2(ereg[it].y, s2),
                  mulh2(ereg[it].z, s2), mulh2(ereg[it].w, s2));
        }
    };
    auto ldB = [&](int c, int buf) {
        uint32_t bb = sb + F2_B_OFF + buf * F2_B_STAGE;
        #pragma unroll
        for (int it = 0; it < 4; it++) {
            int i = tid + it * 256;
            int k = i >> 4, cc = i & 15;
            const __half* src = Bh + (size_t)(c * 64 + k) * D1 + n0 + cc * 8;
            uint32_t dst = bb + k * 256 + ((cc ^ (k & 7)) << 4);
            asm volatile("cp.async.cg.shared.global [%0], [%1], 16;" :: "r"(dst), "l"(src) : "memory");
        }
        asm volatile("cp.async.commit_group;" ::: "memory");
    };

    ldgA(0); stsA(0); ldB(0, 0);

    for (int c = 0; c < nCh; c++) {
        const bool more = (c + 1 < nCh);
        if (more) ldgA(c + 1);
        asm volatile("cp.async.wait_group 0;" ::: "memory");
        __syncthreads();
        if (more) ldB(c + 1, (c + 1) & 1);

        const uint32_t ast = sb + (c & 1) * F2_A_STAGE;
        const uint32_t bst = sb + F2_B_OFF + (c & 1) * F2_B_STAGE;
        #pragma unroll
        for (int ks = 0; ks < 4; ks++) {
            uint32_t afh[2][4];
            #pragma unroll
            for (int mt = 0; mt < 2; mt++) {
                int mb = wm0 + mt * 16 + (lt & 1) * 8;
                int k = ks * 16 + (lt >> 1) * 8 + li;
                uint32_t addr = k * 256 + (((mb >> 3) ^ (k & 7)) << 4);
                ldsm4t(afh[mt], ast + addr);
            }
            uint32_t bfh[8][2];
            #pragma unroll
            for (int nt = 0; nt < 8; nt += 2) {
                int nb = wn0 + nt * 8 + (lt >> 1) * 8;
                int k = ks * 16 + (lt & 1) * 8 + li;
                uint32_t addr = k * 256 + (((nb >> 3) ^ (k & 7)) << 4);
                uint32_t t[4];
                ldsm4t(t, bst + addr);
                bfh[nt][0] = t[0]; bfh[nt][1] = t[1];
                bfh[nt + 1][0] = t[2]; bfh[nt + 1][1] = t[3];
            }
            #pragma unroll
            for (int mt = 0; mt < 2; mt++)
                #pragma unroll
                for (int nt = 0; nt < 8; nt++)
                    mma16816(acc[mt][nt], afh[mt], bfh[nt]);
        }
        if (more) stsA((c + 1) & 1);
    }

    #pragma unroll
    for (int mt = 0; mt < 2; mt++) {
        int row = m0 + wm0 + mt * 16 + (lane >> 2);
        #pragma unroll
        for (int nt = 0; nt < 8; nt++) {
            int col = n0 + wn0 + nt * 8 + (lane & 3) * 2;
            *(float2*)&C[(size_t)row * D1 + col]       = make_float2(acc[mt][nt][0], acc[mt][nt][1]);
            *(float2*)&C[(size_t)(row + 8) * D1 + col] = make_float2(acc[mt][nt][2], acc[mt][nt][3]);
        }
    }
}

// ---------------------------------------------------------------------------
// Launch
// ---------------------------------------------------------------------------
extern "C" void kernel_launch(void* const* d_in, const int* in_sizes, int n_in,
                              void* d_out, int out_size) {
    const float* x1 = (const float*)d_in[0];   // [8192, 256]
    const float* x2 = (const float*)d_in[1];   // [8192, 128]
    const float* W1 = (const float*)d_in[2];   // [128, 256]
    const float* b1 = (const float*)d_in[3];   // [128]

    float* out = (float*)d_out;
    float* f1 = out;                          // [8192, 128]
    float* f2 = out + (size_t)N1 * D2;        // [8192, 256]

    float *wtp, *lsep, *pmaxp, *psump;
    __half *ep, *qh, *ql, *x2h, *x2l, *x2t, *x1f;
    cudaGetSymbolAddress((void**)&ep, g_E);
    cudaGetSymbolAddress((void**)&wtp, g_Wt);
    cudaGetSymbolAddress((void**)&lsep, g_lse);
    cudaGetSymbolAddress((void**)&pmaxp, g_pmax);
    cudaGetSymbolAddress((void**)&psump, g_psum);
    cudaGetSymbolAddress((void**)&qh, g_qh);
    cudaGetSymbolAddress((void**)&ql, g_ql);
    cudaGetSymbolAddress((void**)&x2h, g_x2h);
    cudaGetSymbolAddress((void**)&x2l, g_x2l);
    cudaGetSymbolAddress((void**)&x2t, g_x2t);
    cudaGetSymbolAddress((void**)&x1f, g_x1f);

    cudaFuncSetAttribute((const void*)gemm_s_kernel,
                         cudaFuncAttributeMaxDynamicSharedMemorySize, SMEM_S);
    cudaFuncSetAttribute((const void*)gemm_f1_kernel,
                         cudaFuncAttributeMaxDynamicSharedMemorySize, F1_SMEM);
    cudaFuncSetAttribute((const void*)gemm_f2_kernel,
                         cudaFuncAttributeMaxDynamicSharedMemorySize, F2_SMEM);

    // 1) prep
    transpose_w_kernel<<<(D1 * D2 + 255) / 256, 256>>>(W1, wtp);
    q_gemm_kernel<<<N1 / 32, 256>>>(x1, wtp, qh, ql, b1);
    split_kernel<<<(N2 * D2 / 4 + 255) / 256, 256>>>(x2, N2 * D2, x2h, x2l);
    transpose_h_kernel<<<dim3(D2 / 32, N2 / 32), dim3(32, 8)>>>(x2, N2, D2, x2t);
    tofp16_kernel<<<(N1 * D1 / 4 + 255) / 256, 256>>>(x1, N1 * D1, x1f);
    // 2) E = exp(q@x2^T - pmax_slab) fp16 + per-slab row partials
    gemm_s_kernel<<<dim3(NBLK, N1 / 128), 256, SMEM_S>>>(
        qh, ql, x2h, x2l, ep, pmaxp, psump);
    // 3) combine partials -> lse
    lse_combine_kernel<<<N1 / 256, 256>>>(pmaxp, psump, lsep);
    // 4) f1 = attn @ x2
    gemm_f1_kernel<<<dim3(1, N1 / 64), 256, F1_SMEM>>>(ep, pmaxp, lsep, x2t, f1);
    // 5) f2 = attn^T @ x1
    gemm_f2_kernel<<<dim3(D1 / 128, N2 / 128), 256, F2_SMEM>>>(ep, pmaxp, lsep, x1f, f2);
}

// round 9
// speedup vs baseline: 5.5090x; 1.0080x over previous
#include <cuda_runtime.h>
#include <cuda_fp16.h>
#include <cstdint>

#define N1 8192
#define N2 8192
#define D1 256
#define D2 128
#define NBLK (N2 / 128)   // 64 column-slabs of E

// ---------------------------------------------------------------------------
// Scratch (__device__ globals; allocation-free rule)
// ---------------------------------------------------------------------------
__device__ __half g_E[(size_t)N1 * N2];                // 128 MB: exp(S - pmax_slab)
__device__ float g_lse[N1];
__device__ float g_pmax[(size_t)NBLK * N1];
__device__ float g_psum[(size_t)NBLK * N1];
__device__ __half g_qh[N1 * D2], g_ql[N1 * D2];
__device__ __half g_x2h[N2 * D2], g_x2l[N2 * D2];
__device__ __half g_x2t[D2 * N2];
__device__ __half g_x1f[(size_t)N1 * D1];
__device__ float g_Wt[D1 * D2];

// ---------------------------------------------------------------------------
// Helpers
// ---------------------------------------------------------------------------
__device__ __forceinline__ uint32_t smem_u32(const void* p) {
    uint32_t a;
    asm("{ .reg .u64 t; cvta.to.shared.u64 t, %1; cvt.u32.u64 %0, t; }" : "=r"(a) : "l"(p));
    return a;
}
__device__ __forceinline__ void ldsm4(uint32_t r[4], uint32_t addr) {
    asm volatile("ldmatrix.sync.aligned.m8n8.x4.shared.b16 {%0,%1,%2,%3}, [%4];"
                 : "=r"(r[0]), "=r"(r[1]), "=r"(r[2]), "=r"(r[3]) : "r"(addr));
}
__device__ __forceinline__ void ldsm4t(uint32_t r[4], uint32_t addr) {
    asm volatile("ldmatrix.sync.aligned.m8n8.x4.trans.shared.b16 {%0,%1,%2,%3}, [%4];"
                 : "=r"(r[0]), "=r"(r[1]), "=r"(r[2]), "=r"(r[3]) : "r"(addr));
}
__device__ __forceinline__ void mma16816(float c[4], const uint32_t a[4], const uint32_t b[2]) {
    asm volatile("mma.sync.aligned.m16n8k16.row.col.f32.f16.f16.f32 "
                 "{%0,%1,%2,%3}, {%4,%5,%6,%7}, {%8,%9}, {%0,%1,%2,%3};"
                 : "+f"(c[0]), "+f"(c[1]), "+f"(c[2]), "+f"(c[3])
                 : "r"(a[0]), "r"(a[1]), "r"(a[2]), "r"(a[3]), "r"(b[0]), "r"(b[1]));
}
__device__ __forceinline__ void split_h(float v, __half& h, __half& l) {
    h = __float2half(v);
    l = __float2half(v - __half2float(h));
}
__device__ __forceinline__ void sts16(uint32_t addr, uint32_t a, uint32_t b,
                                      uint32_t c, uint32_t d) {
    asm volatile("st.shared.v4.b32 [%0], {%1,%2,%3,%4};"
                 :: "r"(addr), "r"(a), "r"(b), "r"(c), "r"(d) : "memory");
}
__device__ __forceinline__ uint32_t mulh2(uint32_t e, uint32_t s) {
    __half2 r = __hmul2(*(__half2*)&e, *(__half2*)&s);
    return *(uint32_t*)&r;
}

// ---------------------------------------------------------------------------
// Prep kernels
// ---------------------------------------------------------------------------
__global__ void transpose_w_kernel(const float* __restrict__ W1, float* __restrict__ Wt) {
    int idx = blockIdx.x * blockDim.x + threadIdx.x;
    if (idx < D1 * D2) {
        int n = idx / D1, k = idx % D1;
        Wt[k * D2 + n] = W1[idx];
    }
}

__global__ void q_gemm_kernel(const float* __restrict__ A, const float* __restrict__ B,
                              __half* __restrict__ Ch, __half* __restrict__ Cl,
                              const float* __restrict__ bias) {
    __shared__ float As[32][16];
    __shared__ float Bs[16][128];
    const int m0 = blockIdx.x * 32;
    const int tid = threadIdx.x;
    const int ty = tid >> 4, tx = tid & 15;
    float acc0[8] = {}, acc1[8] = {};

    for (int k0 = 0; k0 < D1; k0 += 16) {
        {
            int m = tid >> 3, k2 = (tid & 7) * 2;
            const float* p = A + (size_t)(m0 + m) * D1 + k0 + k2;
            As[m][k2] = p[0]; As[m][k2 + 1] = p[1];
        }
        #pragma unroll
        for (int c = 0; c < 2; c++) {
            int idx = c * 1024 + tid * 4;
            int k = idx >> 7, n = idx & 127;
            *(float4*)&Bs[k][n] = *(const float4*)(B + (size_t)(k0 + k) * 128 + n);
        }
        __syncthreads();
        #pragma unroll
        for (int k = 0; k < 16; k++) {
            float a0 = As[ty * 2][k], a1 = As[ty * 2 + 1][k];
            float4 b0 = *(const float4*)&Bs[k][tx * 8];
            float4 b1 = *(const float4*)&Bs[k][tx * 8 + 4];
            acc0[0] += a0 * b0.x; acc0[1] += a0 * b0.y; acc0[2] += a0 * b0.z; acc0[3] += a0 * b0.w;
            acc0[4] += a0 * b1.x; acc0[5] += a0 * b1.y; acc0[6] += a0 * b1.z; acc0[7] += a0 * b1.w;
            acc1[0] += a1 * b0.x; acc1[1] += a1 * b0.y; acc1[2] += a1 * b0.z; acc1[3] += a1 * b0.w;
            acc1[4] += a1 * b1.x; acc1[5] += a1 * b1.y; acc1[6] += a1 * b1.z; acc1[7] += a1 * b1.w;
        }
        __syncthreads();
    }
    int m = m0 + ty * 2;
    #pragma unroll
    for (int j = 0; j < 8; j++) {
        float bv = bias[tx * 8 + j];
        __half h, l;
        split_h(acc0[j] + bv, h, l);
        Ch[(size_t)m * 128 + tx * 8 + j] = h; Cl[(size_t)m * 128 + tx * 8 + j] = l;
        split_h(acc1[j] + bv, h, l);
        Ch[(size_t)(m + 1) * 128 + tx * 8 + j] = h; Cl[(size_t)(m + 1) * 128 + tx * 8 + j] = l;
    }
}

__global__ void split_kernel(const float* __restrict__ in, int n,
                             __half* __restrict__ oh, __half* __restrict__ ol) {
    int i = blockIdx.x * blockDim.x + threadIdx.x;
    if (i * 4 < n) {
        float4 v = *(const float4*)(in + (size_t)i * 4);
        __half h, l;
        size_t o = (size_t)i * 4;
        split_h(v.x, h, l); oh[o] = h;     ol[o] = l;
        split_h(v.y, h, l); oh[o + 1] = h; ol[o + 1] = l;
        split_h(v.z, h, l); oh[o + 2] = h; ol[o + 2] = l;
        split_h(v.w, h, l); oh[o + 3] = h; ol[o + 3] = l;
    }
}

__global__ void tofp16_kernel(const float* __restrict__ in, int n, __half* __restrict__ o) {
    int i = blockIdx.x * blockDim.x + threadIdx.x;
    if (i * 4 < n) {
        float4 v = *(const float4*)(in + (size_t)i * 4);
        __half2 a = __floats2half2_rn(v.x, v.y);
        __half2 b = __floats2half2_rn(v.z, v.w);
        *(__half2*)(o + (size_t)i * 4)     = a;
        *(__half2*)(o + (size_t)i * 4 + 2) = b;
    }
}

__global__ void transpose_h_kernel(const float* __restrict__ in, int R, int C,
                                   __half* __restrict__ o) {
    __shared__ float t[32][33];
    int c0 = blockIdx.x * 32, r0 = blockIdx.y * 32;
    for (int i = threadIdx.y; i < 32; i += 8)
        t[i][threadIdx.x] = in[(size_t)(r0 + i) * C + c0 + threadIdx.x];
    __syncthreads();
    for (int i = threadIdx.y; i < 32; i += 8)
        o[(size_t)(c0 + i) * R + r0 + threadIdx.x] = __float2half(t[threadIdx.x][i]);
}

// ---------------------------------------------------------------------------
// lse combine
// ---------------------------------------------------------------------------
__global__ void lse_combine_kernel(const float* __restrict__ pmax,
                                   const float* __restrict__ psum,
                                   float* __restrict__ lse) {
    int row = blockIdx.x * 256 + threadIdx.x;
    float M = -1e30f;
    #pragma unroll 8
    for (int nb = 0; nb < NBLK; nb++)
        M = fmaxf(M, pmax[(size_t)nb * N1 + row]);
    float s = 0.0f;
    #pragma unroll 8
    for (int nb = 0; nb < NBLK; nb++)
        s += psum[(size_t)nb * N1 + row] * __expf(pmax[(size_t)nb * N1 + row] - M);
    lse[row] = M + __logf(s);
}

// ---------------------------------------------------------------------------
// S GEMM: split-fp16 3-MMA; epilogue writes E = exp(S - pmax_slab) fp16
// ---------------------------------------------------------------------------
static constexpr int S_STAGE = 2 * (128 + 128) * 128;     // 64 KB
static constexpr int SMEM_S  = 3 * S_STAGE;               // 192 KB

__device__ __forceinline__ void s_load_stage(
    uint32_t base, int tid, int m0, int n0, int k0,
    const __half* Ah, const __half* Al, const __half* Bh, const __half* Bl) {
    #pragma unroll
    for (int it = 0; it < 16; it++) {
        int i = tid + it * 256;
        int c = i & 7, row = i >> 3;
        const __half* src;
        if (row < 128)       src = Ah + (size_t)(m0 + row) * D2 + k0 + c * 8;
        else if (row < 256)  src = Al + (size_t)(m0 + row - 128) * D2 + k0 + c * 8;
        else if (row < 384)  src = Bh + (size_t)(n0 + row - 256) * D2 + k0 + c * 8;
        else                 src = Bl + (size_t)(n0 + row - 384) * D2 + k0 + c * 8;
        uint32_t dst = base + row * 128 + ((c ^ (row & 7)) << 4);
        asm volatile("cp.async.cg.shared.global [%0], [%1], 16;" :: "r"(dst), "l"(src) : "memory");
    }
    asm volatile("cp.async.commit_group;" ::: "memory");
}

__global__ __launch_bounds__(256, 1) void gemm_s_kernel(
    const __half* __restrict__ Ah, const __half* __restrict__ Al,
    const __half* __restrict__ Bh, const __half* __restrict__ Bl,
    __half* __restrict__ E, float* __restrict__ pmax, float* __restrict__ psum) {
    extern __shared__ char smem[];
    const int tid = threadIdx.x, wid = tid >> 5, lane = tid & 31;
    const int m0 = blockIdx.y * 128, n0 = blockIdx.x * 128;
    const int wm0 = (wid & 3) * 32, wn0 = (wid >> 2) * 64;
    uint32_t sb = smem_u32(smem);

    const int a_r = lane & 15, a_k = lane >> 4;
    const int b_r = (lane & 7) + ((lane >> 4) << 3), b_k = (lane >> 3) & 1;

    float acc[2][8][4] = {};
    s_load_stage(sb, tid, m0, n0, 0, Ah, Al, Bh, Bl);
    s_load_stage(sb + S_STAGE, tid, m0, n0, 64, Ah, Al, Bh, Bl);

    for (int c = 0; c < 2; c++) {
        asm volatile("cp.async.wait_group %0;" :: "n"(0) : "memory");
        __syncthreads();
        const uint32_t st = sb + c * S_STAGE;
        #pragma unroll
        for (int ks = 0; ks < 4; ks++) {
            uint32_t afh[2][4], afl[2][4];
            #pragma unroll
            for (int mt = 0; mt < 2; mt++) {
                int r = wm0 + mt * 16 + a_r;
                int kc = ks * 2 + a_k;
                uint32_t col = (uint32_t)((kc ^ (r & 7)) << 4);
                ldsm4(afh[mt], st + r * 128 + col);
                ldsm4(afl[mt], st + (128 + r) * 128 + col);
            }
            uint32_t bfh[8][2], bfl[8][2];
            #pragma unroll
            for (int nt = 0; nt < 8; nt += 2) {
                int r = wn0 + nt * 8 + b_r;
                int kc = ks * 2 + b_k;
                uint32_t col = (uint32_t)((kc ^ (r & 7)) << 4);
                uint32_t t[4];
                ldsm4(t, st + (256 + r) * 128 + col);
                bfh[nt][0] = t[0]; bfh[nt][1] = t[1];
                bfh[nt + 1][0] = t[2]; bfh[nt + 1][1] = t[3];
                ldsm4(t, st + (384 + r) * 128 + col);
                bfl[nt][0] = t[0]; bfl[nt][1] = t[1];
                bfl[nt + 1][0] = t[2]; bfl[nt + 1][1] = t[3];
            }
            #pragma unroll
            for (int mt = 0; mt < 2; mt++)
                #pragma unroll
                for (int nt = 0; nt < 8; nt++) {
                    mma16816(acc[mt][nt], afh[mt], bfh[nt]);
                    mma16816(acc[mt][nt], afh[mt], bfl[nt]);
                    mma16816(acc[mt][nt], afl[mt], bfh[nt]);
                }
        }
        __syncthreads();
    }

    // ---- epilogue: slab row max -> E fp16 -> psum ----
    float* pm = (float*)smem;      // [8][32]
    float* Ms = pm + 256;          // [128]
    float* ps = Ms + 128;          // [8][32]

    #pragma unroll
    for (int mt = 0; mt < 2; mt++)
        #pragma unroll
        for (int half = 0; half < 2; half++) {
            float mx = -1e30f;
            #pragma unroll
            for (int nt = 0; nt < 8; nt++)
                mx = fmaxf(mx, fmaxf(acc[mt][nt][2 * half], acc[mt][nt][2 * half + 1]));
            mx = fmaxf(mx, __shfl_xor_sync(~0u, mx, 1));
            mx = fmaxf(mx, __shfl_xor_sync(~0u, mx, 2));
            if ((lane & 3) == 0)
                pm[wid * 32 + mt * 16 + half * 8 + (lane >> 2)] = mx;
        }
    __syncthreads();
    if (tid < 128) {
        int a = tid >> 5, rlw = tid & 31;
        Ms[tid] = fmaxf(pm[a * 32 + rlw], pm[(a + 4) * 32 + rlw]);
    }
    __syncthreads();

    #pragma unroll
    for (int mt = 0; mt < 2; mt++)
        #pragma unroll
        for (int half = 0; half < 2; half++) {
            int rl = wm0 + mt * 16 + half * 8 + (lane >> 2);
            float M = Ms[rl];
            float sm = 0.0f;
            #pragma unroll
            for (int nt = 0; nt < 8; nt++) {
                float e0 = __expf(acc[mt][nt][2 * half] - M);
                float e1 = __expf(acc[mt][nt][2 * half + 1] - M);
                sm += e0 + e1;
                __half2 h = __floats2half2_rn(e0, e1);
                *(__half2*)&E[(size_t)(m0 + rl) * N2 + n0 + wn0 + nt * 8 + (lane & 3) * 2] = h;
            }
            sm += __shfl_xor_sync(~0u, sm, 1);
            sm += __shfl_xor_sync(~0u, sm, 2);
            if ((lane & 3) == 0)
                ps[wid * 32 + mt * 16 + half * 8 + (lane >> 2)] = sm;
        }
    __syncthreads();
    if (tid < 128) {
        int a = tid >> 5, rlw = tid & 31;
        pmax[(size_t)blockIdx.x * N1 + m0 + tid] = Ms[tid];
        psum[(size_t)blockIdx.x * N1 + m0 + tid] = ps[a * 32 + rlw] + ps[(a + 4) * 32 + rlw];
    }
}

// ---------------------------------------------------------------------------
// Fused consumer: one launch covering f2 (blocks 0..127) and f1 (128..255).
// 3-stage cp.async B pipeline (wait_group 1), double-buffered fused-exp A.
// smem: A 2x16KB @0, B 3x16KB @32KB = 80KB.
// ---------------------------------------------------------------------------
static constexpr int FB_OFF   = 32 * 1024;
static constexpr int FB_STAGE = 16 * 1024;
static constexpr int FUSED_SMEM = FB_OFF + 3 * FB_STAGE;   // 80 KB

__global__ __launch_bounds__(256, 1) void gemm_fused_kernel(
    const __half* __restrict__ E, const float* __restrict__ pmax,
    const float* __restrict__ lse,
    const __half* __restrict__ X2t, const __half* __restrict__ X1f,
    float* __restrict__ F1, float* __restrict__ F2) {
    extern __shared__ char smem[];
    uint32_t sb = smem_u32(smem);
    const int tid = threadIdx.x, wid = tid >> 5, lane = tid & 31;

    if (blockIdx.x < 128) {
        // ================= f2 tile: C[m0:+128][n0:+128] of attn^T @ x1 =====
        const int bid = blockIdx.x;
        const int m0 = (bid >> 1) * 128, n0 = (bid & 1) * 128;
        const int blk = bid >> 1;
        const int wm0 = (wid & 3) * 32, wn0 = (wid >> 2) * 64;
        const int lt = lane >> 3, li = lane & 7;
        constexpr int A_ST = 64 * 256;   // 16 KB

        float acc[2][8][4] = {};
        uint4 ereg[4];
        float sreg[4];
        const int nCh = N1 >> 6;   // 128

        auto ldgA = [&](int c) {
            #pragma unroll
            for (int it = 0; it < 4; it++) {
                int idx = tid + it * 256;
                int k = idx >> 4, cc = idx & 15;
                ereg[it] = *(const uint4*)(E + (size_t)(c * 64 + k) * N2 + m0 + cc * 8);
                sreg[it] = __expf(pmax[(size_t)blk * N1 + c * 64 + k] - __ldg(lse + c * 64 + k));
            }
        };
        auto stsA = [&](int buf) {
            uint32_t ab = sb + buf * A_ST;
            #pragma unroll
            for (int it = 0; it < 4; it++) {
                int idx = tid + it * 256;
                int k = idx >> 4, cc = idx & 15;
                __half2 s2h = __float2half2_rn(sreg[it]);
                uint32_t s2 = *(uint32_t*)&s2h;
                uint32_t off = k * 256 + ((cc ^ (k & 7)) << 4);
                sts16(ab + off, mulh2(ereg[it].x, s2), mulh2(ereg[it].y, s2),
                      mulh2(ereg[it].z, s2), mulh2(ereg[it].w, s2));
            }
        };
        auto ldB = [&](int c, int buf) {
            uint32_t bb = sb + FB_OFF + buf * FB_STAGE;
            #pragma unroll
            for (int it = 0; it < 4; it++) {
                int i = tid + it * 256;
                int k = i >> 4, cc = i & 15;
                const __half* src = X1f + (size_t)(c * 64 + k) * D1 + n0 + cc * 8;
                uint32_t dst = bb + k * 256 + ((cc ^ (k & 7)) << 4);
                asm volatile("cp.async.cg.shared.global [%0], [%1], 16;" :: "r"(dst), "l"(src) : "memory");
            }
            asm volatile("cp.async.commit_group;" ::: "memory");
        };

        ldgA(0); stsA(0);
        ldB(0, 0); ldB(1, 1);

        for (int c = 0; c < nCh; c++) {
            const bool more = (c + 1 < nCh);
            if (more) ldgA(c + 1);
            asm volatile("cp.async.wait_group 1;" ::: "memory");
            __syncthreads();
            if (c + 2 < nCh) ldB(c + 2, (c + 2) % 3);
            else asm volatile("cp.async.commit_group;" ::: "memory");

            const uint32_t ast = sb + (c & 1) * A_ST;
            const uint32_t bst = sb + FB_OFF + (c % 3) * FB_STAGE;
            #pragma unroll
            for (int ks = 0; ks < 4; ks++) {
                uint32_t afh[2][4];
                #pragma unroll
                for (int mt = 0; mt < 2; mt++) {
                    int mb = wm0 + mt * 16 + (lt & 1) * 8;
                    int k = ks * 16 + (lt >> 1) * 8 + li;
                    uint32_t addr = k * 256 + (((mb >> 3) ^ (k & 7)) << 4);
                    ldsm4t(afh[mt], ast + addr);
                }
                uint32_t bfh[8][2];
                #pragma unroll
                for (int nt = 0; nt < 8; nt += 2) {
                    int nb = wn0 + nt * 8 + (lt >> 1) * 8;
                    int k = ks * 16 + (lt & 1) * 8 + li;
                    uint32_t addr = k * 256 + (((nb >> 3) ^ (k & 7)) << 4);
                    uint32_t t[4];
                    ldsm4t(t, bst + addr);
                    bfh[nt][0] = t[0]; bfh[nt][1] = t[1];
                    bfh[nt + 1][0] = t[2]; bfh[nt + 1][1] = t[3];
                }
                #pragma unroll
                for (int mt = 0; mt < 2; mt++)
                    #pragma unroll
                    for (int nt = 0; nt < 8; nt++)
                        mma16816(acc[mt][nt], afh[mt], bfh[nt]);
            }
            if (more) stsA((c + 1) & 1);
        }

        #pragma unroll
        for (int mt = 0; mt < 2; mt++) {
            int row = m0 + wm0 + mt * 16 + (lane >> 2);
            #pragma unroll
            for (int nt = 0; nt < 8; nt++) {
                int col = n0 + wn0 + nt * 8 + (lane & 3) * 2;
                *(float2*)&F2[(size_t)row * D1 + col]       = make_float2(acc[mt][nt][0], acc[mt][nt][1]);
                *(float2*)&F2[(size_t)(row + 8) * D1 + col] = make_float2(acc[mt][nt][2], acc[mt][nt][3]);
            }
        }
    } else {
        // ================= f1 tile: C[m0:+64][0:128] of attn @ x2 ==========
        const int m0 = (blockIdx.x - 128) * 64;
        const int wm0 = (wid & 1) * 32, wn0 = (wid >> 1) * 32;
        const int a_r = lane & 15, a_k = lane >> 4;
        const int b_r = (lane & 7) + ((lane >> 4) << 3), b_k = (lane >> 3) & 1;
        constexpr int A_ST = 64 * 128;   // 8 KB

        float acc[2][4][4] = {};
        uint4 ereg[2];
        float sreg[2];
        const int nCh = N2 >> 6;   // 128

        float tl2[2];
        #pragma unroll
        for (int it = 0; it < 2; it++) tl2[it] = lse[m0 + ((tid + it * 256) >> 3)];

        auto ldgA = [&](int c) {
            int blk = c >> 1;
            #pragma unroll
            for (int it = 0; it < 2; it++) {
                int idx = tid + it * 256;
                int m = idx >> 3, kq = idx & 7;
                ereg[it] = *(const uint4*)(E + (size_t)(m0 + m) * N2 + c * 64 + kq * 8);
                sreg[it] = __expf(pmax[(size_t)blk * N1 + m0 + m] - tl2[it]);
            }
        };
        auto stsA = [&](int buf) {
            uint32_t ab = sb + buf * A_ST;
            #pragma unroll
            for (int it = 0; it < 2; it++) {
                int idx = tid + it * 256;
                int m = idx >> 3, kq = idx & 7;
                __half2 s2h = __float2half2_rn(sreg[it]);
                uint32_t s2 = *(uint32_t*)&s2h;
                uint32_t off = m * 128 + ((kq ^ (m & 7)) << 4);
                sts16(ab + off, mulh2(ereg[it].x, s2), mulh2(ereg[it].y, s2),
                      mulh2(ereg[it].z, s2), mulh2(ereg[it].w, s2));
            }
        };
        auto ldB = [&](int c, int buf) {
            uint32_t bb = sb + FB_OFF + buf * FB_STAGE;
            #pragma unroll
            for (int it = 0; it < 4; it++) {
                int i = tid + it * 256;
                int n = i >> 3, cc = i & 7;
                const __half* src = X2t + (size_t)n * N2 + c * 64 + cc * 8;
                uint32_t dst = bb + n * 128 + ((cc ^ (n & 7)) << 4);
                asm volatile("cp.async.cg.shared.global [%0], [%1], 16;" :: "r"(dst), "l"(src) : "memory");
            }
            asm volatile("cp.async.commit_group;" ::: "memory");
        };

        ldgA(0); stsA(0);
        ldB(0, 0); ldB(1, 1);

        for (int c = 0; c < nCh; c++) {
            const bool more = (c + 1 < nCh);
            if (more) ldgA(c + 1);
            asm volatile("cp.async.wait_group 1;" ::: "memory");
            __syncthreads();
            if (c + 2 < nCh) ldB(c + 2, (c + 2) % 3);
            else asm volatile("cp.async.commit_group;" ::: "memory");

            const uint32_t ast = sb + (c & 1) * A_ST;
            const uint32_t bst = sb + FB_OFF + (c % 3) * FB_STAGE;
            #pragma unroll
            for (int ks = 0; ks < 4; ks++) {
                uint32_t afh[2][4];
                #pragma unroll
                for (int mt = 0; mt < 2; mt++) {
                    int r = wm0 + mt * 16 + a_r;
                    int kc = ks * 2 + a_k;
                    uint32_t col = (uint32_t)((kc ^ (r & 7)) << 4);
                    ldsm4(afh[mt], ast + r * 128 + col);
                }
                uint32_t bfh[4][2];
                #pragma unroll
                for (int nt = 0; nt < 4; nt += 2) {
                    int r = wn0 + nt * 8 + b_r;
                    int kc = ks * 2 + b_k;
                    uint32_t col = (uint32_t)((kc ^ (r & 7)) << 4);
                    uint32_t t[4];
                    ldsm4(t, bst + r * 128 + col);
                    bfh[nt][0] = t[0]; bfh[nt][1] = t[1];
                    bfh[nt + 1][0] = t[2]; bfh[nt + 1][1] = t[3];
                }
                #pragma unroll
                for (int mt = 0; mt < 2; mt++)
                    #pragma unroll
                    for (int nt = 0; nt < 4; nt++)
                        mma16816(acc[mt][nt], afh[mt], bfh[nt]);
            }
            if (more) stsA((c + 1) & 1);
        }

        #pragma unroll
        for (int mt = 0; mt < 2; mt++) {
            int row = m0 + wm0 + mt * 16 + (lane >> 2);
            #pragma unroll
            for (int nt = 0; nt < 4; nt++) {
                int col = wn0 + nt * 8 + (lane & 3) * 2;
                *(float2*)&F1[(size_t)row * D2 + col]       = make_float2(acc[mt][nt][0], acc[mt][nt][1]);
                *(float2*)&F1[(size_t)(row + 8) * D2 + col] = make_float2(acc[mt][nt][2], acc[mt][nt][3]);
            }
        }
    }
}

// ---------------------------------------------------------------------------
// Launch
// ---------------------------------------------------------------------------
extern "C" void kernel_launch(void* const* d_in, const int* in_sizes, int n_in,
                              void* d_out, int out_size) {
    const float* x1 = (const float*)d_in[0];   // [8192, 256]
    const float* x2 = (const float*)d_in[1];   // [8192, 128]
    const float* W1 = (const float*)d_in[2];   // [128, 256]
    const float* b1 = (const float*)d_in[3];   // [128]

    float* out = (float*)d_out;
    float* f1 = out;                          // [8192, 128]
    float* f2 = out + (size_t)N1 * D2;        // [8192, 256]

    float *wtp, *lsep, *pmaxp, *psump;
    __half *ep, *qh, *ql, *x2h, *x2l, *x2t, *x1f;
    cudaGetSymbolAddress((void**)&ep, g_E);
    cudaGetSymbolAddress((void**)&wtp, g_Wt);
    cudaGetSymbolAddress((void**)&lsep, g_lse);
    cudaGetSymbolAddress((void**)&pmaxp, g_pmax);
    cudaGetSymbolAddress((void**)&psump, g_psum);
    cudaGetSymbolAddress((void**)&qh, g_qh);
    cudaGetSymbolAddress((void**)&ql, g_ql);
    cudaGetSymbolAddress((void**)&x2h, g_x2h);
    cudaGetSymbolAddress((void**)&x2l, g_x2l);
    cudaGetSymbolAddress((void**)&x2t, g_x2t);
    cudaGetSymbolAddress((void**)&x1f, g_x1f);

    cudaFuncSetAttribute((const void*)gemm_s_kernel,
                         cudaFuncAttributeMaxDynamicSharedMemorySize, SMEM_S);
    cudaFuncSetAttribute((const void*)gemm_fused_kernel,
                         cudaFuncAttributeMaxDynamicSharedMemorySize, FUSED_SMEM);

    // 1) prep
    transpose_w_kernel<<<(D1 * D2 + 255) / 256, 256>>>(W1, wtp);
    q_gemm_kernel<<<N1 / 32, 256>>>(x1, wtp, qh, ql, b1);
    split_kernel<<<(N2 * D2 / 4 + 255) / 256, 256>>>(x2, N2 * D2, x2h, x2l);
    transpose_h_kernel<<<dim3(D2 / 32, N2 / 32), dim3(32, 8)>>>(x2, N2, D2, x2t);
    tofp16_kernel<<<(N1 * D1 / 4 + 255) / 256, 256>>>(x1, N1 * D1, x1f);
    // 2) E = exp(q@x2^T - pmax_slab) fp16 + per-slab row partials
    gemm_s_kernel<<<dim3(NBLK, N1 / 128), 256, SMEM_S>>>(
        qh, ql, x2h, x2l, ep, pmaxp, psump);
    // 3) combine partials -> lse
    lse_combine_kernel<<<N1 / 256, 256>>>(pmaxp, psump, lsep);
    // 4) f1 + f2 in one launch (f2 tiles first: blocks 0..127)
    gemm_fused_kernel<<<256, 256, FUSED_SMEM>>>(ep, pmaxp, lsep, x2t, x1f, f1, f2);
}

// round 12
// speedup vs baseline: 6.2571x; 1.1358x over previous
#include <cuda_runtime.h>
#include <cuda_fp16.h>
#include <cstdint>

#define N1 8192
#define N2 8192
#define D1 256
#define D2 128
#define NBLK (N2 / 128)   // 64 column-slabs of E

// ---------------------------------------------------------------------------
// Scratch (__device__ globals; allocation-free rule)
// ---------------------------------------------------------------------------
__device__ __half g_E[(size_t)N1 * N2];                // 128 MB: exp(S - pmax_slab)
__device__ float g_lse[N1];
__device__ float g_pmax[(size_t)NBLK * N1];
__device__ float g_psum[(size_t)NBLK * N1];
__device__ __half g_qh[N1 * D2], g_ql[N1 * D2];
__device__ __half g_x2h[N2 * D2], g_x2l[N2 * D2];
__device__ __half g_x2t[D2 * N2];
__device__ __half g_x1f[(size_t)N1 * D1];
__device__ float g_Wt[D1 * D2];

// ---------------------------------------------------------------------------
// Helpers
// ---------------------------------------------------------------------------
__device__ __forceinline__ uint32_t smem_u32(const void* p) {
    uint32_t a;
    asm("{ .reg .u64 t; cvta.to.shared.u64 t, %1; cvt.u32.u64 %0, t; }" : "=r"(a) : "l"(p));
    return a;
}
__device__ __forceinline__ void ldsm4(uint32_t r[4], uint32_t addr) {
    asm volatile("ldmatrix.sync.aligned.m8n8.x4.shared.b16 {%0,%1,%2,%3}, [%4];"
                 : "=r"(r[0]), "=r"(r[1]), "=r"(r[2]), "=r"(r[3]) : "r"(addr));
}
__device__ __forceinline__ void ldsm4t(uint32_t r[4], uint32_t addr) {
    asm volatile("ldmatrix.sync.aligned.m8n8.x4.trans.shared.b16 {%0,%1,%2,%3}, [%4];"
                 : "=r"(r[0]), "=r"(r[1]), "=r"(r[2]), "=r"(r[3]) : "r"(addr));
}
__device__ __forceinline__ void mma16816(float c[4], const uint32_t a[4], const uint32_t b[2]) {
    asm volatile("mma.sync.aligned.m16n8k16.row.col.f32.f16.f16.f32 "
                 "{%0,%1,%2,%3}, {%4,%5,%6,%7}, {%8,%9}, {%0,%1,%2,%3};"
                 : "+f"(c[0]), "+f"(c[1]), "+f"(c[2]), "+f"(c[3])
                 : "r"(a[0]), "r"(a[1]), "r"(a[2]), "r"(a[3]), "r"(b[0]), "r"(b[1]));
}
__device__ __forceinline__ void split_h(float v, __half& h, __half& l) {
    h = __float2half(v);
    l = __float2half(v - __half2float(h));
}
__device__ __forceinline__ void sts16(uint32_t addr, uint32_t a, uint32_t b,
                                      uint32_t c, uint32_t d) {
    asm volatile("st.shared.v4.b32 [%0], {%1,%2,%3,%4};"
                 :: "r"(addr), "r"(a), "r"(b), "r"(c), "r"(d) : "memory");
}
__device__ __forceinline__ uint32_t mulh2(uint32_t e, uint32_t s) {
    __half2 r = __hmul2(*(__half2*)&e, *(__half2*)&s);
    return *(uint32_t*)&r;
}

// ---------------------------------------------------------------------------
// Prep kernels
// ---------------------------------------------------------------------------
__global__ void transpose_w_kernel(const float* __restrict__ W1, float* __restrict__ Wt) {
    int idx = blockIdx.x * blockDim.x + threadIdx.x;
    if (idx < D1 * D2) {
        int n = idx / D1, k = idx % D1;
        Wt[k * D2 + n] = W1[idx];
    }
}

__global__ void q_gemm_kernel(const float* __restrict__ A, const float* __restrict__ B,
                              __half* __restrict__ Ch, __half* __restrict__ Cl,
                              const float* __restrict__ bias) {
    __shared__ float As[32][16];
    __shared__ float Bs[16][128];
    const int m0 = blockIdx.x * 32;
    const int tid = threadIdx.x;
    const int ty = tid >> 4, tx = tid & 15;
    float acc0[8] = {}, acc1[8] = {};

    for (int k0 = 0; k0 < D1; k0 += 16) {
        {
            int m = tid >> 3, k2 = (tid & 7) * 2;
            const float* p = A + (size_t)(m0 + m) * D1 + k0 + k2;
            As[m][k2] = p[0]; As[m][k2 + 1] = p[1];
        }
        #pragma unroll
        for (int c = 0; c < 2; c++) {
            int idx = c * 1024 + tid * 4;
            int k = idx >> 7, n = idx & 127;
            *(float4*)&Bs[k][n] = *(const float4*)(B + (size_t)(k0 + k) * 128 + n);
        }
        __syncthreads();
        #pragma unroll
        for (int k = 0; k < 16; k++) {
            float a0 = As[ty * 2][k], a1 = As[ty * 2 + 1][k];
            float4 b0 = *(const float4*)&Bs[k][tx * 8];
            float4 b1 = *(const float4*)&Bs[k][tx * 8 + 4];
            acc0[0] += a0 * b0.x; acc0[1] += a0 * b0.y; acc0[2] += a0 * b0.z; acc0[3] += a0 * b0.w;
            acc0[4] += a0 * b1.x; acc0[5] += a0 * b1.y; acc0[6] += a0 * b1.z; acc0[7] += a0 * b1.w;
            acc1[0] += a1 * b0.x; acc1[1] += a1 * b0.y; acc1[2] += a1 * b0.z; acc1[3] += a1 * b0.w;
            acc1[4] += a1 * b1.x; acc1[5] += a1 * b1.y; acc1[6] += a1 * b1.z; acc1[7] += a1 * b1.w;
        }
        __syncthreads();
    }
    int m = m0 + ty * 2;
    #pragma unroll
    for (int j = 0; j < 8; j++) {
        float bv = bias[tx * 8 + j];
        __half h, l;
        split_h(acc0[j] + bv, h, l);
        Ch[(size_t)m * 128 + tx * 8 + j] = h; Cl[(size_t)m * 128 + tx * 8 + j] = l;
        split_h(acc1[j] + bv, h, l);
        Ch[(size_t)(m + 1) * 128 + tx * 8 + j] = h; Cl[(size_t)(m + 1) * 128 + tx * 8 + j] = l;
    }
}

__global__ void split_kernel(const float* __restrict__ in, int n,
                             __half* __restrict__ oh, __half* __restrict__ ol) {
    int i = blockIdx.x * blockDim.x + threadIdx.x;
    if (i * 4 < n) {
        float4 v = *(const float4*)(in + (size_t)i * 4);
        __half h, l;
        size_t o = (size_t)i * 4;
        split_h(v.x, h, l); oh[o] = h;     ol[o] = l;
        split_h(v.y, h, l); oh[o + 1] = h; ol[o + 1] = l;
        split_h(v.z, h, l); oh[o + 2] = h; ol[o + 2] = l;
        split_h(v.w, h, l); oh[o + 3] = h; ol[o + 3] = l;
    }
}

__global__ void tofp16_kernel(const float* __restrict__ in, int n, __half* __restrict__ o) {
    int i = blockIdx.x * blockDim.x + threadIdx.x;
    if (i * 4 < n) {
        float4 v = *(const float4*)(in + (size_t)i * 4);
        __half2 a = __floats2half2_rn(v.x, v.y);
        __half2 b = __floats2half2_rn(v.z, v.w);
        *(__half2*)(o + (size_t)i * 4)     = a;
        *(__half2*)(o + (size_t)i * 4 + 2) = b;
    }
}

__global__ void transpose_h_kernel(const float* __restrict__ in, int R, int C,
                                   __half* __restrict__ o) {
    __shared__ float t[32][33];
    int c0 = blockIdx.x * 32, r0 = blockIdx.y * 32;
    for (int i = threadIdx.y; i < 32; i += 8)
        t[i][threadIdx.x] = in[(size_t)(r0 + i) * C + c0 + threadIdx.x];
    __syncthreads();
    for (int i = threadIdx.y; i < 32; i += 8)
        o[(size_t)(c0 + i) * R + r0 + threadIdx.x] = __float2half(t[threadIdx.x][i]);
}

// ---------------------------------------------------------------------------
// lse combine
// ---------------------------------------------------------------------------
__global__ void lse_combine_kernel(const float* __restrict__ pmax,
                                   const float* __restrict__ psum,
                                   float* __restrict__ lse) {
    int row = blockIdx.x * 256 + threadIdx.x;
    float M = -1e30f;
    #pragma unroll 8
    for (int nb = 0; nb < NBLK; nb++)
        M = fmaxf(M, pmax[(size_t)nb * N1 + row]);
    float s = 0.0f;
    #pragma unroll 8
    for (int nb = 0; nb < NBLK; nb++)
        s += psum[(size_t)nb * N1 + row] * __expf(pmax[(size_t)nb * N1 + row] - M);
    lse[row] = M + __logf(s);
}

// ---------------------------------------------------------------------------
// S GEMM: split-fp16 3-MMA; epilogue writes E = exp(S - pmax_slab) fp16
// ---------------------------------------------------------------------------
static constexpr int S_STAGE = 2 * (128 + 128) * 128;     // 64 KB
static constexpr int SMEM_S  = 3 * S_STAGE;               // 192 KB

__device__ __forceinline__ void s_load_stage(
    uint32_t base, int tid, int m0, int n0, int k0,
    const __half* Ah, const __half* Al, const __half* Bh, const __half* Bl) {
    #pragma unroll
    for (int it = 0; it < 16; it++) {
        int i = tid + it * 256;
        int c = i & 7, row = i >> 3;
        const __half* src;
        if (row < 128)       src = Ah + (size_t)(m0 + row) * D2 + k0 + c * 8;
        else if (row < 256)  src = Al + (size_t)(m0 + row - 128) * D2 + k0 + c * 8;
        else if (row < 384)  src = Bh + (size_t)(n0 + row - 256) * D2 + k0 + c * 8;
        else                 src = Bl + (size_t)(n0 + row - 384) * D2 + k0 + c * 8;
        uint32_t dst = base + row * 128 + ((c ^ (row & 7)) << 4);
        asm volatile("cp.async.cg.shared.global [%0], [%1], 16;" :: "r"(dst), "l"(src) : "memory");
    }
    asm volatile("cp.async.commit_group;" ::: "memory");
}

__global__ __launch_bounds__(256, 1) void gemm_s_kernel(
    const __half* __restrict__ Ah, const __half* __restrict__ Al,
    const __half* __restrict__ Bh, const __half* __restrict__ Bl,
    __half* __restrict__ E, float* __restrict__ pmax, float* __restrict__ psum) {
    extern __shared__ char smem[];
    const int tid = threadIdx.x, wid = tid >> 5, lane = tid & 31;
    const int m0 = blockIdx.y * 128, n0 = blockIdx.x * 128;
    const int wm0 = (wid & 3) * 32, wn0 = (wid >> 2) * 64;
    uint32_t sb = smem_u32(smem);

    const int a_r = lane & 15, a_k = lane >> 4;
    const int b_r = (lane & 7) + ((lane >> 4) << 3), b_k = (lane >> 3) & 1;

    float acc[2][8][4] = {};
    s_load_stage(sb, tid, m0, n0, 0, Ah, Al, Bh, Bl);
    s_load_stage(sb + S_STAGE, tid, m0, n0, 64, Ah, Al, Bh, Bl);

    for (int c = 0; c < 2; c++) {
        asm volatile("cp.async.wait_group %0;" :: "n"(0) : "memory");
        __syncthreads();
        const uint32_t st = sb + c * S_STAGE;
        #pragma unroll
        for (int ks = 0; ks < 4; ks++) {
            uint32_t afh[2][4], afl[2][4];
            #pragma unroll
            for (int mt = 0; mt < 2; mt++) {
                int r = wm0 + mt * 16 + a_r;
                int kc = ks * 2 + a_k;
                uint32_t col = (uint32_t)((kc ^ (r & 7)) << 4);
                ldsm4(afh[mt], st + r * 128 + col);
                ldsm4(afl[mt], st + (128 + r) * 128 + col);
            }
            uint32_t bfh[8][2], bfl[8][2];
            #pragma unroll
            for (int nt = 0; nt < 8; nt += 2) {
                int r = wn0 + nt * 8 + b_r;
                int kc = ks * 2 + b_k;
                uint32_t col = (uint32_t)((kc ^ (r & 7)) << 4);
                uint32_t t[4];
                ldsm4(t, st + (256 + r) * 128 + col);
                bfh[nt][0] = t[0]; bfh[nt][1] = t[1];
                bfh[nt + 1][0] = t[2]; bfh[nt + 1][1] = t[3];
                ldsm4(t, st + (384 + r) * 128 + col);
                bfl[nt][0] = t[0]; bfl[nt][1] = t[1];
                bfl[nt + 1][0] = t[2]; bfl[nt + 1][1] = t[3];
            }
            #pragma unroll
            for (int mt = 0; mt < 2; mt++)
                #pragma unroll
                for (int nt = 0; nt < 8; nt++) {
                    mma16816(acc[mt][nt], afh[mt], bfh[nt]);
                    mma16816(acc[mt][nt], afh[mt], bfl[nt]);
                    mma16816(acc[mt][nt], afl[mt], bfh[nt]);
                }
        }
        __syncthreads();
    }

    // ---- epilogue: slab row max -> E fp16 -> psum ----
    float* pm = (float*)smem;      // [8][32]
    float* Ms = pm + 256;          // [128]
    float* ps = Ms + 128;          // [8][32]

    #pragma unroll
    for (int mt = 0; mt < 2; mt++)
        #pragma unroll
        for (int half = 0; half < 2; half++) {
            float mx = -1e30f;
            #pragma unroll
            for (int nt = 0; nt < 8; nt++)
                mx = fmaxf(mx, fmaxf(acc[mt][nt][2 * half], acc[mt][nt][2 * half + 1]));
            mx = fmaxf(mx, __shfl_xor_sync(~0u, mx, 1));
            mx = fmaxf(mx, __shfl_xor_sync(~0u, mx, 2));
            if ((lane & 3) == 0)
                pm[wid * 32 + mt * 16 + half * 8 + (lane >> 2)] = mx;
        }
    __syncthreads();
    if (tid < 128) {
        int a = tid >> 5, rlw = tid & 31;
        Ms[tid] = fmaxf(pm[a * 32 + rlw], pm[(a + 4) * 32 + rlw]);
    }
    __syncthreads();

    #pragma unroll
    for (int mt = 0; mt < 2; mt++)
        #pragma unroll
        for (int half = 0; half < 2; half++) {
            int rl = wm0 + mt * 16 + half * 8 + (lane >> 2);
            float M = Ms[rl];
            float sm = 0.0f;
            #pragma unroll
            for (int nt = 0; nt < 8; nt++) {
                float e0 = __expf(acc[mt][nt][2 * half] - M);
                float e1 = __expf(acc[mt][nt][2 * half + 1] - M);
                sm += e0 + e1;
                __half2 h = __floats2half2_rn(e0, e1);
                *(__half2*)&E[(size_t)(m0 + rl) * N2 + n0 + wn0 + nt * 8 + (lane & 3) * 2] = h;
            }
            sm += __shfl_xor_sync(~0u, sm, 1);
            sm += __shfl_xor_sync(~0u, sm, 2);
            if ((lane & 3) == 0)
                ps[wid * 32 + mt * 16 + half * 8 + (lane >> 2)] = sm;
        }
    __syncthreads();
    if (tid < 128) {
        int a = tid >> 5, rlw = tid & 31;
        pmax[(size_t)blockIdx.x * N1 + m0 + tid] = Ms[tid];
        psum[(size_t)blockIdx.x * N1 + m0 + tid] = ps[a * 32 + rlw] + ps[(a + 4) * 32 + rlw];
    }
}

// ---------------------------------------------------------------------------
// Fused consumer, OCCUPANCY 2: f2 (blocks 0..127) + f1 (128..255).
// smem: A 2x16KB @0, B 3x16KB @32KB = 80KB. 2 CTAs/SM (160KB of 228KB).
// ---------------------------------------------------------------------------
static constexpr int FB_OFF   = 32 * 1024;
static constexpr int FB_STAGE = 16 * 1024;
static constexpr int FUSED_SMEM = FB_OFF + 3 * FB_STAGE;   // 80 KB

__global__ __launch_bounds__(256, 2) void gemm_fused_kernel(
    const __half* __restrict__ E, const float* __restrict__ pmax,
    const float* __restrict__ lse,
    const __half* __restrict__ X2t, const __half* __restrict__ X1f,
    float* __restrict__ F1, float* __restrict__ F2) {
    extern __shared__ char smem[];
    uint32_t sb = smem_u32(smem);
    const int tid = threadIdx.x, wid = tid >> 5, lane = tid & 31;

    if (blockIdx.x < 128) {
        // ================= f2 tile: C[m0:+128][n0:+128] of attn^T @ x1 =====
        const int bid = blockIdx.x;
        const int m0 = (bid >> 1) * 128, n0 = (bid & 1) * 128;
        const int blk = bid >> 1;
        const int wm0 = (wid & 3) * 32, wn0 = (wid >> 2) * 64;
        const int lt = lane >> 3, li = lane & 7;
        constexpr int A_ST = 64 * 256;   // 16 KB

        float acc[2][8][4] = {};
        uint4 ereg[4];
        float sreg[4];
        const int nCh = N1 >> 6;   // 128

        auto ldgA = [&](int c) {
            #pragma unroll
            for (int it = 0; it < 4; it++) {
                int idx = tid + it * 256;
                int k = idx >> 4, cc = idx & 15;
                ereg[it] = *(const uint4*)(E + (size_t)(c * 64 + k) * N2 + m0 + cc * 8);
                sreg[it] = __expf(pmax[(size_t)blk * N1 + c * 64 + k] - __ldg(lse + c * 64 + k));
            }
        };
        auto stsA = [&](int buf) {
            uint32_t ab = sb + buf * A_ST;
            #pragma unroll
            for (int it = 0; it < 4; it++) {
                int idx = tid + it * 256;
                int k = idx >> 4, cc = idx & 15;
                __half2 s2h = __float2half2_rn(sreg[it]);
                uint32_t s2 = *(uint32_t*)&s2h;
                uint32_t off = k * 256 + ((cc ^ (k & 7)) << 4);
                sts16(ab + off, mulh2(ereg[it].x, s2), mulh2(ereg[it].y, s2),
                      mulh2(ereg[it].z, s2), mulh2(ereg[it].w, s2));
            }
        };
        auto ldB = [&](int c, int buf) {
            uint32_t bb = sb + FB_OFF + buf * FB_STAGE;
            #pragma unroll
            for (int it = 0; it < 4; it++) {
                int i = tid + it * 256;
                int k = i >> 4, cc = i & 15;
                const __half* src = X1f + (size_t)(c * 64 + k) * D1 + n0 + cc * 8;
                uint32_t dst = bb + k * 256 + ((cc ^ (k & 7)) << 4);
                asm volatile("cp.async.cg.shared.global [%0], [%1], 16;" :: "r"(dst), "l"(src) : "memory");
            }
            asm volatile("cp.async.commit_group;" ::: "memory");
        };

        ldgA(0); stsA(0);
        ldB(0, 0); ldB(1, 1);

        for (int c = 0; c < nCh; c++) {
            const bool more = (c + 1 < nCh);
            if (more) ldgA(c + 1);
            asm volatile("cp.async.wait_group 1;" ::: "memory");
            __syncthreads();
            if (c + 2 < nCh) ldB(c + 2, (c + 2) % 3);
            else asm volatile("cp.async.commit_group;" ::: "memory");

            const uint32_t ast = sb + (c & 1) * A_ST;
            const uint32_t bst = sb + FB_OFF + (c % 3) * FB_STAGE;
            #pragma unroll
            for (int ks = 0; ks < 4; ks++) {
                uint32_t afh[2][4];
                #pragma unroll
                for (int mt = 0; mt < 2; mt++) {
                    int mb = wm0 + mt * 16 + (lt & 1) * 8;
                    int k = ks * 16 + (lt >> 1) * 8 + li;
                    uint32_t addr = k * 256 + (((mb >> 3) ^ (k & 7)) << 4);
                    ldsm4t(afh[mt], ast + addr);
                }
                uint32_t bfh[8][2];
                #pragma unroll
                for (int nt = 0; nt < 8; nt += 2) {
                    int nb = wn0 + nt * 8 + (lt >> 1) * 8;
                    int k = ks * 16 + (lt & 1) * 8 + li;
                    uint32_t addr = k * 256 + (((nb >> 3) ^ (k & 7)) << 4);
                    uint32_t t[4];
                    ldsm4t(t, bst + addr);
                    bfh[nt][0] = t[0]; bfh[nt][1] = t[1];
                    bfh[nt + 1][0] = t[2]; bfh[nt + 1][1] = t[3];
                }
                #pragma unroll
                for (int mt = 0; mt < 2; mt++)
                    #pragma unroll
                    for (int nt = 0; nt < 8; nt++)
                        mma16816(acc[mt][nt], afh[mt], bfh[nt]);
            }
            if (more) stsA((c + 1) & 1);
        }

        #pragma unroll
        for (int mt = 0; mt < 2; mt++) {
            int row = m0 + wm0 + mt * 16 + (lane >> 2);
            #pragma unroll
            for (int nt = 0; nt < 8; nt++) {
                int col = n0 + wn0 + nt * 8 + (lane & 3) * 2;
                *(float2*)&F2[(size_t)row * D1 + col]       = make_float2(acc[mt][nt][0], acc[mt][nt][1]);
                *(float2*)&F2[(size_t)(row + 8) * D1 + col] = make_float2(acc[mt][nt][2], acc[mt][nt][3]);
            }
        }
    } else {
        // ================= f1 tile: C[m0:+64][0:128] of attn @ x2 ==========
        const int m0 = (blockIdx.x - 128) * 64;
        const int wm0 = (wid & 1) * 32, wn0 = (wid >> 1) * 32;
        const int a_r = lane & 15, a_k = lane >> 4;
        const int b_r = (lane & 7) + ((lane >> 4) << 3), b_k = (lane >> 3) & 1;
        constexpr int A_ST = 64 * 128;   // 8 KB

        float acc[2][4][4] = {};
        uint4 ereg[2];
        float sreg[2];
        const int nCh = N2 >> 6;   // 128

        float tl2[2];
        #pragma unroll
        for (int it = 0; it < 2; it++) tl2[it] = lse[m0 + ((tid + it * 256) >> 3)];

        auto ldgA = [&](int c) {
            int blk = c >> 1;
            #pragma unroll
            for (int it = 0; it < 2; it++) {
                int idx = tid + it * 256;
                int m = idx >> 3, kq = idx & 7;
                ereg[it] = *(const uint4*)(E + (size_t)(m0 + m) * N2 + c * 64 + kq * 8);
                sreg[it] = __expf(pmax[(size_t)blk * N1 + m0 + m] - tl2[it]);
            }
        };
        auto stsA = [&](int buf) {
            uint32_t ab = sb + buf * A_ST;
            #pragma unroll
            for (int it = 0; it < 2; it++) {
                int idx = tid + it * 256;
                int m = idx >> 3, kq = idx & 7;
                __half2 s2h = __float2half2_rn(sreg[it]);
                uint32_t s2 = *(uint32_t*)&s2h;
                uint32_t off = m * 128 + ((kq ^ (m & 7)) << 4);
                sts16(ab + off, mulh2(ereg[it].x, s2), mulh2(ereg[it].y, s2),
                      mulh2(ereg[it].z, s2), mulh2(ereg[it].w, s2));
            }
        };
        auto ldB = [&](int c, int buf) {
            uint32_t bb = sb + FB_OFF + buf * FB_STAGE;
            #pragma unroll
            for (int it = 0; it < 4; it++) {
                int i = tid + it * 256;
                int n = i >> 3, cc = i & 7;
                const __half* src = X2t + (size_t)n * N2 + c * 64 + cc * 8;
                uint32_t dst = bb + n * 128 + ((cc ^ (n & 7)) << 4);
                asm volatile("cp.async.cg.shared.global [%0], [%1], 16;" :: "r"(dst), "l"(src) : "memory");
            }
            asm volatile("cp.async.commit_group;" ::: "memory");
        };

        ldgA(0); stsA(0);
        ldB(0, 0); ldB(1, 1);

        for (int c = 0; c < nCh; c++) {
            const bool more = (c + 1 < nCh);
            if (more) ldgA(c + 1);
            asm volatile("cp.async.wait_group 1;" ::: "memory");
            __syncthreads();
            if (c + 2 < nCh) ldB(c + 2, (c + 2) % 3);
            else asm volatile("cp.async.commit_group;" ::: "memory");

            const uint32_t ast = sb + (c & 1) * A_ST;
            const uint32_t bst = sb + FB_OFF + (c % 3) * FB_STAGE;
            #pragma unroll
            for (int ks = 0; ks < 4; ks++) {
                uint32_t afh[2][4];
                #pragma unroll
                for (int mt = 0; mt < 2; mt++) {
                    int r = wm0 + mt * 16 + a_r;
                    int kc = ks * 2 + a_k;
                    uint32_t col = (uint32_t)((kc ^ (r & 7)) << 4);
                    ldsm4(afh[mt], ast + r * 128 + col);
                }
                uint32_t bfh[4][2];
                #pragma unroll
                for (int nt = 0; nt < 4; nt += 2) {
                    int r = wn0 + nt * 8 + b_r;
                    int kc = ks * 2 + b_k;
                    uint32_t col = (uint32_t)((kc ^ (r & 7)) << 4);
                    uint32_t t[4];
                    ldsm4(t, bst + r * 128 + col);
                    bfh[nt][0] = t[0]; bfh[nt][1] = t[1];
                    bfh[nt + 1][0] = t[2]; bfh[nt + 1][1] = t[3];
                }
                #pragma unroll
                for (int mt = 0; mt < 2; mt++)
                    #pragma unroll
                    for (int nt = 0; nt < 4; nt++)
                        mma16816(acc[mt][nt], afh[mt], bfh[nt]);
            }
            if (more) stsA((c + 1) & 1);
        }

        #pragma unroll
        for (int mt = 0; mt < 2; mt++) {
            int row = m0 + wm0 + mt * 16 + (lane >> 2);
            #pragma unroll
            for (int nt = 0; nt < 4; nt++) {
                int col = wn0 + nt * 8 + (lane & 3) * 2;
                *(float2*)&F1[(size_t)row * D2 + col]       = make_float2(acc[mt][nt][0], acc[mt][nt][1]);
                *(float2*)&F1[(size_t)(row + 8) * D2 + col] = make_float2(acc[mt][nt][2], acc[mt][nt][3]);
            }
        }
    }
}

// ---------------------------------------------------------------------------
// Launch  (gemm_s at launch index 3 so ncu's capture slot lands on it)
// ---------------------------------------------------------------------------
extern "C" void kernel_launch(void* const* d_in, const int* in_sizes, int n_in,
                              void* d_out, int out_size) {
    const float* x1 = (const float*)d_in[0];   // [8192, 256]
    const float* x2 = (const float*)d_in[1];   // [8192, 128]
    const float* W1 = (const float*)d_in[2];   // [128, 256]
    const float* b1 = (const float*)d_in[3];   // [128]

    float* out = (float*)d_out;
    float* f1 = out;                          // [8192, 128]
    float* f2 = out + (size_t)N1 * D2;        // [8192, 256]

    float *wtp, *lsep, *pmaxp, *psump;
    __half *ep, *qh, *ql, *x2h, *x2l, *x2t, *x1f;
    cudaGetSymbolAddress((void**)&ep, g_E);
    cudaGetSymbolAddress((void**)&wtp, g_Wt);
    cudaGetSymbolAddress((void**)&lsep, g_lse);
    cudaGetSymbolAddress((void**)&pmaxp, g_pmax);
    cudaGetSymbolAddress((void**)&psump, g_psum);
    cudaGetSymbolAddress((void**)&qh, g_qh);
    cudaGetSymbolAddress((void**)&ql, g_ql);
    cudaGetSymbolAddress((void**)&x2h, g_x2h);
    cudaGetSymbolAddress((void**)&x2l, g_x2l);
    cudaGetSymbolAddress((void**)&x2t, g_x2t);
    cudaGetSymbolAddress((void**)&x1f, g_x1f);

    cudaFuncSetAttribute((const void*)gemm_s_kernel,
                         cudaFuncAttributeMaxDynamicSharedMemorySize, SMEM_S);
    cudaFuncSetAttribute((const void*)gemm_fused_kernel,
                         cudaFuncAttributeMaxDynamicSharedMemorySize, FUSED_SMEM);

    // prep needed by gemm_s only
    transpose_w_kernel<<<(D1 * D2 + 255) / 256, 256>>>(W1, wtp);              // 0
    q_gemm_kernel<<<N1 / 32, 256>>>(x1, wtp, qh, ql, b1);                     // 1
    split_kernel<<<(N2 * D2 / 4 + 255) / 256, 256>>>(x2, N2 * D2, x2h, x2l);  // 2
    // 3: the big S kernel (profiled slot)
    gemm_s_kernel<<<dim3(NBLK, N1 / 128), 256, SMEM_S>>>(
        qh, ql, x2h, x2l, ep, pmaxp, psump);
    // remaining prep for consumers
    transpose_h_kernel<<<dim3(D2 / 32, N2 / 32), dim3(32, 8)>>>(x2, N2, D2, x2t); // 4
    tofp16_kernel<<<(N1 * D1 / 4 + 255) / 256, 256>>>(x1, N1 * D1, x1f);          // 5
    lse_combine_kernel<<<N1 / 256, 256>>>(pmaxp, psump, lsep);                    // 6
    // 7: fused consumers (f2 blocks first)
    gemm_fused_kernel<<<256, 256, FUSED_SMEM>>>(ep, pmaxp, lsep, x2t, x1f, f1, f2);
}

// round 13
// speedup vs baseline: 6.5804x; 1.0517x over previous
#include <cuda_runtime.h>
#include <cuda_fp16.h>
#include <cstdint>

#define N1 8192
#define N2 8192
#define D1 256
#define D2 128
#define NBLK (N2 / 64)    // 128 column-slabs (64-wide) of E

// ---------------------------------------------------------------------------
// Scratch (__device__ globals; allocation-free rule)
// ---------------------------------------------------------------------------
__device__ __half g_E[(size_t)N1 * N2];                // 128 MB: exp(S - pmax_slab)
__device__ float g_lse[N1];
__device__ float g_pmax[(size_t)NBLK * N1];            // 4 MB
__device__ float g_psum[(size_t)NBLK * N1];            // 4 MB
__device__ __half g_qh[N1 * D2], g_ql[N1 * D2];
__device__ __half g_x2h[N2 * D2], g_x2l[N2 * D2];
__device__ __half g_x2t[D2 * N2];
__device__ __half g_x1f[(size_t)N1 * D1];
__device__ float g_Wt[D1 * D2];

// ---------------------------------------------------------------------------
// Helpers
// ---------------------------------------------------------------------------
__device__ __forceinline__ uint32_t smem_u32(const void* p) {
    uint32_t a;
    asm("{ .reg .u64 t; cvta.to.shared.u64 t, %1; cvt.u32.u64 %0, t; }" : "=r"(a) : "l"(p));
    return a;
}
__device__ __forceinline__ void ldsm4(uint32_t r[4], uint32_t addr) {
    asm volatile("ldmatrix.sync.aligned.m8n8.x4.shared.b16 {%0,%1,%2,%3}, [%4];"
                 : "=r"(r[0]), "=r"(r[1]), "=r"(r[2]), "=r"(r[3]) : "r"(addr));
}
__device__ __forceinline__ void ldsm4t(uint32_t r[4], uint32_t addr) {
    asm volatile("ldmatrix.sync.aligned.m8n8.x4.trans.shared.b16 {%0,%1,%2,%3}, [%4];"
                 : "=r"(r[0]), "=r"(r[1]), "=r"(r[2]), "=r"(r[3]) : "r"(addr));
}
__device__ __forceinline__ void mma16816(float c[4], const uint32_t a[4], const uint32_t b[2]) {
    asm volatile("mma.sync.aligned.m16n8k16.row.col.f32.f16.f16.f32 "
                 "{%0,%1,%2,%3}, {%4,%5,%6,%7}, {%8,%9}, {%0,%1,%2,%3};"
                 : "+f"(c[0]), "+f"(c[1]), "+f"(c[2]), "+f"(c[3])
                 : "r"(a[0]), "r"(a[1]), "r"(a[2]), "r"(a[3]), "r"(b[0]), "r"(b[1]));
}
__device__ __forceinline__ void split_h(float v, __half& h, __half& l) {
    h = __float2half(v);
    l = __float2half(v - __half2float(h));
}
__device__ __forceinline__ void sts16(uint32_t addr, uint32_t a, uint32_t b,
                                      uint32_t c, uint32_t d) {
    asm volatile("st.shared.v4.b32 [%0], {%1,%2,%3,%4};"
                 :: "r"(addr), "r"(a), "r"(b), "r"(c), "r"(d) : "memory");
}
__device__ __forceinline__ uint32_t mulh2(uint32_t e, uint32_t s) {
    __half2 r = __hmul2(*(__half2*)&e, *(__half2*)&s);
    return *(uint32_t*)&r;
}

// ---------------------------------------------------------------------------
// Prep kernels
// ---------------------------------------------------------------------------
__global__ void transpose_w_kernel(const float* __restrict__ W1, float* __restrict__ Wt) {
    int idx = blockIdx.x * blockDim.x + threadIdx.x;
    if (idx < D1 * D2) {
        int n = idx / D1, k = idx % D1;
        Wt[k * D2 + n] = W1[idx];
    }
}

__global__ void q_gemm_kernel(const float* __restrict__ A, const float* __restrict__ B,
                              __half* __restrict__ Ch, __half* __restrict__ Cl,
                              const float* __restrict__ bias) {
    __shared__ float As[32][16];
    __shared__ float Bs[16][128];
    const int m0 = blockIdx.x * 32;
    const int tid = threadIdx.x;
    const int ty = tid >> 4, tx = tid & 15;
    float acc0[8] = {}, acc1[8] = {};

    for (int k0 = 0; k0 < D1; k0 += 16) {
        {
            int m = tid >> 3, k2 = (tid & 7) * 2;
            const float* p = A + (size_t)(m0 + m) * D1 + k0 + k2;
            As[m][k2] = p[0]; As[m][k2 + 1] = p[1];
        }
        #pragma unroll
        for (int c = 0; c < 2; c++) {
            int idx = c * 1024 + tid * 4;
            int k = idx >> 7, n = idx & 127;
            *(float4*)&Bs[k][n] = *(const float4*)(B + (size_t)(k0 + k) * 128 + n);
        }
        __syncthreads();
        #pragma unroll
        for (int k = 0; k < 16; k++) {
            float a0 = As[ty * 2][k], a1 = As[ty * 2 + 1][k];
            float4 b0 = *(const float4*)&Bs[k][tx * 8];
            float4 b1 = *(const float4*)&Bs[k][tx * 8 + 4];
            acc0[0] += a0 * b0.x; acc0[1] += a0 * b0.y; acc0[2] += a0 * b0.z; acc0[3] += a0 * b0.w;
            acc0[4] += a0 * b1.x; acc0[5] += a0 * b1.y; acc0[6] += a0 * b1.z; acc0[7] += a0 * b1.w;
            acc1[0] += a1 * b0.x; acc1[1] += a1 * b0.y; acc1[2] += a1 * b0.z; acc1[3] += a1 * b0.w;
            acc1[4] += a1 * b1.x; acc1[5] += a1 * b1.y; acc1[6] += a1 * b1.z; acc1[7] += a1 * b1.w;
        }
        __syncthreads();
    }
    int m = m0 + ty * 2;
    #pragma unroll
    for (int j = 0; j < 8; j++) {
        float bv = bias[tx * 8 + j];
        __half h, l;
        split_h(acc0[j] + bv, h, l);
        Ch[(size_t)m * 128 + tx * 8 + j] = h; Cl[(size_t)m * 128 + tx * 8 + j] = l;
        split_h(acc1[j] + bv, h, l);
        Ch[(size_t)(m + 1) * 128 + tx * 8 + j] = h; Cl[(size_t)(m + 1) * 128 + tx * 8 + j] = l;
    }
}

__global__ void split_kernel(const float* __restrict__ in, int n,
                             __half* __restrict__ oh, __half* __restrict__ ol) {
    int i = blockIdx.x * blockDim.x + threadIdx.x;
    if (i * 4 < n) {
        float4 v = *(const float4*)(in + (size_t)i * 4);
        __half h, l;
        size_t o = (size_t)i * 4;
        split_h(v.x, h, l); oh[o] = h;     ol[o] = l;
        split_h(v.y, h, l); oh[o + 1] = h; ol[o + 1] = l;
        split_h(v.z, h, l); oh[o + 2] = h; ol[o + 2] = l;
        split_h(v.w, h, l); oh[o + 3] = h; ol[o + 3] = l;
    }
}

__global__ void tofp16_kernel(const float* __restrict__ in, int n, __half* __restrict__ o) {
    int i = blockIdx.x * blockDim.x + threadIdx.x;
    if (i * 4 < n) {
        float4 v = *(const float4*)(in + (size_t)i * 4);
        __half2 a = __floats2half2_rn(v.x, v.y);
        __half2 b = __floats2half2_rn(v.z, v.w);
        *(__half2*)(o + (size_t)i * 4)     = a;
        *(__half2*)(o + (size_t)i * 4 + 2) = b;
    }
}

__global__ void transpose_h_kernel(const float* __restrict__ in, int R, int C,
                                   __half* __restrict__ o) {
    __shared__ float t[32][33];
    int c0 = blockIdx.x * 32, r0 = blockIdx.y * 32;
    for (int i = threadIdx.y; i < 32; i += 8)
        t[i][threadIdx.x] = in[(size_t)(r0 + i) * C + c0 + threadIdx.x];
    __syncthreads();
    for (int i = threadIdx.y; i < 32; i += 8)
        o[(size_t)(c0 + i) * R + r0 + threadIdx.x] = __float2half(t[threadIdx.x][i]);
}

// ---------------------------------------------------------------------------
// lse combine (128 slabs of 64 cols)
// ---------------------------------------------------------------------------
__global__ void lse_combine_kernel(const float* __restrict__ pmax,
                                   const float* __restrict__ psum,
                                   float* __restrict__ lse) {
    int row = blockIdx.x * 256 + threadIdx.x;
    float M = -1e30f;
    #pragma unroll 8
    for (int nb = 0; nb < NBLK; nb++)
        M = fmaxf(M, pmax[(size_t)nb * N1 + row]);
    float s = 0.0f;
    #pragma unroll 8
    for (int nb = 0; nb < NBLK; nb++)
        s += psum[(size_t)nb * N1 + row] * __expf(pmax[(size_t)nb * N1 + row] - M);
    lse[row] = M + __logf(s);
}

// ---------------------------------------------------------------------------
// S GEMM: BM=128, BN=64, split-fp16 3-MMA, OCCUPANCY 2 (96 KB smem).
// Epilogue writes E = exp(S - pmax_slab) fp16 + per-64-slab row (pmax, psum).
// Stage rows: Ah 0..127, Al 128..255, Bh 256..319, Bl 320..383 (128B rows).
// ---------------------------------------------------------------------------
static constexpr int S_STAGE = (2 * 128 + 2 * 64) * 128;  // 48 KB
static constexpr int SMEM_S  = 2 * S_STAGE;               // 96 KB

__device__ __forceinline__ void s_load_stage(
    uint32_t base, int tid, int m0, int n0, int k0,
    const __half* Ah, const __half* Al, const __half* Bh, const __half* Bl) {
    #pragma unroll
    for (int it = 0; it < 12; it++) {
        int i = tid + it * 256;
        int c = i & 7, row = i >> 3;
        const __half* src;
        if (row < 128)       src = Ah + (size_t)(m0 + row) * D2 + k0 + c * 8;
        else if (row < 256)  src = Al + (size_t)(m0 + row - 128) * D2 + k0 + c * 8;
        else if (row < 320)  src = Bh + (size_t)(n0 + row - 256) * D2 + k0 + c * 8;
        else                 src = Bl + (size_t)(n0 + row - 320) * D2 + k0 + c * 8;
        uint32_t dst = base + row * 128 + ((c ^ (row & 7)) << 4);
        asm volatile("cp.async.cg.shared.global [%0], [%1], 16;" :: "r"(dst), "l"(src) : "memory");
    }
    asm volatile("cp.async.commit_group;" ::: "memory");
}

__global__ __launch_bounds__(256, 2) void gemm_s_kernel(
    const __half* __restrict__ Ah, const __half* __restrict__ Al,
    const __half* __restrict__ Bh, const __half* __restrict__ Bl,
    __half* __restrict__ E, float* __restrict__ pmax, float* __restrict__ psum) {
    extern __shared__ char smem[];
    const int tid = threadIdx.x, wid = tid >> 5, lane = tid & 31;
    const int m0 = blockIdx.y * 128, n0 = blockIdx.x * 64;
    const int wm0 = (wid & 3) * 32, wn0 = (wid >> 2) * 32;
    uint32_t sb = smem_u32(smem);

    const int a_r = lane & 15, a_k = lane >> 4;
    const int b_r = (lane & 7) + ((lane >> 4) << 3), b_k = (lane >> 3) & 1;

    float acc[2][4][4] = {};
    s_load_stage(sb, tid, m0, n0, 0, Ah, Al, Bh, Bl);
    s_load_stage(sb + S_STAGE, tid, m0, n0, 64, Ah, Al, Bh, Bl);

    for (int c = 0; c < 2; c++) {
        asm volatile("cp.async.wait_group %0;" :: "n"(0) : "memory");
        __syncthreads();
        const uint32_t st = sb + c * S_STAGE;
        #pragma unroll
        for (int ks = 0; ks < 4; ks++) {
            uint32_t afh[2][4], afl[2][4];
            #pragma unroll
            for (int mt = 0; mt < 2; mt++) {
                int r = wm0 + mt * 16 + a_r;
                int kc = ks * 2 + a_k;
                uint32_t col = (uint32_t)((kc ^ (r & 7)) << 4);
                ldsm4(afh[mt], st + r * 128 + col);
                ldsm4(afl[mt], st + (128 + r) * 128 + col);
            }
            uint32_t bfh[4][2], bfl[4][2];
            #pragma unroll
            for (int nt = 0; nt < 4; nt += 2) {
                int r = wn0 + nt * 8 + b_r;
                int kc = ks * 2 + b_k;
                uint32_t col = (uint32_t)((kc ^ (r & 7)) << 4);
                uint32_t t[4];
                ldsm4(t, st + (256 + r) * 128 + col);
                bfh[nt][0] = t[0]; bfh[nt][1] = t[1];
                bfh[nt + 1][0] = t[2]; bfh[nt + 1][1] = t[3];
                ldsm4(t, st + (320 + r) * 128 + col);
                bfl[nt][0] = t[0]; bfl[nt][1] = t[1];
                bfl[nt + 1][0] = t[2]; bfl[nt + 1][1] = t[3];
            }
            #pragma unroll
            for (int mt = 0; mt < 2; mt++)
                #pragma unroll
                for (int nt = 0; nt < 4; nt++) {
                    mma16816(acc[mt][nt], afh[mt], bfh[nt]);
                    mma16816(acc[mt][nt], afh[mt], bfl[nt]);
                    mma16816(acc[mt][nt], afl[mt], bfh[nt]);
                }
        }
        __syncthreads();
    }

    // ---- epilogue: 64-slab row max -> E fp16 -> psum ----
    float* pm = (float*)smem;      // [8][32]
    float* Ms = pm + 256;          // [128]
    float* ps = Ms + 128;          // [8][32]

    #pragma unroll
    for (int mt = 0; mt < 2; mt++)
        #pragma unroll
        for (int half = 0; half < 2; half++) {
            float mx = -1e30f;
            #pragma unroll
            for (int nt = 0; nt < 4; nt++)
                mx = fmaxf(mx, fmaxf(acc[mt][nt][2 * half], acc[mt][nt][2 * half + 1]));
            mx = fmaxf(mx, __shfl_xor_sync(~0u, mx, 1));
            mx = fmaxf(mx, __shfl_xor_sync(~0u, mx, 2));
            if ((lane & 3) == 0)
                pm[wid * 32 + mt * 16 + half * 8 + (lane >> 2)] = mx;
        }
    __syncthreads();
    if (tid < 128) {
        int a = tid >> 5, rlw = tid & 31;
        Ms[tid] = fmaxf(pm[a * 32 + rlw], pm[(a + 4) * 32 + rlw]);
    }
    __syncthreads();

    #pragma unroll
    for (int mt = 0; mt < 2; mt++)
        #pragma unroll
        for (int half = 0; half < 2; half++) {
            int rl = wm0 + mt * 16 + half * 8 + (lane >> 2);
            float M = Ms[rl];
            float sm = 0.0f;
            #pragma unroll
            for (int nt = 0; nt < 4; nt++) {
                float e0 = __expf(acc[mt][nt][2 * half] - M);
                float e1 = __expf(acc[mt][nt][2 * half + 1] - M);
                sm += e0 + e1;
                __half2 h = __floats2half2_rn(e0, e1);
                *(__half2*)&E[(size_t)(m0 + rl) * N2 + n0 + wn0 + nt * 8 + (lane & 3) * 2] = h;
            }
            sm += __shfl_xor_sync(~0u, sm, 1);
            sm += __shfl_xor_sync(~0u, sm, 2);
            if ((lane & 3) == 0)
                ps[wid * 32 + mt * 16 + half * 8 + (lane >> 2)] = sm;
        }
    __syncthreads();
    if (tid < 128) {
        int a = tid >> 5, rlw = tid & 31;
        pmax[(size_t)blockIdx.x * N1 + m0 + tid] = Ms[tid];
        psum[(size_t)blockIdx.x * N1 + m0 + tid] = ps[a * 32 + rlw] + ps[(a + 4) * 32 + rlw];
    }
}

// ---------------------------------------------------------------------------
// Fused consumer, OCCUPANCY 2: f2 (blocks 0..127) + f1 (128..255).
// smem: A 2x16KB @0, B 3x16KB @32KB = 80KB.
// ---------------------------------------------------------------------------
static constexpr int FB_OFF   = 32 * 1024;
static constexpr int FB_STAGE = 16 * 1024;
static constexpr int FUSED_SMEM = FB_OFF + 3 * FB_STAGE;   // 80 KB

__global__ __launch_bounds__(256, 2) void gemm_fused_kernel(
    const __half* __restrict__ E, const float* __restrict__ pmax,
    const float* __restrict__ lse,
    const __half* __restrict__ X2t, const __half* __restrict__ X1f,
    float* __restrict__ F1, float* __restrict__ F2) {
    extern __shared__ char smem[];
    uint32_t sb = smem_u32(smem);
    const int tid = threadIdx.x, wid = tid >> 5, lane = tid & 31;

    if (blockIdx.x < 128) {
        // ================= f2 tile: C[m0:+128][n0:+128] of attn^T @ x1 =====
        const int bid = blockIdx.x;
        const int m0 = (bid >> 1) * 128, n0 = (bid & 1) * 128;
        const int wm0 = (wid & 3) * 32, wn0 = (wid >> 2) * 64;
        const int lt = lane >> 3, li = lane & 7;
        constexpr int A_ST = 64 * 256;   // 16 KB

        float acc[2][8][4] = {};
        uint4 ereg[4];
        float sreg[4];
        const int nCh = N1 >> 6;   // 128

        auto ldgA = [&](int c) {
            #pragma unroll
            for (int it = 0; it < 4; it++) {
                int idx = tid + it * 256;
                int k = idx >> 4, cc = idx & 15;
                // E columns m0+cc*8 .. +8 all lie in 64-slab (m0>>6)+(cc>>3)
                ereg[it] = *(const uint4*)(E + (size_t)(c * 64 + k) * N2 + m0 + cc * 8);
                sreg[it] = __expf(pmax[(size_t)((m0 >> 6) + (cc >> 3)) * N1 + c * 64 + k]
                                  - __ldg(lse + c * 64 + k));
            }
        };
        auto stsA = [&](int buf) {
            uint32_t ab = sb + buf * A_ST;
            #pragma unroll
            for (int it = 0; it < 4; it++) {
                int idx = tid + it * 256;
                int k = idx >> 4, cc = idx & 15;
                __half2 s2h = __float2half2_rn(sreg[it]);
                uint32_t s2 = *(uint32_t*)&s2h;
                uint32_t off = k * 256 + ((cc ^ (k & 7)) << 4);
                sts16(ab + off, mulh2(ereg[it].x, s2), mulh2(ereg[it].y, s2),
                      mulh2(ereg[it].z, s2), mulh2(ereg[it].w, s2));
            }
        };
        auto ldB = [&](int c, int buf) {
            uint32_t bb = sb + FB_OFF + buf * FB_STAGE;
            #pragma unroll
            for (int it = 0; it < 4; it++) {
                int i = tid + it * 256;
                int k = i >> 4, cc = i & 15;
                const __half* src = X1f + (size_t)(c * 64 + k) * D1 + n0 + cc * 8;
                uint32_t dst = bb + k * 256 + ((cc ^ (k & 7)) << 4);
                asm volatile("cp.async.cg.shared.global [%0], [%1], 16;" :: "r"(dst), "l"(src) : "memory");
            }
            asm volatile("cp.async.commit_group;" ::: "memory");
        };

        ldgA(0); stsA(0);
        ldB(0, 0); ldB(1, 1);

        for (int c = 0; c < nCh; c++) {
            const bool more = (c + 1 < nCh);
            if (more) ldgA(c + 1);
            asm volatile("cp.async.wait_group 1;" ::: "memory");
            __syncthreads();
            if (c + 2 < nCh) ldB(c + 2, (c + 2) % 3);
            else asm volatile("cp.async.commit_group;" ::: "memory");

            const uint32_t ast = sb + (c & 1) * A_ST;
            const uint32_t bst = sb + FB_OFF + (c % 3) * FB_STAGE;
            #pragma unroll
            for (int ks = 0; ks < 4; ks++) {
                uint32_t afh[2][4];
                #pragma unroll
                for (int mt = 0; mt < 2; mt++) {
                    int mb = wm0 + mt * 16 + (lt & 1) * 8;
                    int k = ks * 16 + (lt >> 1) * 8 + li;
                    uint32_t addr = k * 256 + (((mb >> 3) ^ (k & 7)) << 4);
                    ldsm4t(afh[mt], ast + addr);
                }
                uint32_t bfh[8][2];
                #pragma unroll
                for (int nt = 0; nt < 8; nt += 2) {
                    int nb = wn0 + nt * 8 + (lt >> 1) * 8;
                    int k = ks * 16 + (lt & 1) * 8 + li;
                    uint32_t addr = k * 256 + (((nb >> 3) ^ (k & 7)) << 4);
                    uint32_t t[4];
                    ldsm4t(t, bst + addr);
                    bfh[nt][0] = t[0]; bfh[nt][1] = t[1];
                    bfh[nt + 1][0] = t[2]; bfh[nt + 1][1] = t[3];
                }
                #pragma unroll
                for (int mt = 0; mt < 2; mt++)
                    #pragma unroll
                    for (int nt = 0; nt < 8; nt++)
                        mma16816(acc[mt][nt], afh[mt], bfh[nt]);
            }
            if (more) stsA((c + 1) & 1);
        }

        #pragma unroll
        for (int mt = 0; mt < 2; mt++) {
            int row = m0 + wm0 + mt * 16 + (lane >> 2);
            #pragma unroll
            for (int nt = 0; nt < 8; nt++) {
                int col = n0 + wn0 + nt * 8 + (lane & 3) * 2;
                *(float2*)&F2[(size_t)row * D1 + col]       = make_float2(acc[mt][nt][0], acc[mt][nt][1]);
                *(float2*)&F2[(size_t)(row + 8) * D1 + col] = make_float2(acc[mt][nt][2], acc[mt][nt][3]);
            }
        }
    } else {
        // ================= f1 tile: C[m0:+64][0:128] of attn @ x2 ==========
        const int m0 = (blockIdx.x - 128) * 64;
        const int wm0 = (wid & 1) * 32, wn0 = (wid >> 1) * 32;
        const int a_r = lane & 15, a_k = lane >> 4;
        const int b_r = (lane & 7) + ((lane >> 4) << 3), b_k = (lane >> 3) & 1;
        constexpr int A_ST = 64 * 128;   // 8 KB

        float acc[2][4][4] = {};
        uint4 ereg[2];
        float sreg[2];
        const int nCh = N2 >> 6;   // 128

        float tl2[2];
        #pragma unroll
        for (int it = 0; it < 2; it++) tl2[it] = lse[m0 + ((tid + it * 256) >> 3)];

        auto ldgA = [&](int c) {
            // E columns c*64..+64 form exactly slab c
            #pragma unroll
            for (int it = 0; it < 2; it++) {
                int idx = tid + it * 256;
                int m = idx >> 3, kq = idx & 7;
                ereg[it] = *(const uint4*)(E + (size_t)(m0 + m) * N2 + c * 64 + kq * 8);
                sreg[it] = __expf(pmax[(size_t)c * N1 + m0 + m] - tl2[it]);
            }
        };
        auto stsA = [&](int buf) {
            uint32_t ab = sb + buf * A_ST;
            #pragma unroll
            for (int it = 0; it < 2; it++) {
                int idx = tid + it * 256;
                int m = idx >> 3, kq = idx & 7;
                __half2 s2h = __float2half2_rn(sreg[it]);
                uint32_t s2 = *(uint32_t*)&s2h;
                uint32_t off = m * 128 + ((kq ^ (m & 7)) << 4);
                sts16(ab + off, mulh2(ereg[it].x, s2), mulh2(ereg[it].y, s2),
                      mulh2(ereg[it].z, s2), mulh2(ereg[it].w, s2));
            }
        };
        auto ldB = [&](int c, int buf) {
            uint32_t bb = sb + FB_OFF + buf * FB_STAGE;
            #pragma unroll
            for (int it = 0; it < 4; it++) {
                int i = tid + it * 256;
                int n = i >> 3, cc = i & 7;
                const __half* src = X2t + (size_t)n * N2 + c * 64 + cc * 8;
                uint32_t dst = bb + n * 128 + ((cc ^ (n & 7)) << 4);
                asm volatile("cp.async.cg.shared.global [%0], [%1], 16;" :: "r"(dst), "l"(src) : "memory");
            }
            asm volatile("cp.async.commit_group;" ::: "memory");
        };

        ldgA(0); stsA(0);
        ldB(0, 0); ldB(1, 1);

        for (int c = 0; c < nCh; c++) {
            const bool more = (c + 1 < nCh);
            if (more) ldgA(c + 1);
            asm volatile("cp.async.wait_group 1;" ::: "memory");
            __syncthreads();
            if (c + 2 < nCh) ldB(c + 2, (c + 2) % 3);
            else asm volatile("cp.async.commit_group;" ::: "memory");

            const uint32_t ast = sb + (c & 1) * A_ST;
            const uint32_t bst = sb + FB_OFF + (c % 3) * FB_STAGE;
            #pragma unroll
            for (int ks = 0; ks < 4; ks++) {
                uint32_t afh[2][4];
                #pragma unroll
                for (int mt = 0; mt < 2; mt++) {
                    int r = wm0 + mt * 16 + a_r;
                    int kc = ks * 2 + a_k;
                    uint32_t col = (uint32_t)((kc ^ (r & 7)) << 4);
                    ldsm4(afh[mt], ast + r * 128 + col);
                }
                uint32_t bfh[4][2];
                #pragma unroll
                for (int nt = 0; nt < 4; nt += 2) {
                    int r = wn0 + nt * 8 + b_r;
                    int kc = ks * 2 + b_k;
                    uint32_t col = (uint32_t)((kc ^ (r & 7)) << 4);
                    uint32_t t[4];
                    ldsm4(t, bst + r * 128 + col);
                    bfh[nt][0] = t[0]; bfh[nt][1] = t[1];
                    bfh[nt + 1][0] = t[2]; bfh[nt + 1][1] = t[3];
                }
                #pragma unroll
                for (int mt = 0; mt < 2; mt++)
                    #pragma unroll
                    for (int nt = 0; nt < 4; nt++)
                        mma16816(acc[mt][nt], afh[mt], bfh[nt]);
            }
            if (more) stsA((c + 1) & 1);
        }

        #pragma unroll
        for (int mt = 0; mt < 2; mt++) {
            int row = m0 + wm0 + mt * 16 + (lane >> 2);
            #pragma unroll
            for (int nt = 0; nt < 4; nt++) {
                int col = wn0 + nt * 8 + (lane & 3) * 2;
                *(float2*)&F1[(size_t)row * D2 + col]       = make_float2(acc[mt][nt][0], acc[mt][nt][1]);
                *(float2*)&F1[(size_t)(row + 8) * D2 + col] = make_float2(acc[mt][nt][2], acc[mt][nt][3]);
            }
        }
    }
}

// ---------------------------------------------------------------------------
// Launch  (gemm_s at launch index 3 for the ncu capture slot)
// ---------------------------------------------------------------------------
extern "C" void kernel_launch(void* const* d_in, const int* in_sizes, int n_in,
                              void* d_out, int out_size) {
    const float* x1 = (const float*)d_in[0];   // [8192, 256]
    const float* x2 = (const float*)d_in[1];   // [8192, 128]
    const float* W1 = (const float*)d_in[2];   // [128, 256]
    const float* b1 = (const float*)d_in[3];   // [128]

    float* out = (float*)d_out;
    float* f1 = out;                          // [8192, 128]
    float* f2 = out + (size_t)N1 * D2;        // [8192, 256]

    float *wtp, *lsep, *pmaxp, *psump;
    __half *ep, *qh, *ql, *x2h, *x2l, *x2t, *x1f;
    cudaGetSymbolAddress((void**)&ep, g_E);
    cudaGetSymbolAddress((void**)&wtp, g_Wt);
    cudaGetSymbolAddress((void**)&lsep, g_lse);
    cudaGetSymbolAddress((void**)&pmaxp, g_pmax);
    cudaGetSymbolAddress((void**)&psump, g_psum);
    cudaGetSymbolAddress((void**)&qh, g_qh);
    cudaGetSymbolAddress((void**)&ql, g_ql);
    cudaGetSymbolAddress((void**)&x2h, g_x2h);
    cudaGetSymbolAddress((void**)&x2l, g_x2l);
    cudaGetSymbolAddress((void**)&x2t, g_x2t);
    cudaGetSymbolAddress((void**)&x1f, g_x1f);

    cudaFuncSetAttribute((const void*)gemm_s_kernel,
                         cudaFuncAttributeMaxDynamicSharedMemorySize, SMEM_S);
    cudaFuncSetAttribute((const void*)gemm_fused_kernel,
                         cudaFuncAttributeMaxDynamicSharedMemorySize, FUSED_SMEM);

    // prep needed by gemm_s only
    transpose_w_kernel<<<(D1 * D2 + 255) / 256, 256>>>(W1, wtp);              // 0
    q_gemm_kernel<<<N1 / 32, 256>>>(x1, wtp, qh, ql, b1);                     // 1
    split_kernel<<<(N2 * D2 / 4 + 255) / 256, 256>>>(x2, N2 * D2, x2h, x2l);  // 2
    // 3: the big S kernel (profiled slot), occupancy 2
    gemm_s_kernel<<<dim3(N2 / 64, N1 / 128), 256, SMEM_S>>>(
        qh, ql, x2h, x2l, ep, pmaxp, psump);
    // remaining prep for consumers
    transpose_h_kernel<<<dim3(D2 / 32, N2 / 32), dim3(32, 8)>>>(x2, N2, D2, x2t); // 4
    tofp16_kernel<<<(N1 * D1 / 4 + 255) / 256, 256>>>(x1, N1 * D1, x1f);          // 5
    lse_combine_kernel<<<N1 / 256, 256>>>(pmaxp, psump, lsep);                    // 6
    // 7: fused consumers (f2 blocks first)
    gemm_fused_kernel<<<256, 256, FUSED_SMEM>>>(ep, pmaxp, lsep, x2t, x1f, f1, f2);
}